// round 2
// baseline (speedup 1.0000x reference)
#include <cuda_runtime.h>
#include <math.h>

#define BATCH 16
#define CCH   256
#define NSP   4096
#define M3    768
#define NGRP  4
#define CPG   64
#define NH    8
#define HD    32
#define ACH   8   // att_kernel n-split chunks

typedef unsigned long long ull;

// ---------------- scratch (device globals; no allocations allowed) ----------
__device__ float g_qkv[BATCH * M3 * NSP];            // q,k,v per batch
__device__ float g_attout[BATCH * CCH * NSP];        // attention output
__device__ float g_att[BATCH * NH * HD * HD];        // 32x32 per (b,h)
__device__ float g_attp[BATCH * NH * ACH * HD * HD]; // partials
__device__ float g_mu[BATCH * NGRP];
__device__ float g_rsig[BATCH * NGRP];

// ---------------- packed f32x2 helpers (sm_103a) ----------------------------
__device__ __forceinline__ ull pk2(float x, float y) {
    ull r; asm("mov.b64 %0, {%1, %2};" : "=l"(r) : "f"(x), "f"(y)); return r;
}
__device__ __forceinline__ void fma2(ull& d, ull a, ull b) {
    asm("fma.rn.f32x2 %0, %1, %2, %3;" : "=l"(d) : "l"(a), "l"(b), "l"(d));
}
__device__ __forceinline__ float2 up2(ull v) {
    float lo, hi; asm("mov.b64 {%0, %1}, %2;" : "=f"(lo), "=f"(hi) : "l"(v));
    return make_float2(lo, hi);
}

// ---------------- 1) GroupNorm statistics ----------------------------------
__global__ __launch_bounds__(1024) void gn_stats_kernel(const float* __restrict__ x)
{
    int bg = blockIdx.x;
    const float4* p = (const float4*)(x + (size_t)bg * CPG * NSP);
    float s = 0.f, sq = 0.f;
    for (int i = threadIdx.x; i < 65536; i += 1024) {
        float4 v = p[i];
        s  += v.x + v.y + v.z + v.w;
        sq += v.x * v.x + v.y * v.y + v.z * v.z + v.w * v.w;
    }
    __shared__ float ss[32], ssq[32];
    #pragma unroll
    for (int o = 16; o; o >>= 1) {
        s  += __shfl_down_sync(0xffffffffu, s, o);
        sq += __shfl_down_sync(0xffffffffu, sq, o);
    }
    int w = threadIdx.x >> 5, l = threadIdx.x & 31;
    if (l == 0) { ss[w] = s; ssq[w] = sq; }
    __syncthreads();
    if (w == 0) {
        s  = ss[l];
        sq = ssq[l];
        #pragma unroll
        for (int o = 16; o; o >>= 1) {
            s  += __shfl_down_sync(0xffffffffu, s, o);
            sq += __shfl_down_sync(0xffffffffu, sq, o);
        }
        if (l == 0) {
            const float inv = 1.0f / (float)(CPG * NSP);
            float mu  = s * inv;
            float var = sq * inv - mu * mu;
            g_mu[bg]   = mu;
            g_rsig[bg] = rsqrtf(var + 1e-5f);
        }
    }
}

// ---------------- 2/6) SGEMM 128x128x8, 256 threads, FFMA2 inner loop ------
// C[b][o][n] = sum_c A[o][c] * B[b][c][n]   (+ optional GN on B, bias on C)
// Accumulators are packed f32x2 pairs along n. A is stored into smem
// duplicated (a,a) so the broadcast operand is a straight 8B LDS.
template<int M, bool FUSE_GN, bool ADD_BIAS, bool B_SYM, bool C_SYM>
__global__ __launch_bounds__(256) void sgemm_kernel(
    const float* __restrict__ A,     // [M][256]
    const float* __restrict__ Bext,  // [BATCH][256][4096] (if !B_SYM)
    float*       __restrict__ Cext,  // [BATCH][M][4096]   (if !C_SYM)
    const float* __restrict__ gnw,
    const float* __restrict__ gnb,
    const float* __restrict__ bias)
{
    const int K = 256, N = NSP;
    int b = blockIdx.z;
    const float* Bbase = B_SYM ? g_attout : Bext;
    float*       Cbase = C_SYM ? g_qkv    : Cext;
    const float* Bp = Bbase + (size_t)b * K * N;
    float*       Cp = Cbase + (size_t)b * M * N;
    int m0 = blockIdx.y * 128, n0 = blockIdx.x * 128;

    __shared__ float As2[8][256];  // duplicated pairs: [k][2*row+{0,1}]
    __shared__ float Bs[8][128];

    int tid  = threadIdx.x;
    int arow = tid >> 1,  acol = (tid & 1) << 2;   // A: 128 rows x 8 cols
    int brow = tid >> 5,  bcol = (tid & 31) << 2;  // B: 8 rows x 128 cols
    int tm   = (tid >> 4) << 3;
    int tn   = (tid & 15) << 3;

    ull acc[8][4];
    #pragma unroll
    for (int i = 0; i < 8; i++)
        #pragma unroll
        for (int j = 0; j < 4; j++) acc[i][j] = 0ull;

    for (int k0 = 0; k0 < K; k0 += 8) {
        float4 av = *(const float4*)(A + (size_t)(m0 + arow) * K + k0 + acol);
        *(ull*)&As2[acol + 0][arow * 2] = pk2(av.x, av.x);
        *(ull*)&As2[acol + 1][arow * 2] = pk2(av.y, av.y);
        *(ull*)&As2[acol + 2][arow * 2] = pk2(av.z, av.z);
        *(ull*)&As2[acol + 3][arow * 2] = pk2(av.w, av.w);

        int c = k0 + brow;
        float4 bv = *(const float4*)(Bp + (size_t)c * N + n0 + bcol);
        if (FUSE_GN) {
            int g = c >> 6;
            float rs = g_rsig[b * NGRP + g];
            float mu = g_mu[b * NGRP + g];
            float w  = gnw[c] * rs;
            float bb = gnb[c] - mu * w;
            bv.x = bv.x * w + bb;
            bv.y = bv.y * w + bb;
            bv.z = bv.z * w + bb;
            bv.w = bv.w * w + bb;
        }
        *(float4*)&Bs[brow][bcol] = bv;
        __syncthreads();

        #pragma unroll
        for (int kk = 0; kk < 8; kk++) {
            const ull* a2 = (const ull*)&As2[kk][2 * tm];
            const ull* b2 = (const ull*)&Bs[kk][tn];
            ull ra[8], rb[4];
            #pragma unroll
            for (int i = 0; i < 8; i++) ra[i] = a2[i];
            #pragma unroll
            for (int j = 0; j < 4; j++) rb[j] = b2[j];
            #pragma unroll
            for (int i = 0; i < 8; i++)
                #pragma unroll
                for (int j = 0; j < 4; j++)
                    fma2(acc[i][j], ra[i], rb[j]);
        }
        __syncthreads();
    }

    #pragma unroll
    for (int i = 0; i < 8; i++) {
        float bvv = ADD_BIAS ? bias[m0 + tm + i] : 0.f;
        float2 t0 = up2(acc[i][0]), t1 = up2(acc[i][1]);
        float2 t2 = up2(acc[i][2]), t3 = up2(acc[i][3]);
        float4 o0 = make_float4(t0.x + bvv, t0.y + bvv, t1.x + bvv, t1.y + bvv);
        float4 o1 = make_float4(t2.x + bvv, t2.y + bvv, t3.x + bvv, t3.y + bvv);
        float* cr = Cp + (size_t)(m0 + tm + i) * N + n0 + tn;
        *(float4*)(cr)     = o0;
        *(float4*)(cr + 4) = o1;
    }
}

// ---------------- 3) softmax over K rows (in place in g_qkv) ---------------
__global__ __launch_bounds__(256) void softmax_kernel()
{
    int row = blockIdx.x;
    int b = row >> 8, ch = row & 255;
    float* p = g_qkv + (size_t)(b * M3 + CCH + ch) * NSP;
    float4* p4 = (float4*)p;

    float4 v[4];
    float mx = -3.4e38f;
    #pragma unroll
    for (int i = 0; i < 4; i++) {
        v[i] = p4[threadIdx.x + i * 256];
        mx = fmaxf(mx, fmaxf(fmaxf(v[i].x, v[i].y), fmaxf(v[i].z, v[i].w)));
    }
    __shared__ float sm[8], ssum[8];
    #pragma unroll
    for (int o = 16; o; o >>= 1) mx = fmaxf(mx, __shfl_xor_sync(0xffffffffu, mx, o));
    int w = threadIdx.x >> 5, l = threadIdx.x & 31;
    if (l == 0) sm[w] = mx;
    __syncthreads();
    mx = sm[0];
    #pragma unroll
    for (int i = 1; i < 8; i++) mx = fmaxf(mx, sm[i]);

    float s = 0.f;
    #pragma unroll
    for (int i = 0; i < 4; i++) {
        v[i].x = expf(v[i].x - mx);
        v[i].y = expf(v[i].y - mx);
        v[i].z = expf(v[i].z - mx);
        v[i].w = expf(v[i].w - mx);
        s += v[i].x + v[i].y + v[i].z + v[i].w;
    }
    #pragma unroll
    for (int o = 16; o; o >>= 1) s += __shfl_xor_sync(0xffffffffu, s, o);
    if (l == 0) ssum[w] = s;
    __syncthreads();
    s = 0.f;
    #pragma unroll
    for (int i = 0; i < 8; i++) s += ssum[i];
    float r = 1.0f / s;
    #pragma unroll
    for (int i = 0; i < 4; i++) {
        v[i].x *= r; v[i].y *= r; v[i].z *= r; v[i].w *= r;
        p4[threadIdx.x + i * 256] = v[i];
    }
}

// ---------------- 4) att partials: split the n loop 8 ways -----------------
// grid = 1024 (bh*8+chunk), block = 256.
__global__ __launch_bounds__(256) void att_kernel()
{
    int bh = blockIdx.x >> 3;
    int chunk = blockIdx.x & (ACH - 1);
    int b = bh >> 3, h = bh & 7;
    const float* kp = g_qkv + (size_t)(b * M3 + CCH     + h * HD) * NSP;
    const float* vp = g_qkv + (size_t)(b * M3 + 2 * CCH + h * HD) * NSP;

    __shared__ float ks[128][33];
    __shared__ float vs[128][33];

    int tid = threadIdx.x;
    int d0 = (tid >> 4) << 1;
    int e0 = (tid & 15) << 1;
    float a00 = 0.f, a01 = 0.f, a10 = 0.f, a11 = 0.f;

    int nbeg = chunk * (NSP / ACH);
    int nend = nbeg + (NSP / ACH);
    for (int n0 = nbeg; n0 < nend; n0 += 128) {
        #pragma unroll
        for (int t = 0; t < 4; t++) {
            int lin = tid + t * 256;
            int d   = lin >> 5;
            int nq  = (lin & 31) << 2;
            float4 kv = *(const float4*)(kp + (size_t)d * NSP + n0 + nq);
            ks[nq + 0][d] = kv.x; ks[nq + 1][d] = kv.y;
            ks[nq + 2][d] = kv.z; ks[nq + 3][d] = kv.w;
            float4 vv = *(const float4*)(vp + (size_t)d * NSP + n0 + nq);
            vs[nq + 0][d] = vv.x; vs[nq + 1][d] = vv.y;
            vs[nq + 2][d] = vv.z; vs[nq + 3][d] = vv.w;
        }
        __syncthreads();
        #pragma unroll 8
        for (int nn = 0; nn < 128; nn++) {
            float k0v = ks[nn][d0], k1v = ks[nn][d0 + 1];
            float v0v = vs[nn][e0], v1v = vs[nn][e0 + 1];
            a00 += k0v * v0v; a01 += k0v * v1v;
            a10 += k1v * v0v; a11 += k1v * v1v;
        }
        __syncthreads();
    }
    float* ap = g_attp + (size_t)blockIdx.x * HD * HD;
    ap[(d0 + 0) * HD + e0 + 0] = a00;
    ap[(d0 + 0) * HD + e0 + 1] = a01;
    ap[(d0 + 1) * HD + e0 + 0] = a10;
    ap[(d0 + 1) * HD + e0 + 1] = a11;
}

// reduce the 8 partials: grid = 128, block = 256
__global__ __launch_bounds__(256) void att_reduce_kernel()
{
    int bh = blockIdx.x;
    #pragma unroll
    for (int t = 0; t < 4; t++) {
        int idx = threadIdx.x + t * 256;
        float s = 0.f;
        #pragma unroll
        for (int c = 0; c < ACH; c++)
            s += g_attp[(size_t)(bh * ACH + c) * 1024 + idx];
        g_att[(size_t)bh * 1024 + idx] = s;
    }
}

// ---------------- 5) out[b, h*32+e, n] = sum_d att[d,e] * q[d,n] -----------
__global__ __launch_bounds__(256) void outmul_kernel()
{
    int bh = blockIdx.y;
    int b = bh >> 3, h = bh & 7;
    int n  = blockIdx.x * 32 + (threadIdx.x & 31);
    int eg = threadIdx.x >> 5;

    __shared__ float4 att_s[32][8];
    ((float4*)att_s)[threadIdx.x] = ((const float4*)(g_att + (size_t)bh * 1024))[threadIdx.x];
    __syncthreads();

    const float* qp = g_qkv + (size_t)(b * M3 + h * HD) * NSP + n;
    float acc0 = 0.f, acc1 = 0.f, acc2 = 0.f, acc3 = 0.f;
    #pragma unroll
    for (int d = 0; d < 32; d++) {
        float qv = qp[(size_t)d * NSP];
        float4 a = att_s[d][eg];
        acc0 += a.x * qv; acc1 += a.y * qv;
        acc2 += a.z * qv; acc3 += a.w * qv;
    }
    float* op = g_attout + (size_t)(b * CCH + h * HD + eg * 4) * NSP + n;
    op[0 * NSP] = acc0; op[1 * NSP] = acc1;
    op[2 * NSP] = acc2; op[3 * NSP] = acc3;
}

// ---------------- launch ----------------------------------------------------
extern "C" void kernel_launch(void* const* d_in, const int* in_sizes, int n_in,
                              void* d_out, int out_size)
{
    const float* x     = (const float*)d_in[0];
    const float* gnw   = (const float*)d_in[1];
    const float* gnb   = (const float*)d_in[2];
    const float* qkvw  = (const float*)d_in[3];
    const float* projw = (const float*)d_in[4];
    const float* projb = (const float*)d_in[5];
    float* out = (float*)d_out;

    gn_stats_kernel<<<BATCH * NGRP, 1024>>>(x);

    sgemm_kernel<M3, true, false, false, true>
        <<<dim3(NSP / 128, M3 / 128, BATCH), 256>>>(qkvw, x, nullptr, gnw, gnb, nullptr);

    softmax_kernel<<<BATCH * CCH, 256>>>();

    att_kernel<<<BATCH * NH * ACH, 256>>>();
    att_reduce_kernel<<<BATCH * NH, 256>>>();

    outmul_kernel<<<dim3(NSP / 32, BATCH * NH), 256>>>();

    sgemm_kernel<CCH, false, true, true, false>
        <<<dim3(NSP / 128, CCH / 128, BATCH), 256>>>(projw, nullptr, out, nullptr, nullptr, projb);
}

// round 3
// speedup vs baseline: 1.9409x; 1.9409x over previous
#include <cuda_runtime.h>
#include <cuda_bf16.h>
#include <math.h>

#define BATCH 16
#define CCH   256
#define NSP   4096
#define M3    768
#define NGRP  4
#define CPG   64
#define NH    8
#define HD    32
#define ACH   8

#define PA 40    // A smem row pitch (bf16 elems)
#define PB 136   // B smem row pitch (bf16 elems)

typedef unsigned int uint;

// ---------------- scratch ----------------------------------------------------
__device__ float g_qkv[BATCH * M3 * NSP];
__device__ float g_attout[BATCH * CCH * NSP];
__device__ float g_att[BATCH * NH * HD * HD];
__device__ float g_attp[BATCH * NH * ACH * HD * HD];
__device__ float g_mu[BATCH * NGRP];
__device__ float g_rsig[BATCH * NGRP];

// ---------------- helpers ----------------------------------------------------
__device__ __forceinline__ uint pkbf2(float a, float b) {
    __nv_bfloat162 t;
    t.x = __float2bfloat16(a);
    t.y = __float2bfloat16(b);
    return *reinterpret_cast<uint*>(&t);
}

// split float4 into hi (bf16x4) and lo (residual bf16x4)
__device__ __forceinline__ void split4(float4 v, uint2& hi, uint2& lo) {
    float hx = __bfloat162float(__float2bfloat16(v.x));
    float hy = __bfloat162float(__float2bfloat16(v.y));
    float hz = __bfloat162float(__float2bfloat16(v.z));
    float hw = __bfloat162float(__float2bfloat16(v.w));
    hi.x = pkbf2(hx, hy);
    hi.y = pkbf2(hz, hw);
    lo.x = pkbf2(v.x - hx, v.y - hy);
    lo.y = pkbf2(v.z - hz, v.w - hw);
}

__device__ __forceinline__ void ldsm4(uint& r0, uint& r1, uint& r2, uint& r3, uint addr) {
    asm volatile("ldmatrix.sync.aligned.m8n8.x4.shared.b16 {%0,%1,%2,%3}, [%4];"
                 : "=r"(r0), "=r"(r1), "=r"(r2), "=r"(r3) : "r"(addr));
}
__device__ __forceinline__ void ldsm2t(uint& r0, uint& r1, uint addr) {
    asm volatile("ldmatrix.sync.aligned.m8n8.x2.trans.shared.b16 {%0,%1}, [%2];"
                 : "=r"(r0), "=r"(r1) : "r"(addr));
}
__device__ __forceinline__ void mma16816(float4& d, uint a0, uint a1, uint a2, uint a3,
                                         uint b0, uint b1) {
    asm volatile("mma.sync.aligned.m16n8k16.row.col.f32.bf16.bf16.f32 "
                 "{%0,%1,%2,%3}, {%4,%5,%6,%7}, {%8,%9}, {%0,%1,%2,%3};"
                 : "+f"(d.x), "+f"(d.y), "+f"(d.z), "+f"(d.w)
                 : "r"(a0), "r"(a1), "r"(a2), "r"(a3), "r"(b0), "r"(b1));
}

// ---------------- 1) GroupNorm statistics ------------------------------------
__global__ __launch_bounds__(1024) void gn_stats_kernel(const float* __restrict__ x)
{
    int bg = blockIdx.x;
    const float4* p = (const float4*)(x + (size_t)bg * CPG * NSP);
    float s = 0.f, sq = 0.f;
    for (int i = threadIdx.x; i < 65536; i += 1024) {
        float4 v = p[i];
        s  += v.x + v.y + v.z + v.w;
        sq += v.x * v.x + v.y * v.y + v.z * v.z + v.w * v.w;
    }
    __shared__ float ss[32], ssq[32];
    #pragma unroll
    for (int o = 16; o; o >>= 1) {
        s  += __shfl_down_sync(0xffffffffu, s, o);
        sq += __shfl_down_sync(0xffffffffu, sq, o);
    }
    int w = threadIdx.x >> 5, l = threadIdx.x & 31;
    if (l == 0) { ss[w] = s; ssq[w] = sq; }
    __syncthreads();
    if (w == 0) {
        s  = ss[l];
        sq = ssq[l];
        #pragma unroll
        for (int o = 16; o; o >>= 1) {
            s  += __shfl_down_sync(0xffffffffu, s, o);
            sq += __shfl_down_sync(0xffffffffu, sq, o);
        }
        if (l == 0) {
            const float inv = 1.0f / (float)(CPG * NSP);
            float mu  = s * inv;
            float var = sq * inv - mu * mu;
            g_mu[bg]   = mu;
            g_rsig[bg] = rsqrtf(var + 1e-5f);
        }
    }
}

// ---------------- 2/6) tensor-core GEMM, bf16 3-term split -------------------
// C[b][o][n] = sum_c A[o][c] * B[b][c][n]   (+ optional GN on B, bias on C)
template<int M, bool FUSE_GN, bool ADD_BIAS, bool B_SYM, bool C_SYM>
__global__ __launch_bounds__(256, 1) void tgemm_kernel(
    const float* __restrict__ A,
    const float* __restrict__ Bext,
    float*       __restrict__ Cext,
    const float* __restrict__ gnw,
    const float* __restrict__ gnb,
    const float* __restrict__ bias)
{
    const int K = 256, N = NSP;
    int b = blockIdx.z;
    const float* Bbase = B_SYM ? g_attout : Bext;
    float*       Cbase = C_SYM ? g_qkv    : Cext;
    const float* Bp = Bbase + (size_t)b * K * N;
    float*       Cp = Cbase + (size_t)b * M * N;
    int m0 = blockIdx.y * 128, n0 = blockIdx.x * 128;

    __shared__ __nv_bfloat16 AsH[128 * PA];
    __shared__ __nv_bfloat16 AsL[128 * PA];
    __shared__ __nv_bfloat16 BsH[32 * PB];
    __shared__ __nv_bfloat16 BsL[32 * PB];

    int tid  = threadIdx.x;
    int wid  = tid >> 5;
    int lane = tid & 31;
    int wm = (wid >> 2) * 64;   // warp m-offset within block
    int wn = (wid & 3) * 32;    // warp n-offset

    // ldmatrix per-lane address components
    int a_row = (lane & 7) + ((lane >> 3) & 1) * 8;
    int a_koff = ((lane >> 4) & 1) * 8;
    int b_row = (lane & 7) + ((lane >> 3) & 1) * 8;

    uint aH_base = (uint)__cvta_generic_to_shared(AsH);
    uint aL_base = (uint)__cvta_generic_to_shared(AsL);
    uint bH_base = (uint)__cvta_generic_to_shared(BsH);
    uint bL_base = (uint)__cvta_generic_to_shared(BsL);

    float4 acc[4][4];
    #pragma unroll
    for (int i = 0; i < 4; i++)
        #pragma unroll
        for (int j = 0; j < 4; j++) acc[i][j] = make_float4(0.f, 0.f, 0.f, 0.f);

    for (int k0 = 0; k0 < K; k0 += 32) {
        // ---- load + split A tile 128x32 ----
        #pragma unroll
        for (int t = 0; t < 4; t++) {
            int idx = tid + t * 256;
            int row = idx >> 3;
            int q   = idx & 7;
            float4 av = *(const float4*)(A + (size_t)(m0 + row) * K + k0 + q * 4);
            uint2 hi, lo;
            split4(av, hi, lo);
            *(uint2*)&AsH[row * PA + q * 4] = hi;
            *(uint2*)&AsL[row * PA + q * 4] = lo;
        }
        // ---- load + GN + split B tile 32x128 ----
        #pragma unroll
        for (int t = 0; t < 4; t++) {
            int idx = tid + t * 256;
            int k   = idx >> 5;
            int nq  = (idx & 31) * 4;
            float4 bv = *(const float4*)(Bp + (size_t)(k0 + k) * N + n0 + nq);
            if (FUSE_GN) {
                int c = k0 + k;
                int g = c >> 6;
                float rs = g_rsig[b * NGRP + g];
                float mu = g_mu[b * NGRP + g];
                float w  = gnw[c] * rs;
                float bb = gnb[c] - mu * w;
                bv.x = bv.x * w + bb;
                bv.y = bv.y * w + bb;
                bv.z = bv.z * w + bb;
                bv.w = bv.w * w + bb;
            }
            uint2 hi, lo;
            split4(bv, hi, lo);
            *(uint2*)&BsH[k * PB + nq] = hi;
            *(uint2*)&BsL[k * PB + nq] = lo;
        }
        __syncthreads();

        #pragma unroll
        for (int kk = 0; kk < 32; kk += 16) {
            uint ah[4][4], al[4][4], bh[4][2], bl[4][2];
            #pragma unroll
            for (int mt = 0; mt < 4; mt++) {
                uint off = ((uint)(wm + mt * 16 + a_row) * PA + kk + a_koff) * 2;
                ldsm4(ah[mt][0], ah[mt][1], ah[mt][2], ah[mt][3], aH_base + off);
                ldsm4(al[mt][0], al[mt][1], al[mt][2], al[mt][3], aL_base + off);
            }
            #pragma unroll
            for (int nt = 0; nt < 4; nt++) {
                uint off = ((uint)(kk + b_row) * PB + wn + nt * 8) * 2;
                ldsm2t(bh[nt][0], bh[nt][1], bH_base + off);
                ldsm2t(bl[nt][0], bl[nt][1], bL_base + off);
            }
            #pragma unroll
            for (int mt = 0; mt < 4; mt++)
                #pragma unroll
                for (int nt = 0; nt < 4; nt++) {
                    mma16816(acc[mt][nt], ah[mt][0], ah[mt][1], ah[mt][2], ah[mt][3],
                             bh[nt][0], bh[nt][1]);
                    mma16816(acc[mt][nt], ah[mt][0], ah[mt][1], ah[mt][2], ah[mt][3],
                             bl[nt][0], bl[nt][1]);
                    mma16816(acc[mt][nt], al[mt][0], al[mt][1], al[mt][2], al[mt][3],
                             bh[nt][0], bh[nt][1]);
                }
        }
        __syncthreads();
    }

    // ---- epilogue: direct float2 stores ----
    int g = lane >> 2, t4 = lane & 3;
    #pragma unroll
    for (int mt = 0; mt < 4; mt++) {
        int m_g = m0 + wm + mt * 16 + g;
        float b0v = ADD_BIAS ? bias[m_g]     : 0.f;
        float b1v = ADD_BIAS ? bias[m_g + 8] : 0.f;
        #pragma unroll
        for (int nt = 0; nt < 4; nt++) {
            int n_g = n0 + wn + nt * 8 + 2 * t4;
            float4 d = acc[mt][nt];
            float2 lo = make_float2(d.x + b0v, d.y + b0v);
            float2 hi = make_float2(d.z + b1v, d.w + b1v);
            *(float2*)(Cp + (size_t)m_g * N + n_g)       = lo;
            *(float2*)(Cp + (size_t)(m_g + 8) * N + n_g) = hi;
        }
    }
}

// ---------------- 3) softmax over K rows --------------------------------------
__global__ __launch_bounds__(256) void softmax_kernel()
{
    int row = blockIdx.x;
    int b = row >> 8, ch = row & 255;
    float* p = g_qkv + (size_t)(b * M3 + CCH + ch) * NSP;
    float4* p4 = (float4*)p;

    float4 v[4];
    float mx = -3.4e38f;
    #pragma unroll
    for (int i = 0; i < 4; i++) {
        v[i] = p4[threadIdx.x + i * 256];
        mx = fmaxf(mx, fmaxf(fmaxf(v[i].x, v[i].y), fmaxf(v[i].z, v[i].w)));
    }
    __shared__ float sm[8], ssum[8];
    #pragma unroll
    for (int o = 16; o; o >>= 1) mx = fmaxf(mx, __shfl_xor_sync(0xffffffffu, mx, o));
    int w = threadIdx.x >> 5, l = threadIdx.x & 31;
    if (l == 0) sm[w] = mx;
    __syncthreads();
    mx = sm[0];
    #pragma unroll
    for (int i = 1; i < 8; i++) mx = fmaxf(mx, sm[i]);

    float s = 0.f;
    #pragma unroll
    for (int i = 0; i < 4; i++) {
        v[i].x = expf(v[i].x - mx);
        v[i].y = expf(v[i].y - mx);
        v[i].z = expf(v[i].z - mx);
        v[i].w = expf(v[i].w - mx);
        s += v[i].x + v[i].y + v[i].z + v[i].w;
    }
    #pragma unroll
    for (int o = 16; o; o >>= 1) s += __shfl_xor_sync(0xffffffffu, s, o);
    if (l == 0) ssum[w] = s;
    __syncthreads();
    s = 0.f;
    #pragma unroll
    for (int i = 0; i < 8; i++) s += ssum[i];
    float r = 1.0f / s;
    #pragma unroll
    for (int i = 0; i < 4; i++) {
        v[i].x *= r; v[i].y *= r; v[i].z *= r; v[i].w *= r;
        p4[threadIdx.x + i * 256] = v[i];
    }
}

// ---------------- 4) att partials ---------------------------------------------
__global__ __launch_bounds__(256) void att_kernel()
{
    int bh = blockIdx.x >> 3;
    int chunk = blockIdx.x & (ACH - 1);
    int b = bh >> 3, h = bh & 7;
    const float* kp = g_qkv + (size_t)(b * M3 + CCH     + h * HD) * NSP;
    const float* vp = g_qkv + (size_t)(b * M3 + 2 * CCH + h * HD) * NSP;

    __shared__ float ks[128][34];
    __shared__ float vs[128][34];

    int tid = threadIdx.x;
    int d0 = (tid >> 4) << 1;
    int e0 = (tid & 15) << 1;
    float a00 = 0.f, a01 = 0.f, a10 = 0.f, a11 = 0.f;

    int nbeg = chunk * (NSP / ACH);
    int nend = nbeg + (NSP / ACH);
    for (int n0 = nbeg; n0 < nend; n0 += 128) {
        #pragma unroll
        for (int t = 0; t < 4; t++) {
            int lin = tid + t * 256;
            int d   = lin >> 5;
            int nq  = (lin & 31) << 2;
            float4 kv = *(const float4*)(kp + (size_t)d * NSP + n0 + nq);
            ks[nq + 0][d] = kv.x; ks[nq + 1][d] = kv.y;
            ks[nq + 2][d] = kv.z; ks[nq + 3][d] = kv.w;
            float4 vv = *(const float4*)(vp + (size_t)d * NSP + n0 + nq);
            vs[nq + 0][d] = vv.x; vs[nq + 1][d] = vv.y;
            vs[nq + 2][d] = vv.z; vs[nq + 3][d] = vv.w;
        }
        __syncthreads();
        #pragma unroll 8
        for (int nn = 0; nn < 128; nn++) {
            float2 kk2 = *(const float2*)&ks[nn][d0];
            float2 vv2 = *(const float2*)&vs[nn][e0];
            a00 += kk2.x * vv2.x; a01 += kk2.x * vv2.y;
            a10 += kk2.y * vv2.x; a11 += kk2.y * vv2.y;
        }
        __syncthreads();
    }
    float* ap = g_attp + (size_t)blockIdx.x * HD * HD;
    ap[(d0 + 0) * HD + e0 + 0] = a00;
    ap[(d0 + 0) * HD + e0 + 1] = a01;
    ap[(d0 + 1) * HD + e0 + 0] = a10;
    ap[(d0 + 1) * HD + e0 + 1] = a11;
}

__global__ __launch_bounds__(256) void att_reduce_kernel()
{
    int bh = blockIdx.x;
    #pragma unroll
    for (int t = 0; t < 4; t++) {
        int idx = threadIdx.x + t * 256;
        float s = 0.f;
        #pragma unroll
        for (int c = 0; c < ACH; c++)
            s += g_attp[(size_t)(bh * ACH + c) * 1024 + idx];
        g_att[(size_t)bh * 1024 + idx] = s;
    }
}

// ---------------- 5) out = att^T * q ------------------------------------------
__global__ __launch_bounds__(256) void outmul_kernel()
{
    int bh = blockIdx.y;
    int b = bh >> 3, h = bh & 7;
    int n  = blockIdx.x * 32 + (threadIdx.x & 31);
    int eg = threadIdx.x >> 5;

    __shared__ float4 att_s[32][8];
    ((float4*)att_s)[threadIdx.x] = ((const float4*)(g_att + (size_t)bh * 1024))[threadIdx.x];
    __syncthreads();

    const float* qp = g_qkv + (size_t)(b * M3 + h * HD) * NSP + n;
    float acc0 = 0.f, acc1 = 0.f, acc2 = 0.f, acc3 = 0.f;
    #pragma unroll
    for (int d = 0; d < 32; d++) {
        float qv = qp[(size_t)d * NSP];
        float4 a = att_s[d][eg];
        acc0 += a.x * qv; acc1 += a.y * qv;
        acc2 += a.z * qv; acc3 += a.w * qv;
    }
    float* op = g_attout + (size_t)(b * CCH + h * HD + eg * 4) * NSP + n;
    op[0 * NSP] = acc0; op[1 * NSP] = acc1;
    op[2 * NSP] = acc2; op[3 * NSP] = acc3;
}

// ---------------- launch --------------------------------------------------------
extern "C" void kernel_launch(void* const* d_in, const int* in_sizes, int n_in,
                              void* d_out, int out_size)
{
    const float* x     = (const float*)d_in[0];
    const float* gnw   = (const float*)d_in[1];
    const float* gnb   = (const float*)d_in[2];
    const float* qkvw  = (const float*)d_in[3];
    const float* projw = (const float*)d_in[4];
    const float* projb = (const float*)d_in[5];
    float* out = (float*)d_out;

    gn_stats_kernel<<<BATCH * NGRP, 1024>>>(x);

    tgemm_kernel<M3, true, false, false, true>
        <<<dim3(NSP / 128, M3 / 128, BATCH), 256>>>(qkvw, x, nullptr, gnw, gnb, nullptr);

    softmax_kernel<<<BATCH * CCH, 256>>>();

    att_kernel<<<BATCH * NH * ACH, 256>>>();
    att_reduce_kernel<<<BATCH * NH, 256>>>();

    outmul_kernel<<<dim3(NSP / 32, BATCH * NH), 256>>>();

    tgemm_kernel<CCH, false, true, true, false>
        <<<dim3(NSP / 128, CCH / 128, BATCH), 256>>>(projw, nullptr, out, nullptr, nullptr, projb);
}

// round 4
// speedup vs baseline: 2.1981x; 1.1325x over previous
#include <cuda_runtime.h>
#include <cuda_bf16.h>
#include <math.h>

#define BATCH 16
#define CCH   256
#define NSP   4096
#define M3    768
#define NGRP  4
#define CPG   64
#define NH    8
#define HD    32

#define PA 40    // A smem row pitch (bf16 elems)
#define PB 136   // B smem row pitch (bf16 elems)
#define ATT_P 36 // att smem row pitch (floats)

typedef unsigned int uint;

// ---------------- scratch ----------------------------------------------------
__device__ float g_qkv[BATCH * M3 * NSP];
__device__ float g_att[BATCH * NH * HD * HD];
__device__ float g_attp[BATCH * NH * 32 * HD * HD];   // 32 partials per bh
__device__ float g_wf[BATCH * CCH * CCH];             // folded proj*att weights
__device__ float g_mu[BATCH * NGRP];
__device__ float g_rsig[BATCH * NGRP];
__device__ float g_gnp[BATCH * NGRP * 4 * 2];         // gn partials
__device__ float g_kmx[BATCH * CCH];                  // per k-row max
__device__ float g_krs[BATCH * CCH];                  // per k-row 1/sum(exp)

// ---------------- helpers ----------------------------------------------------
__device__ __forceinline__ uint pkbf2(float a, float b) {
    __nv_bfloat162 t;
    t.x = __float2bfloat16(a);
    t.y = __float2bfloat16(b);
    return *reinterpret_cast<uint*>(&t);
}
__device__ __forceinline__ void split4(float4 v, uint2& hi, uint2& lo) {
    float hx = __bfloat162float(__float2bfloat16(v.x));
    float hy = __bfloat162float(__float2bfloat16(v.y));
    float hz = __bfloat162float(__float2bfloat16(v.z));
    float hw = __bfloat162float(__float2bfloat16(v.w));
    hi.x = pkbf2(hx, hy);
    hi.y = pkbf2(hz, hw);
    lo.x = pkbf2(v.x - hx, v.y - hy);
    lo.y = pkbf2(v.z - hz, v.w - hw);
}
__device__ __forceinline__ void ldsm4(uint& r0, uint& r1, uint& r2, uint& r3, uint addr) {
    asm volatile("ldmatrix.sync.aligned.m8n8.x4.shared.b16 {%0,%1,%2,%3}, [%4];"
                 : "=r"(r0), "=r"(r1), "=r"(r2), "=r"(r3) : "r"(addr));
}
__device__ __forceinline__ void ldsm2t(uint& r0, uint& r1, uint addr) {
    asm volatile("ldmatrix.sync.aligned.m8n8.x2.trans.shared.b16 {%0,%1}, [%2];"
                 : "=r"(r0), "=r"(r1) : "r"(addr));
}
__device__ __forceinline__ void mma16816(float4& d, uint a0, uint a1, uint a2, uint a3,
                                         uint b0, uint b1) {
    asm volatile("mma.sync.aligned.m16n8k16.row.col.f32.bf16.bf16.f32 "
                 "{%0,%1,%2,%3}, {%4,%5,%6,%7}, {%8,%9}, {%0,%1,%2,%3};"
                 : "+f"(d.x), "+f"(d.y), "+f"(d.z), "+f"(d.w)
                 : "r"(a0), "r"(a1), "r"(a2), "r"(a3), "r"(b0), "r"(b1));
}

// ---------------- 1) GroupNorm stats: partial + final ------------------------
__global__ __launch_bounds__(256) void gn_partial_kernel(const float* __restrict__ x)
{
    int bg = blockIdx.x >> 2, part = blockIdx.x & 3;
    const float4* p = (const float4*)x + (size_t)bg * 65536 + part * 16384;
    float s = 0.f, sq = 0.f;
    for (int i = threadIdx.x; i < 16384; i += 256) {
        float4 v = p[i];
        s  += v.x + v.y + v.z + v.w;
        sq += v.x * v.x + v.y * v.y + v.z * v.z + v.w * v.w;
    }
    __shared__ float ss[8], ssq[8];
    #pragma unroll
    for (int o = 16; o; o >>= 1) {
        s  += __shfl_down_sync(0xffffffffu, s, o);
        sq += __shfl_down_sync(0xffffffffu, sq, o);
    }
    int w = threadIdx.x >> 5, l = threadIdx.x & 31;
    if (l == 0) { ss[w] = s; ssq[w] = sq; }
    __syncthreads();
    if (threadIdx.x == 0) {
        s = 0.f; sq = 0.f;
        #pragma unroll
        for (int i = 0; i < 8; i++) { s += ss[i]; sq += ssq[i]; }
        g_gnp[blockIdx.x * 2]     = s;
        g_gnp[blockIdx.x * 2 + 1] = sq;
    }
}
__global__ void gn_final_kernel()
{
    int bg = threadIdx.x;   // 0..63
    float s = 0.f, sq = 0.f;
    #pragma unroll
    for (int i = 0; i < 4; i++) {
        s  += g_gnp[(bg * 4 + i) * 2];
        sq += g_gnp[(bg * 4 + i) * 2 + 1];
    }
    const float inv = 1.0f / (float)(CPG * NSP);
    float mu  = s * inv;
    float var = sq * inv - mu * mu;
    g_mu[bg]   = mu;
    g_rsig[bg] = rsqrtf(var + 1e-5f);
}

// ---------------- 2/7) tensor-core GEMM, bf16 3-term split -------------------
// C[b][o][n] = sum_c A[o][c] * B[b][c][n]
template<int M, bool FUSE_GN, bool ADD_BIAS, bool B_QKV, bool C_QKV, bool A_BATCH>
__global__ __launch_bounds__(256, 1) void tgemm_kernel(
    const float* __restrict__ A,
    const float* __restrict__ Bext,
    float*       __restrict__ Cext,
    const float* __restrict__ gnw,
    const float* __restrict__ gnb,
    const float* __restrict__ bias)
{
    const int K = 256, N = NSP;
    int b = blockIdx.z;
    const float* Ap = A_BATCH ? (g_wf + (size_t)b * CCH * CCH) : A;
    const float* Bp = B_QKV ? (g_qkv + (size_t)b * M3 * NSP)
                            : (Bext + (size_t)b * K * N);
    float*       Cp = C_QKV ? (g_qkv + (size_t)b * M * N)
                            : (Cext + (size_t)b * M * N);
    int m0 = blockIdx.y * 128, n0 = blockIdx.x * 128;

    __shared__ __nv_bfloat16 AsH[128 * PA];
    __shared__ __nv_bfloat16 AsL[128 * PA];
    __shared__ __nv_bfloat16 BsH[32 * PB];
    __shared__ __nv_bfloat16 BsL[32 * PB];

    int tid  = threadIdx.x;
    int wid  = tid >> 5;
    int lane = tid & 31;
    int wm = (wid >> 2) * 64;
    int wn = (wid & 3) * 32;

    int a_row = (lane & 7) + ((lane >> 3) & 1) * 8;
    int a_koff = ((lane >> 4) & 1) * 8;
    int b_row = (lane & 7) + ((lane >> 3) & 1) * 8;

    uint aH_base = (uint)__cvta_generic_to_shared(AsH);
    uint aL_base = (uint)__cvta_generic_to_shared(AsL);
    uint bH_base = (uint)__cvta_generic_to_shared(BsH);
    uint bL_base = (uint)__cvta_generic_to_shared(BsL);

    float4 acc[4][4];
    #pragma unroll
    for (int i = 0; i < 4; i++)
        #pragma unroll
        for (int j = 0; j < 4; j++) acc[i][j] = make_float4(0.f, 0.f, 0.f, 0.f);

    for (int k0 = 0; k0 < K; k0 += 32) {
        #pragma unroll
        for (int t = 0; t < 4; t++) {
            int idx = tid + t * 256;
            int row = idx >> 3;
            int q   = idx & 7;
            float4 av = *(const float4*)(Ap + (size_t)(m0 + row) * K + k0 + q * 4);
            uint2 hi, lo;
            split4(av, hi, lo);
            *(uint2*)&AsH[row * PA + q * 4] = hi;
            *(uint2*)&AsL[row * PA + q * 4] = lo;
        }
        #pragma unroll
        for (int t = 0; t < 4; t++) {
            int idx = tid + t * 256;
            int k   = idx >> 5;
            int nq  = (idx & 31) * 4;
            float4 bv = *(const float4*)(Bp + (size_t)(k0 + k) * N + n0 + nq);
            if (FUSE_GN) {
                int c = k0 + k;
                int g = c >> 6;
                float rs = g_rsig[b * NGRP + g];
                float mu = g_mu[b * NGRP + g];
                float w  = gnw[c] * rs;
                float bb = gnb[c] - mu * w;
                bv.x = bv.x * w + bb;
                bv.y = bv.y * w + bb;
                bv.z = bv.z * w + bb;
                bv.w = bv.w * w + bb;
            }
            uint2 hi, lo;
            split4(bv, hi, lo);
            *(uint2*)&BsH[k * PB + nq] = hi;
            *(uint2*)&BsL[k * PB + nq] = lo;
        }
        __syncthreads();

        #pragma unroll
        for (int kk = 0; kk < 32; kk += 16) {
            uint ah[4][4], al[4][4], bh[4][2], bl[4][2];
            #pragma unroll
            for (int mt = 0; mt < 4; mt++) {
                uint off = ((uint)(wm + mt * 16 + a_row) * PA + kk + a_koff) * 2;
                ldsm4(ah[mt][0], ah[mt][1], ah[mt][2], ah[mt][3], aH_base + off);
                ldsm4(al[mt][0], al[mt][1], al[mt][2], al[mt][3], aL_base + off);
            }
            #pragma unroll
            for (int nt = 0; nt < 4; nt++) {
                uint off = ((uint)(kk + b_row) * PB + wn + nt * 8) * 2;
                ldsm2t(bh[nt][0], bh[nt][1], bH_base + off);
                ldsm2t(bl[nt][0], bl[nt][1], bL_base + off);
            }
            #pragma unroll
            for (int mt = 0; mt < 4; mt++)
                #pragma unroll
                for (int nt = 0; nt < 4; nt++) {
                    mma16816(acc[mt][nt], ah[mt][0], ah[mt][1], ah[mt][2], ah[mt][3],
                             bh[nt][0], bh[nt][1]);
                    mma16816(acc[mt][nt], ah[mt][0], ah[mt][1], ah[mt][2], ah[mt][3],
                             bl[nt][0], bl[nt][1]);
                    mma16816(acc[mt][nt], al[mt][0], al[mt][1], al[mt][2], al[mt][3],
                             bh[nt][0], bh[nt][1]);
                }
        }
        __syncthreads();
    }

    int g = lane >> 2, t4 = lane & 3;
    #pragma unroll
    for (int mt = 0; mt < 4; mt++) {
        int m_g = m0 + wm + mt * 16 + g;
        float b0v = ADD_BIAS ? bias[m_g]     : 0.f;
        float b1v = ADD_BIAS ? bias[m_g + 8] : 0.f;
        #pragma unroll
        for (int nt = 0; nt < 4; nt++) {
            int n_g = n0 + wn + nt * 8 + 2 * t4;
            float4 d = acc[mt][nt];
            float2 lo = make_float2(d.x + b0v, d.y + b0v);
            float2 hi = make_float2(d.z + b1v, d.w + b1v);
            *(float2*)(Cp + (size_t)m_g * N + n_g)       = lo;
            *(float2*)(Cp + (size_t)(m_g + 8) * N + n_g) = hi;
        }
    }
}

// ---------------- 3) k-row stats: max and 1/sum(exp) -------------------------
__global__ __launch_bounds__(256) void kstats_kernel()
{
    int row = blockIdx.x;           // b*256 + ch
    int b = row >> 8, ch = row & 255;
    const float4* p4 = (const float4*)(g_qkv + (size_t)(b * M3 + CCH + ch) * NSP);

    float4 v[4];
    float mx = -3.4e38f;
    #pragma unroll
    for (int i = 0; i < 4; i++) {
        v[i] = p4[threadIdx.x + i * 256];
        mx = fmaxf(mx, fmaxf(fmaxf(v[i].x, v[i].y), fmaxf(v[i].z, v[i].w)));
    }
    __shared__ float sm[8], ssum[8];
    #pragma unroll
    for (int o = 16; o; o >>= 1) mx = fmaxf(mx, __shfl_xor_sync(0xffffffffu, mx, o));
    int w = threadIdx.x >> 5, l = threadIdx.x & 31;
    if (l == 0) sm[w] = mx;
    __syncthreads();
    mx = sm[0];
    #pragma unroll
    for (int i = 1; i < 8; i++) mx = fmaxf(mx, sm[i]);

    float s = 0.f;
    #pragma unroll
    for (int i = 0; i < 4; i++) {
        s += __expf(v[i].x - mx) + __expf(v[i].y - mx)
           + __expf(v[i].z - mx) + __expf(v[i].w - mx);
    }
    #pragma unroll
    for (int o = 16; o; o >>= 1) s += __shfl_xor_sync(0xffffffffu, s, o);
    if (l == 0) ssum[w] = s;
    __syncthreads();
    if (threadIdx.x == 0) {
        s = 0.f;
        #pragma unroll
        for (int i = 0; i < 8; i++) s += ssum[i];
        g_kmx[row] = mx;
        g_krs[row] = 1.0f / s;
    }
}

// ---------------- 4) att partials with fused exp, 4x4 tiles ------------------
// grid = 1024 (bh*8+chunk), block = 256 = 4 subgroups x 64 threads.
__global__ __launch_bounds__(256) void att_kernel()
{
    int bh = blockIdx.x >> 3;
    int chunk = blockIdx.x & 7;
    int b = bh >> 3, h = bh & 7;
    const float* kp = g_qkv + (size_t)(b * M3 + CCH     + h * HD) * NSP;
    const float* vp = g_qkv + (size_t)(b * M3 + 2 * CCH + h * HD) * NSP;

    __shared__ float ks[128][ATT_P];
    __shared__ float vs[128][ATT_P];
    __shared__ float mxs[32];

    int tid = threadIdx.x;
    if (tid < 32) mxs[tid] = g_kmx[b * CCH + h * HD + tid];
    __syncthreads();

    int sg = tid >> 6;
    int t6 = tid & 63;
    int d0 = (t6 & 7) * 4;
    int e0 = (t6 >> 3) * 4;
    int nfill = tid & 127;           // fixed n for fill
    int dgb   = tid >> 7;            // 0 or 1

    float acc[4][4];
    #pragma unroll
    for (int i = 0; i < 4; i++)
        #pragma unroll
        for (int j = 0; j < 4; j++) acc[i][j] = 0.f;

    int nbeg = chunk * 512;
    for (int n0 = nbeg; n0 < nbeg + 512; n0 += 128) {
        // fill: 8 dg groups x 128 n; thread handles dg = dgb + 2t, n = nfill
        #pragma unroll
        for (int t = 0; t < 4; t++) {
            int dg = dgb + 2 * t;
            int dr = dg * 4;
            float4 kv;
            kv.x = __expf(kp[(size_t)(dr + 0) * NSP + n0 + nfill] - mxs[dr + 0]);
            kv.y = __expf(kp[(size_t)(dr + 1) * NSP + n0 + nfill] - mxs[dr + 1]);
            kv.z = __expf(kp[(size_t)(dr + 2) * NSP + n0 + nfill] - mxs[dr + 2]);
            kv.w = __expf(kp[(size_t)(dr + 3) * NSP + n0 + nfill] - mxs[dr + 3]);
            *(float4*)&ks[nfill][dr] = kv;
            float4 vv;
            vv.x = vp[(size_t)(dr + 0) * NSP + n0 + nfill];
            vv.y = vp[(size_t)(dr + 1) * NSP + n0 + nfill];
            vv.z = vp[(size_t)(dr + 2) * NSP + n0 + nfill];
            vv.w = vp[(size_t)(dr + 3) * NSP + n0 + nfill];
            *(float4*)&vs[nfill][dr] = vv;
        }
        __syncthreads();

        int nb = sg * 32;
        #pragma unroll 8
        for (int nn = 0; nn < 32; nn++) {
            float4 ka = *(const float4*)&ks[nb + nn][d0];
            float4 va = *(const float4*)&vs[nb + nn][e0];
            acc[0][0] += ka.x * va.x; acc[0][1] += ka.x * va.y;
            acc[0][2] += ka.x * va.z; acc[0][3] += ka.x * va.w;
            acc[1][0] += ka.y * va.x; acc[1][1] += ka.y * va.y;
            acc[1][2] += ka.y * va.z; acc[1][3] += ka.y * va.w;
            acc[2][0] += ka.z * va.x; acc[2][1] += ka.z * va.y;
            acc[2][2] += ka.z * va.z; acc[2][3] += ka.z * va.w;
            acc[3][0] += ka.w * va.x; acc[3][1] += ka.w * va.y;
            acc[3][2] += ka.w * va.z; acc[3][3] += ka.w * va.w;
        }
        __syncthreads();
    }

    float* ap = g_attp + ((size_t)blockIdx.x * 4 + sg) * 1024;
    #pragma unroll
    for (int i = 0; i < 4; i++) {
        float4 o = make_float4(acc[i][0], acc[i][1], acc[i][2], acc[i][3]);
        *(float4*)(ap + (d0 + i) * HD + e0) = o;
    }
}

// ---------------- 5) reduce 32 partials, apply 1/sum -------------------------
__global__ __launch_bounds__(256) void att_reduce_kernel()
{
    int bh = blockIdx.x;
    int b = bh >> 3, h = bh & 7;
    #pragma unroll
    for (int t = 0; t < 4; t++) {
        int idx = threadIdx.x + t * 256;   // d*32+e
        int d = idx >> 5;
        float s = 0.f;
        #pragma unroll
        for (int c = 0; c < 32; c++)
            s += g_attp[((size_t)bh * 32 + c) * 1024 + idx];
        g_att[(size_t)bh * 1024 + idx] = s * g_krs[b * CCH + h * HD + d];
    }
}

// ---------------- 6) fold proj weights with att -------------------------------
// Wf[b][o][h*32+d] = sum_e projw[o][h*32+e] * att[b][h][d][e]
__global__ __launch_bounds__(256) void wf_fold_kernel(const float* __restrict__ projw)
{
    int b = blockIdx.x >> 4, ob = blockIdx.x & 15;
    __shared__ float attS[8][32][33];
    __shared__ float wS[16 * 256];
    int tid = threadIdx.x;

    #pragma unroll
    for (int t = 0; t < 8; t++) {
        int idx = tid + t * 256;           // float4 index 0..2047
        float4 v = ((const float4*)(g_att + (size_t)b * 8192))[idx];
        int fi = idx * 4;
        int hh = fi >> 10, dd = (fi >> 5) & 31, ee = fi & 31;
        attS[hh][dd][ee + 0] = v.x;
        attS[hh][dd][ee + 1] = v.y;
        attS[hh][dd][ee + 2] = v.z;
        attS[hh][dd][ee + 3] = v.w;
    }
    #pragma unroll
    for (int t = 0; t < 4; t++) {
        int idx = tid + t * 256;
        ((float4*)wS)[idx] = ((const float4*)(projw + (size_t)ob * 16 * 256))[idx];
    }
    __syncthreads();

    int hh = tid >> 5, dd = tid & 31;
    float acc[16];
    #pragma unroll
    for (int i = 0; i < 16; i++) acc[i] = 0.f;
    for (int e = 0; e < 32; e++) {
        float a = attS[hh][dd][e];
        #pragma unroll
        for (int oi = 0; oi < 16; oi++)
            acc[oi] += a * wS[oi * 256 + hh * 32 + e];
    }
    #pragma unroll
    for (int oi = 0; oi < 16; oi++)
        g_wf[((size_t)b * CCH + ob * 16 + oi) * CCH + tid] = acc[oi];
}

// ---------------- launch -------------------------------------------------------
extern "C" void kernel_launch(void* const* d_in, const int* in_sizes, int n_in,
                              void* d_out, int out_size)
{
    const float* x     = (const float*)d_in[0];
    const float* gnw   = (const float*)d_in[1];
    const float* gnb   = (const float*)d_in[2];
    const float* qkvw  = (const float*)d_in[3];
    const float* projw = (const float*)d_in[4];
    const float* projb = (const float*)d_in[5];
    float* out = (float*)d_out;

    gn_partial_kernel<<<BATCH * NGRP * 4, 256>>>(x);
    gn_final_kernel<<<1, BATCH * NGRP>>>();

    tgemm_kernel<M3, true, false, false, true, false>
        <<<dim3(NSP / 128, M3 / 128, BATCH), 256>>>(qkvw, x, nullptr, gnw, gnb, nullptr);

    kstats_kernel<<<BATCH * CCH, 256>>>();

    att_kernel<<<BATCH * NH * 8, 256>>>();
    att_reduce_kernel<<<BATCH * NH, 256>>>();

    wf_fold_kernel<<<BATCH * 16, 256>>>(projw);

    tgemm_kernel<CCH, false, true, true, false, true>
        <<<dim3(NSP / 128, CCH / 128, BATCH), 256>>>(nullptr, nullptr, out, nullptr, nullptr, projb);
}

// round 10
// speedup vs baseline: 2.3523x; 1.0702x over previous
#include <cuda_runtime.h>
#include <cuda_bf16.h>
#include <math.h>
#include <cstdint>

#define BATCH 16
#define CCH   256
#define NSP   4096
#define M3    768
#define NGRP  4
#define CPG   64
#define NH    8
#define HD    32
#define ATT_P 36

#define PA 40     // A smem pitch (bf16)
#define PB 136    // B smem pitch (bf16)

typedef unsigned int uint;

// smem stage layout (bytes)
#define AH_OFF 0
#define AL_OFF 10240
#define BH_OFF 20480
#define BL_OFF 29184
#define STG_B  37888
#define GSMEM  (3 * STG_B)   // 113664

// ---------------- scratch (referenced ONLY in device code) --------------------
__device__ __align__(16) float g_qkv[BATCH * M3 * NSP];
__device__ __align__(16) float g_att[BATCH * NH * HD * HD];
__device__ __align__(16) float g_attp[BATCH * NH * 32 * HD * HD];
__device__ __align__(16) float g_wf[BATCH * CCH * CCH];
__device__ float g_mu[BATCH * NGRP];
__device__ float g_rsig[BATCH * NGRP];
__device__ float g_gnp[BATCH * NGRP * 4 * 2];
__device__ float g_kmx[BATCH * CCH];
__device__ float g_krs[BATCH * CCH];
__device__ __align__(16) __nv_bfloat16 g_xh[BATCH * CCH * NSP];   // GN(x) hi [b][k][n]
__device__ __align__(16) __nv_bfloat16 g_xl[BATCH * CCH * NSP];
__device__ __align__(16) __nv_bfloat16 g_qh[BATCH * CCH * NSP];   // q hi [b][k][n]
__device__ __align__(16) __nv_bfloat16 g_ql[BATCH * CCH * NSP];
__device__ __align__(16) __nv_bfloat16 g_wh[M3 * CCH];            // qkvw hi [m][k]
__device__ __align__(16) __nv_bfloat16 g_wl[M3 * CCH];
__device__ __align__(16) __nv_bfloat16 g_wfh[BATCH * CCH * CCH];  // folded w hi [b][o][k]
__device__ __align__(16) __nv_bfloat16 g_wfl[BATCH * CCH * CCH];

// ---------------- helpers ------------------------------------------------------
__device__ __forceinline__ uint pkbf2(float a, float b) {
    __nv_bfloat162 t;
    t.x = __float2bfloat16(a);
    t.y = __float2bfloat16(b);
    return *reinterpret_cast<uint*>(&t);
}
__device__ __forceinline__ void split4(float4 v, uint2& hi, uint2& lo) {
    float hx = __bfloat162float(__float2bfloat16(v.x));
    float hy = __bfloat162float(__float2bfloat16(v.y));
    float hz = __bfloat162float(__float2bfloat16(v.z));
    float hw = __bfloat162float(__float2bfloat16(v.w));
    hi.x = pkbf2(hx, hy);
    hi.y = pkbf2(hz, hw);
    lo.x = pkbf2(v.x - hx, v.y - hy);
    lo.y = pkbf2(v.z - hz, v.w - hw);
}
__device__ __forceinline__ void ldsm4(uint& r0, uint& r1, uint& r2, uint& r3, uint addr) {
    asm volatile("ldmatrix.sync.aligned.m8n8.x4.shared.b16 {%0,%1,%2,%3}, [%4];"
                 : "=r"(r0), "=r"(r1), "=r"(r2), "=r"(r3) : "r"(addr));
}
__device__ __forceinline__ void ldsm2t(uint& r0, uint& r1, uint addr) {
    asm volatile("ldmatrix.sync.aligned.m8n8.x2.trans.shared.b16 {%0,%1}, [%2];"
                 : "=r"(r0), "=r"(r1) : "r"(addr));
}
__device__ __forceinline__ void mma16816(float4& d, uint a0, uint a1, uint a2, uint a3,
                                         uint b0, uint b1) {
    asm volatile("mma.sync.aligned.m16n8k16.row.col.f32.bf16.bf16.f32 "
                 "{%0,%1,%2,%3}, {%4,%5,%6,%7}, {%8,%9}, {%0,%1,%2,%3};"
                 : "+f"(d.x), "+f"(d.y), "+f"(d.z), "+f"(d.w)
                 : "r"(a0), "r"(a1), "r"(a2), "r"(a3), "r"(b0), "r"(b1));
}
__device__ __forceinline__ void cpasync16(uint dst, const void* src) {
    asm volatile("cp.async.cg.shared.global [%0], [%1], 16;" :: "r"(dst), "l"(src));
}
#define CP_COMMIT() asm volatile("cp.async.commit_group;" ::: "memory")
template<int N>
__device__ __forceinline__ void cp_wait() {
    asm volatile("cp.async.wait_group %0;" :: "n"(N) : "memory");
}

// ---------------- 1) GroupNorm stats --------------------------------------------
__global__ __launch_bounds__(256) void gn_partial_kernel(const float* __restrict__ x)
{
    int bg = blockIdx.x >> 2, part = blockIdx.x & 3;
    const float4* p = (const float4*)x + (size_t)bg * 65536 + part * 16384;
    float s = 0.f, sq = 0.f;
    for (int i = threadIdx.x; i < 16384; i += 256) {
        float4 v = p[i];
        s  += v.x + v.y + v.z + v.w;
        sq += v.x * v.x + v.y * v.y + v.z * v.z + v.w * v.w;
    }
    __shared__ float ss[8], ssq[8];
    #pragma unroll
    for (int o = 16; o; o >>= 1) {
        s  += __shfl_down_sync(0xffffffffu, s, o);
        sq += __shfl_down_sync(0xffffffffu, sq, o);
    }
    int w = threadIdx.x >> 5, l = threadIdx.x & 31;
    if (l == 0) { ss[w] = s; ssq[w] = sq; }
    __syncthreads();
    if (threadIdx.x == 0) {
        s = 0.f; sq = 0.f;
        #pragma unroll
        for (int i = 0; i < 8; i++) { s += ss[i]; sq += ssq[i]; }
        g_gnp[blockIdx.x * 2]     = s;
        g_gnp[blockIdx.x * 2 + 1] = sq;
    }
}
__global__ void gn_final_kernel()
{
    int bg = threadIdx.x;
    float s = 0.f, sq = 0.f;
    #pragma unroll
    for (int i = 0; i < 4; i++) {
        s  += g_gnp[(bg * 4 + i) * 2];
        sq += g_gnp[(bg * 4 + i) * 2 + 1];
    }
    const float inv = 1.0f / (float)(CPG * NSP);
    float mu  = s * inv;
    float var = sq * inv - mu * mu;
    g_mu[bg]   = mu;
    g_rsig[bg] = rsqrtf(var + 1e-5f);
}

// ---------------- 2) GN + split x (elementwise, internal dst) -------------------
__global__ __launch_bounds__(256) void gnsplit_kernel(const float* __restrict__ x,
                                                      const float* __restrict__ gnw,
                                                      const float* __restrict__ gnb)
{
    size_t idx = (size_t)blockIdx.x * 256 + threadIdx.x;
    size_t f = idx * 4;
    int b = (int)(f >> 20);
    int c = (int)((f >> 12) & 255);
    int g = c >> 6;
    float rs = g_rsig[b * NGRP + g];
    float mu = g_mu[b * NGRP + g];
    float w  = gnw[c] * rs;
    float bb = gnb[c] - mu * w;
    float4 v = ((const float4*)x)[idx];
    v.x = v.x * w + bb;
    v.y = v.y * w + bb;
    v.z = v.z * w + bb;
    v.w = v.w * w + bb;
    uint2 hi, lo;
    split4(v, hi, lo);
    *(uint2*)(g_xh + f) = hi;
    *(uint2*)(g_xl + f) = lo;
}

// ---------------- 3) split q rows (internal src+dst) -----------------------------
__global__ __launch_bounds__(256) void qsplit_kernel()
{
    size_t idx = (size_t)blockIdx.x * 256 + threadIdx.x;
    size_t f = idx * 4;
    int b = (int)(f >> 20);
    size_t rem = f & (((size_t)1 << 20) - 1);
    float4 v = *(const float4*)(g_qkv + (size_t)b * M3 * NSP + rem);
    uint2 hi, lo;
    split4(v, hi, lo);
    *(uint2*)(g_qh + f) = hi;
    *(uint2*)(g_ql + f) = lo;
}

// ---------------- 4) weight splits (internal dst / src) --------------------------
__global__ __launch_bounds__(256) void wsplit_kernel(const float* __restrict__ w)
{
    int idx = blockIdx.x * 256 + threadIdx.x;
    float4 v = ((const float4*)w)[idx];
    uint2 hi, lo;
    split4(v, hi, lo);
    *(uint2*)(g_wh + idx * 4) = hi;
    *(uint2*)(g_wl + idx * 4) = lo;
}
__global__ __launch_bounds__(256) void wfsplit_kernel()
{
    int idx = blockIdx.x * 256 + threadIdx.x;
    float4 v = ((const float4*)g_wf)[idx];
    uint2 hi, lo;
    split4(v, hi, lo);
    *(uint2*)(g_wfh + idx * 4) = hi;
    *(uint2*)(g_wfl + idx * 4) = lo;
}

// ---------------- 5) pipelined bf16 3-term GEMM ----------------------------------
// C[b][m][n] = sum_k A[m][k] * B[b][k][n]; operand selection via templates.
template<int M, bool ADD_BIAS, int ASEL, int BSEL, bool C_OUT>
__global__ __launch_bounds__(256, 1) void pgemm_kernel(
    float* __restrict__ Cext, const float* __restrict__ bias)
{
    extern __shared__ char smraw[];
    const int K = 256;
    int b = blockIdx.z;
    const __nv_bfloat16* Ah = (ASEL == 0) ? g_wh : (g_wfh + (size_t)b * M * K);
    const __nv_bfloat16* Al = (ASEL == 0) ? g_wl : (g_wfl + (size_t)b * M * K);
    const __nv_bfloat16* Bh = ((BSEL == 0) ? g_xh : g_qh) + (size_t)b * K * NSP;
    const __nv_bfloat16* Bl = ((BSEL == 0) ? g_xl : g_ql) + (size_t)b * K * NSP;
    float* Cp = (C_OUT ? Cext : g_qkv) + (size_t)b * M * NSP;
    int m0 = blockIdx.y * 128, n0 = blockIdx.x * 128;

    int tid  = threadIdx.x;
    int wid  = tid >> 5;
    int lane = tid & 31;
    int wm = (wid >> 2) * 64;
    int wn = (wid & 3) * 32;

    uint sbase = (uint)__cvta_generic_to_shared(smraw);

    // per-thread cp.async chunk assignment (2 chunks per array)
    int c0i = tid, c1i = tid + 256;
    int a0r = c0i >> 2, a0k = (c0i & 3) * 8;
    int a1r = c1i >> 2, a1k = (c1i & 3) * 8;
    int b0k = c0i >> 4, b0n = (c0i & 15) * 8;
    int b1k = c1i >> 4, b1n = (c1i & 15) * 8;
    uint a0d = (uint)(a0r * PA + a0k) * 2;
    uint a1d = (uint)(a1r * PA + a1k) * 2;
    uint b0d = (uint)(b0k * PB + b0n) * 2;
    uint b1d = (uint)(b1k * PB + b1n) * 2;
    const __nv_bfloat16* a0s_h = Ah + (size_t)(m0 + a0r) * K + a0k;
    const __nv_bfloat16* a1s_h = Ah + (size_t)(m0 + a1r) * K + a1k;
    const __nv_bfloat16* a0s_l = Al + (size_t)(m0 + a0r) * K + a0k;
    const __nv_bfloat16* a1s_l = Al + (size_t)(m0 + a1r) * K + a1k;
    const __nv_bfloat16* b0s_h = Bh + (size_t)b0k * NSP + n0 + b0n;
    const __nv_bfloat16* b1s_h = Bh + (size_t)b1k * NSP + n0 + b1n;
    const __nv_bfloat16* b0s_l = Bl + (size_t)b0k * NSP + n0 + b0n;
    const __nv_bfloat16* b1s_l = Bl + (size_t)b1k * NSP + n0 + b1n;

    // ldmatrix lane mapping (R4-proven)
    int a_row  = (lane & 7) + ((lane >> 3) & 1) * 8;
    int a_koff = ((lane >> 4) & 1) * 8;
    int b_row  = (lane & 7) + ((lane >> 3) & 1) * 8;

    float4 acc[4][4];
    #pragma unroll
    for (int i = 0; i < 4; i++)
        #pragma unroll
        for (int j = 0; j < 4; j++) acc[i][j] = make_float4(0.f, 0.f, 0.f, 0.f);

    const int NK = K / 32;   // 8

    #define ISSUE(kc_, stg_) do {                                           \
        int ko_ = (kc_) * 32;                                               \
        size_t bko_ = (size_t)ko_ * NSP;                                    \
        uint d_ = sbase + (uint)(stg_) * STG_B;                             \
        cpasync16(d_ + AH_OFF + a0d, a0s_h + ko_);                          \
        cpasync16(d_ + AH_OFF + a1d, a1s_h + ko_);                          \
        cpasync16(d_ + AL_OFF + a0d, a0s_l + ko_);                          \
        cpasync16(d_ + AL_OFF + a1d, a1s_l + ko_);                          \
        cpasync16(d_ + BH_OFF + b0d, b0s_h + bko_);                         \
        cpasync16(d_ + BH_OFF + b1d, b1s_h + bko_);                         \
        cpasync16(d_ + BL_OFF + b0d, b0s_l + bko_);                         \
        cpasync16(d_ + BL_OFF + b1d, b1s_l + bko_);                         \
        CP_COMMIT();                                                        \
    } while (0)

    ISSUE(0, 0);
    ISSUE(1, 1);

    for (int kc = 0; kc < NK; kc++) {
        if (kc < NK - 1) cp_wait<1>(); else cp_wait<0>();
        __syncthreads();
        if (kc + 2 < NK) {
            int stg = kc + 2;
            while (stg >= 3) stg -= 3;
            ISSUE(kc + 2, stg);
        }

        int cs = kc;
        while (cs >= 3) cs -= 3;
        uint aH = sbase + (uint)cs * STG_B + AH_OFF;
        uint aL = sbase + (uint)cs * STG_B + AL_OFF;
        uint bH = sbase + (uint)cs * STG_B + BH_OFF;
        uint bL = sbase + (uint)cs * STG_B + BL_OFF;

        #pragma unroll
        for (int kk = 0; kk < 32; kk += 16) {
            uint ah[4][4], al[4][4], bh[4][2], bl[4][2];
            #pragma unroll
            for (int mt = 0; mt < 4; mt++) {
                uint off = (uint)((wm + mt * 16 + a_row) * PA + kk + a_koff) * 2;
                ldsm4(ah[mt][0], ah[mt][1], ah[mt][2], ah[mt][3], aH + off);
                ldsm4(al[mt][0], al[mt][1], al[mt][2], al[mt][3], aL + off);
            }
            #pragma unroll
            for (int nt = 0; nt < 4; nt++) {
                uint off = (uint)((kk + b_row) * PB + wn + nt * 8) * 2;
                ldsm2t(bh[nt][0], bh[nt][1], bH + off);
                ldsm2t(bl[nt][0], bl[nt][1], bL + off);
            }
            #pragma unroll
            for (int mt = 0; mt < 4; mt++)
                #pragma unroll
                for (int nt = 0; nt < 4; nt++) {
                    mma16816(acc[mt][nt], ah[mt][0], ah[mt][1], ah[mt][2], ah[mt][3],
                             bh[nt][0], bh[nt][1]);
                    mma16816(acc[mt][nt], ah[mt][0], ah[mt][1], ah[mt][2], ah[mt][3],
                             bl[nt][0], bl[nt][1]);
                    mma16816(acc[mt][nt], al[mt][0], al[mt][1], al[mt][2], al[mt][3],
                             bh[nt][0], bh[nt][1]);
                }
        }
    }

    int g = lane >> 2, t4 = lane & 3;
    #pragma unroll
    for (int mt = 0; mt < 4; mt++) {
        int m_g = m0 + wm + mt * 16 + g;
        float b0v = ADD_BIAS ? bias[m_g]     : 0.f;
        float b1v = ADD_BIAS ? bias[m_g + 8] : 0.f;
        #pragma unroll
        for (int nt = 0; nt < 4; nt++) {
            int n_g = n0 + wn + nt * 8 + 2 * t4;
            float4 d = acc[mt][nt];
            float2 lo = make_float2(d.x + b0v, d.y + b0v);
            float2 hi = make_float2(d.z + b1v, d.w + b1v);
            *(float2*)(Cp + (size_t)m_g * NSP + n_g)       = lo;
            *(float2*)(Cp + (size_t)(m_g + 8) * NSP + n_g) = hi;
        }
    }
}

// ---------------- 6) k-row stats ---------------------------------------------------
__global__ __launch_bounds__(256) void kstats_kernel()
{
    int row = blockIdx.x;
    int b = row >> 8, ch = row & 255;
    const float4* p4 = (const float4*)(g_qkv + (size_t)(b * M3 + CCH + ch) * NSP);

    float4 v[4];
    float mx = -3.4e38f;
    #pragma unroll
    for (int i = 0; i < 4; i++) {
        v[i] = p4[threadIdx.x + i * 256];
        mx = fmaxf(mx, fmaxf(fmaxf(v[i].x, v[i].y), fmaxf(v[i].z, v[i].w)));
    }
    __shared__ float sm[8], ssum[8];
    #pragma unroll
    for (int o = 16; o; o >>= 1) mx = fmaxf(mx, __shfl_xor_sync(0xffffffffu, mx, o));
    int w = threadIdx.x >> 5, l = threadIdx.x & 31;
    if (l == 0) sm[w] = mx;
    __syncthreads();
    mx = sm[0];
    #pragma unroll
    for (int i = 1; i < 8; i++) mx = fmaxf(mx, sm[i]);

    float s = 0.f;
    #pragma unroll
    for (int i = 0; i < 4; i++) {
        s += __expf(v[i].x - mx) + __expf(v[i].y - mx)
           + __expf(v[i].z - mx) + __expf(v[i].w - mx);
    }
    #pragma unroll
    for (int o = 16; o; o >>= 1) s += __shfl_xor_sync(0xffffffffu, s, o);
    if (l == 0) ssum[w] = s;
    __syncthreads();
    if (threadIdx.x == 0) {
        s = 0.f;
        #pragma unroll
        for (int i = 0; i < 8; i++) s += ssum[i];
        g_kmx[row] = mx;
        g_krs[row] = 1.0f / s;
    }
}

// ---------------- 7) att partials ---------------------------------------------------
__global__ __launch_bounds__(256) void att_kernel()
{
    int bh = blockIdx.x >> 3;
    int chunk = blockIdx.x & 7;
    int b = bh >> 3, h = bh & 7;
    const float* kp = g_qkv + (size_t)(b * M3 + CCH     + h * HD) * NSP;
    const float* vp = g_qkv + (size_t)(b * M3 + 2 * CCH + h * HD) * NSP;

    __shared__ float ks[128][ATT_P];
    __shared__ float vs[128][ATT_P];
    __shared__ float mxs[32];

    int tid = threadIdx.x;
    if (tid < 32) mxs[tid] = g_kmx[b * CCH + h * HD + tid];
    __syncthreads();

    int sg = tid >> 6;
    int t6 = tid & 63;
    int d0 = (t6 & 7) * 4;
    int e0 = (t6 >> 3) * 4;
    int nfill = tid & 127;
    int dgb   = tid >> 7;

    float acc[4][4];
    #pragma unroll
    for (int i = 0; i < 4; i++)
        #pragma unroll
        for (int j = 0; j < 4; j++) acc[i][j] = 0.f;

    int nbeg = chunk * 512;
    for (int n0 = nbeg; n0 < nbeg + 512; n0 += 128) {
        #pragma unroll
        for (int t = 0; t < 4; t++) {
            int dg = dgb + 2 * t;
            int dr = dg * 4;
            float4 kv;
            kv.x = __expf(kp[(size_t)(dr + 0) * NSP + n0 + nfill] - mxs[dr + 0]);
            kv.y = __expf(kp[(size_t)(dr + 1) * NSP + n0 + nfill] - mxs[dr + 1]);
            kv.z = __expf(kp[(size_t)(dr + 2) * NSP + n0 + nfill] - mxs[dr + 2]);
            kv.w = __expf(kp[(size_t)(dr + 3) * NSP + n0 + nfill] - mxs[dr + 3]);
            *(float4*)&ks[nfill][dr] = kv;
            float4 vv;
            vv.x = vp[(size_t)(dr + 0) * NSP + n0 + nfill];
            vv.y = vp[(size_t)(dr + 1) * NSP + n0 + nfill];
            vv.z = vp[(size_t)(dr + 2) * NSP + n0 + nfill];
            vv.w = vp[(size_t)(dr + 3) * NSP + n0 + nfill];
            *(float4*)&vs[nfill][dr] = vv;
        }
        __syncthreads();

        int nb = sg * 32;
        #pragma unroll 8
        for (int nn = 0; nn < 32; nn++) {
            float4 ka = *(const float4*)&ks[nb + nn][d0];
            float4 va = *(const float4*)&vs[nb + nn][e0];
            acc[0][0] += ka.x * va.x; acc[0][1] += ka.x * va.y;
            acc[0][2] += ka.x * va.z; acc[0][3] += ka.x * va.w;
            acc[1][0] += ka.y * va.x; acc[1][1] += ka.y * va.y;
            acc[1][2] += ka.y * va.z; acc[1][3] += ka.y * va.w;
            acc[2][0] += ka.z * va.x; acc[2][1] += ka.z * va.y;
            acc[2][2] += ka.z * va.z; acc[2][3] += ka.z * va.w;
            acc[3][0] += ka.w * va.x; acc[3][1] += ka.w * va.y;
            acc[3][2] += ka.w * va.z; acc[3][3] += ka.w * va.w;
        }
        __syncthreads();
    }

    float* ap = g_attp + ((size_t)blockIdx.x * 4 + sg) * 1024;
    #pragma unroll
    for (int i = 0; i < 4; i++) {
        float4 o = make_float4(acc[i][0], acc[i][1], acc[i][2], acc[i][3]);
        *(float4*)(ap + (d0 + i) * HD + e0) = o;
    }
}

__global__ __launch_bounds__(256) void att_reduce_kernel()
{
    int bh = blockIdx.x;
    int b = bh >> 3, h = bh & 7;
    #pragma unroll
    for (int t = 0; t < 4; t++) {
        int idx = threadIdx.x + t * 256;
        int d = idx >> 5;
        float s = 0.f;
        #pragma unroll
        for (int c = 0; c < 32; c++)
            s += g_attp[((size_t)bh * 32 + c) * 1024 + idx];
        g_att[(size_t)bh * 1024 + idx] = s * g_krs[b * CCH + h * HD + d];
    }
}

// ---------------- 8) fold proj weights with att --------------------------------------
__global__ __launch_bounds__(256) void wf_fold_kernel(const float* __restrict__ projw)
{
    int b = blockIdx.x >> 4, ob = blockIdx.x & 15;
    __shared__ float attS[8][32][33];
    __shared__ float wS[16 * 256];
    int tid = threadIdx.x;

    #pragma unroll
    for (int t = 0; t < 8; t++) {
        int idx = tid + t * 256;
        float4 v = ((const float4*)(g_att + (size_t)b * 8192))[idx];
        int fi = idx * 4;
        int hh = fi >> 10, dd = (fi >> 5) & 31, ee = fi & 31;
        attS[hh][dd][ee + 0] = v.x;
        attS[hh][dd][ee + 1] = v.y;
        attS[hh][dd][ee + 2] = v.z;
        attS[hh][dd][ee + 3] = v.w;
    }
    #pragma unroll
    for (int t = 0; t < 4; t++) {
        int idx = tid + t * 256;
        ((float4*)wS)[idx] = ((const float4*)(projw + (size_t)ob * 16 * 256))[idx];
    }
    __syncthreads();

    int hh = tid >> 5, dd = tid & 31;
    float acc[16];
    #pragma unroll
    for (int i = 0; i < 16; i++) acc[i] = 0.f;
    for (int e = 0; e < 32; e++) {
        float a = attS[hh][dd][e];
        #pragma unroll
        for (int oi = 0; oi < 16; oi++)
            acc[oi] += a * wS[oi * 256 + hh * 32 + e];
    }
    #pragma unroll
    for (int oi = 0; oi < 16; oi++)
        g_wf[((size_t)b * CCH + ob * 16 + oi) * CCH + tid] = acc[oi];
}

// ---------------- launch ----------------------------------------------------------------
extern "C" void kernel_launch(void* const* d_in, const int* in_sizes, int n_in,
                              void* d_out, int out_size)
{
    const float* x     = (const float*)d_in[0];
    const float* gnw   = (const float*)d_in[1];
    const float* gnb   = (const float*)d_in[2];
    const float* qkvw  = (const float*)d_in[3];
    const float* projw = (const float*)d_in[4];
    const float* projb = (const float*)d_in[5];
    float* out = (float*)d_out;

    cudaFuncSetAttribute(pgemm_kernel<M3, false, 0, 0, false>,
                         cudaFuncAttributeMaxDynamicSharedMemorySize, GSMEM);
    cudaFuncSetAttribute(pgemm_kernel<CCH, true, 1, 1, true>,
                         cudaFuncAttributeMaxDynamicSharedMemorySize, GSMEM);

    gn_partial_kernel<<<BATCH * NGRP * 4, 256>>>(x);
    gn_final_kernel<<<1, BATCH * NGRP>>>();

    gnsplit_kernel<<<BATCH * CCH * NSP / 1024, 256>>>(x, gnw, gnb);
    wsplit_kernel<<<M3 * CCH / 1024, 256>>>(qkvw);

    pgemm_kernel<M3, false, 0, 0, false>
        <<<dim3(NSP / 128, M3 / 128, BATCH), 256, GSMEM>>>(nullptr, nullptr);

    kstats_kernel<<<BATCH * CCH, 256>>>();

    att_kernel<<<BATCH * NH * 8, 256>>>();
    att_reduce_kernel<<<BATCH * NH, 256>>>();

    wf_fold_kernel<<<BATCH * 16, 256>>>(projw);
    wfsplit_kernel<<<BATCH * CCH * CCH / 1024, 256>>>();

    qsplit_kernel<<<BATCH * CCH * NSP / 1024, 256>>>();

    pgemm_kernel<CCH, true, 1, 1, true>
        <<<dim3(NSP / 128, CCH / 128, BATCH), 256, GSMEM>>>(out, projb);
}

// round 11
// speedup vs baseline: 2.4314x; 1.0336x over previous
#include <cuda_runtime.h>
#include <cuda_bf16.h>
#include <math.h>
#include <cstdint>

#define BATCH 16
#define CCH   256
#define NSP   4096
#define M3    768
#define NGRP  4
#define CPG   64
#define NH    8
#define HD    32
#define ATT_P 36
#define ACHK  16   // att n-split chunks

#define PA 40     // A smem pitch (bf16)
#define PB 136    // B smem pitch (bf16)

typedef unsigned int uint;

// smem stage layout (bytes)
#define AH_OFF 0
#define AL_OFF 10240
#define BH_OFF 20480
#define BL_OFF 29184
#define STG_B  37888
#define GSMEM  (3 * STG_B)   // 113664

// ---------------- scratch (referenced ONLY in device code) --------------------
__device__ __align__(16) float g_qkv[BATCH * M3 * NSP];
__device__ __align__(16) float g_att[BATCH * NH * HD * HD];
__device__ __align__(16) float g_attp[BATCH * NH * ACHK * 4 * HD * HD];
__device__ __align__(16) float g_wf[BATCH * CCH * CCH];
__device__ float g_mu[BATCH * NGRP];
__device__ float g_rsig[BATCH * NGRP];
__device__ float g_gnp[BATCH * NGRP * 4 * 2];
__device__ float g_kmx[BATCH * CCH];
__device__ float g_krs[BATCH * CCH];
__device__ __align__(16) __nv_bfloat16 g_xh[BATCH * CCH * NSP];   // GN(x) hi [b][k][n]
__device__ __align__(16) __nv_bfloat16 g_xl[BATCH * CCH * NSP];
__device__ __align__(16) __nv_bfloat16 g_qh[BATCH * CCH * NSP];   // q hi [b][k][n]
__device__ __align__(16) __nv_bfloat16 g_ql[BATCH * CCH * NSP];
__device__ __align__(16) __nv_bfloat16 g_wh[M3 * CCH];            // qkvw hi [m][k]
__device__ __align__(16) __nv_bfloat16 g_wl[M3 * CCH];
__device__ __align__(16) __nv_bfloat16 g_wfh[BATCH * CCH * CCH];  // folded w hi [b][o][k]
__device__ __align__(16) __nv_bfloat16 g_wfl[BATCH * CCH * CCH];

// ---------------- helpers ------------------------------------------------------
__device__ __forceinline__ uint pkbf2(float a, float b) {
    __nv_bfloat162 t;
    t.x = __float2bfloat16(a);
    t.y = __float2bfloat16(b);
    return *reinterpret_cast<uint*>(&t);
}
__device__ __forceinline__ void split2(float a, float b, uint& hi, uint& lo) {
    float ha = __bfloat162float(__float2bfloat16(a));
    float hb = __bfloat162float(__float2bfloat16(b));
    hi = pkbf2(ha, hb);
    lo = pkbf2(a - ha, b - hb);
}
__device__ __forceinline__ void split4(float4 v, uint2& hi, uint2& lo) {
    split2(v.x, v.y, hi.x, lo.x);
    split2(v.z, v.w, hi.y, lo.y);
}
__device__ __forceinline__ void ldsm4(uint& r0, uint& r1, uint& r2, uint& r3, uint addr) {
    asm volatile("ldmatrix.sync.aligned.m8n8.x4.shared.b16 {%0,%1,%2,%3}, [%4];"
                 : "=r"(r0), "=r"(r1), "=r"(r2), "=r"(r3) : "r"(addr));
}
__device__ __forceinline__ void ldsm2t(uint& r0, uint& r1, uint addr) {
    asm volatile("ldmatrix.sync.aligned.m8n8.x2.trans.shared.b16 {%0,%1}, [%2];"
                 : "=r"(r0), "=r"(r1) : "r"(addr));
}
__device__ __forceinline__ void mma16816(float4& d, uint a0, uint a1, uint a2, uint a3,
                                         uint b0, uint b1) {
    asm volatile("mma.sync.aligned.m16n8k16.row.col.f32.bf16.bf16.f32 "
                 "{%0,%1,%2,%3}, {%4,%5,%6,%7}, {%8,%9}, {%0,%1,%2,%3};"
                 : "+f"(d.x), "+f"(d.y), "+f"(d.z), "+f"(d.w)
                 : "r"(a0), "r"(a1), "r"(a2), "r"(a3), "r"(b0), "r"(b1));
}
__device__ __forceinline__ void cpasync16(uint dst, const void* src) {
    asm volatile("cp.async.cg.shared.global [%0], [%1], 16;" :: "r"(dst), "l"(src));
}
#define CP_COMMIT() asm volatile("cp.async.commit_group;" ::: "memory")
template<int N>
__device__ __forceinline__ void cp_wait() {
    asm volatile("cp.async.wait_group %0;" :: "n"(N) : "memory");
}

// ---------------- 1) GroupNorm stats --------------------------------------------
__global__ __launch_bounds__(256) void gn_partial_kernel(const float* __restrict__ x)
{
    int bg = blockIdx.x >> 2, part = blockIdx.x & 3;
    const float4* p = (const float4*)x + (size_t)bg * 65536 + part * 16384;
    float s = 0.f, sq = 0.f;
    for (int i = threadIdx.x; i < 16384; i += 256) {
        float4 v = p[i];
        s  += v.x + v.y + v.z + v.w;
        sq += v.x * v.x + v.y * v.y + v.z * v.z + v.w * v.w;
    }
    __shared__ float ss[8], ssq[8];
    #pragma unroll
    for (int o = 16; o; o >>= 1) {
        s  += __shfl_down_sync(0xffffffffu, s, o);
        sq += __shfl_down_sync(0xffffffffu, sq, o);
    }
    int w = threadIdx.x >> 5, l = threadIdx.x & 31;
    if (l == 0) { ss[w] = s; ssq[w] = sq; }
    __syncthreads();
    if (threadIdx.x == 0) {
        s = 0.f; sq = 0.f;
        #pragma unroll
        for (int i = 0; i < 8; i++) { s += ss[i]; sq += ssq[i]; }
        g_gnp[blockIdx.x * 2]     = s;
        g_gnp[blockIdx.x * 2 + 1] = sq;
    }
}
__global__ void gn_final_kernel()
{
    int bg = threadIdx.x;
    float s = 0.f, sq = 0.f;
    #pragma unroll
    for (int i = 0; i < 4; i++) {
        s  += g_gnp[(bg * 4 + i) * 2];
        sq += g_gnp[(bg * 4 + i) * 2 + 1];
    }
    const float inv = 1.0f / (float)(CPG * NSP);
    float mu  = s * inv;
    float var = sq * inv - mu * mu;
    g_mu[bg]   = mu;
    g_rsig[bg] = rsqrtf(var + 1e-5f);
}

// ---------------- 2) GN + split x (elementwise, internal dst) -------------------
__global__ __launch_bounds__(256) void gnsplit_kernel(const float* __restrict__ x,
                                                      const float* __restrict__ gnw,
                                                      const float* __restrict__ gnb)
{
    size_t idx = (size_t)blockIdx.x * 256 + threadIdx.x;
    size_t f = idx * 4;
    int b = (int)(f >> 20);
    int c = (int)((f >> 12) & 255);
    int g = c >> 6;
    float rs = g_rsig[b * NGRP + g];
    float mu = g_mu[b * NGRP + g];
    float w  = gnw[c] * rs;
    float bb = gnb[c] - mu * w;
    float4 v = ((const float4*)x)[idx];
    v.x = v.x * w + bb;
    v.y = v.y * w + bb;
    v.z = v.z * w + bb;
    v.w = v.w * w + bb;
    uint2 hi, lo;
    split4(v, hi, lo);
    *(uint2*)(g_xh + f) = hi;
    *(uint2*)(g_xl + f) = lo;
}

// ---------------- 3) weight splits (internal dst / src) --------------------------
__global__ __launch_bounds__(256) void wsplit_kernel(const float* __restrict__ w)
{
    int idx = blockIdx.x * 256 + threadIdx.x;
    float4 v = ((const float4*)w)[idx];
    uint2 hi, lo;
    split4(v, hi, lo);
    *(uint2*)(g_wh + idx * 4) = hi;
    *(uint2*)(g_wl + idx * 4) = lo;
}
__global__ __launch_bounds__(256) void wfsplit_kernel()
{
    int idx = blockIdx.x * 256 + threadIdx.x;
    float4 v = ((const float4*)g_wf)[idx];
    uint2 hi, lo;
    split4(v, hi, lo);
    *(uint2*)(g_wfh + idx * 4) = hi;
    *(uint2*)(g_wfl + idx * 4) = lo;
}

// ---------------- 4) pipelined bf16 3-term GEMM ----------------------------------
// C[b][m][n] = sum_k A[m][k] * B[b][k][n]; operand selection via templates.
// SPLIT_Q: q m-tiles (blockIdx.y < 2) write split bf16 to g_qh/g_ql directly.
template<int M, bool ADD_BIAS, int ASEL, int BSEL, bool C_OUT, bool SPLIT_Q>
__global__ __launch_bounds__(256, 1) void pgemm_kernel(
    float* __restrict__ Cext, const float* __restrict__ bias)
{
    extern __shared__ char smraw[];
    const int K = 256;
    int b = blockIdx.z;
    const __nv_bfloat16* Ah = (ASEL == 0) ? g_wh : (g_wfh + (size_t)b * M * K);
    const __nv_bfloat16* Al = (ASEL == 0) ? g_wl : (g_wfl + (size_t)b * M * K);
    const __nv_bfloat16* Bh = ((BSEL == 0) ? g_xh : g_qh) + (size_t)b * K * NSP;
    const __nv_bfloat16* Bl = ((BSEL == 0) ? g_xl : g_ql) + (size_t)b * K * NSP;
    float* Cp = (C_OUT ? Cext : g_qkv) + (size_t)b * M * NSP;
    int m0 = blockIdx.y * 128, n0 = blockIdx.x * 128;

    int tid  = threadIdx.x;
    int wid  = tid >> 5;
    int lane = tid & 31;
    int wm = (wid >> 2) * 64;
    int wn = (wid & 3) * 32;

    uint sbase = (uint)__cvta_generic_to_shared(smraw);

    // per-thread cp.async chunk assignment (2 chunks per array)
    int c0i = tid, c1i = tid + 256;
    int a0r = c0i >> 2, a0k = (c0i & 3) * 8;
    int a1r = c1i >> 2, a1k = (c1i & 3) * 8;
    int b0k = c0i >> 4, b0n = (c0i & 15) * 8;
    int b1k = c1i >> 4, b1n = (c1i & 15) * 8;
    uint a0d = (uint)(a0r * PA + a0k) * 2;
    uint a1d = (uint)(a1r * PA + a1k) * 2;
    uint b0d = (uint)(b0k * PB + b0n) * 2;
    uint b1d = (uint)(b1k * PB + b1n) * 2;
    const __nv_bfloat16* a0s_h = Ah + (size_t)(m0 + a0r) * K + a0k;
    const __nv_bfloat16* a1s_h = Ah + (size_t)(m0 + a1r) * K + a1k;
    const __nv_bfloat16* a0s_l = Al + (size_t)(m0 + a0r) * K + a0k;
    const __nv_bfloat16* a1s_l = Al + (size_t)(m0 + a1r) * K + a1k;
    const __nv_bfloat16* b0s_h = Bh + (size_t)b0k * NSP + n0 + b0n;
    const __nv_bfloat16* b1s_h = Bh + (size_t)b1k * NSP + n0 + b1n;
    const __nv_bfloat16* b0s_l = Bl + (size_t)b0k * NSP + n0 + b0n;
    const __nv_bfloat16* b1s_l = Bl + (size_t)b1k * NSP + n0 + b1n;

    // ldmatrix lane mapping (proven)
    int a_row  = (lane & 7) + ((lane >> 3) & 1) * 8;
    int a_koff = ((lane >> 4) & 1) * 8;
    int b_row  = (lane & 7) + ((lane >> 3) & 1) * 8;

    float4 acc[4][4];
    #pragma unroll
    for (int i = 0; i < 4; i++)
        #pragma unroll
        for (int j = 0; j < 4; j++) acc[i][j] = make_float4(0.f, 0.f, 0.f, 0.f);

    const int NK = K / 32;   // 8

    #define ISSUE(kc_, stg_) do {                                           \
        int ko_ = (kc_) * 32;                                               \
        size_t bko_ = (size_t)ko_ * NSP;                                    \
        uint d_ = sbase + (uint)(stg_) * STG_B;                             \
        cpasync16(d_ + AH_OFF + a0d, a0s_h + ko_);                          \
        cpasync16(d_ + AH_OFF + a1d, a1s_h + ko_);                          \
        cpasync16(d_ + AL_OFF + a0d, a0s_l + ko_);                          \
        cpasync16(d_ + AL_OFF + a1d, a1s_l + ko_);                          \
        cpasync16(d_ + BH_OFF + b0d, b0s_h + bko_);                         \
        cpasync16(d_ + BH_OFF + b1d, b1s_h + bko_);                         \
        cpasync16(d_ + BL_OFF + b0d, b0s_l + bko_);                         \
        cpasync16(d_ + BL_OFF + b1d, b1s_l + bko_);                         \
        CP_COMMIT();                                                        \
    } while (0)

    ISSUE(0, 0);
    ISSUE(1, 1);

    for (int kc = 0; kc < NK; kc++) {
        if (kc < NK - 1) cp_wait<1>(); else cp_wait<0>();
        __syncthreads();
        if (kc + 2 < NK) {
            int stg = kc + 2;
            while (stg >= 3) stg -= 3;
            ISSUE(kc + 2, stg);
        }

        int cs = kc;
        while (cs >= 3) cs -= 3;
        uint aH = sbase + (uint)cs * STG_B + AH_OFF;
        uint aL = sbase + (uint)cs * STG_B + AL_OFF;
        uint bH = sbase + (uint)cs * STG_B + BH_OFF;
        uint bL = sbase + (uint)cs * STG_B + BL_OFF;

        #pragma unroll
        for (int kk = 0; kk < 32; kk += 16) {
            uint ah[4][4], al[4][4], bh[4][2], bl[4][2];
            #pragma unroll
            for (int mt = 0; mt < 4; mt++) {
                uint off = (uint)((wm + mt * 16 + a_row) * PA + kk + a_koff) * 2;
                ldsm4(ah[mt][0], ah[mt][1], ah[mt][2], ah[mt][3], aH + off);
                ldsm4(al[mt][0], al[mt][1], al[mt][2], al[mt][3], aL + off);
            }
            #pragma unroll
            for (int nt = 0; nt < 4; nt++) {
                uint off = (uint)((kk + b_row) * PB + wn + nt * 8) * 2;
                ldsm2t(bh[nt][0], bh[nt][1], bH + off);
                ldsm2t(bl[nt][0], bl[nt][1], bL + off);
            }
            #pragma unroll
            for (int mt = 0; mt < 4; mt++)
                #pragma unroll
                for (int nt = 0; nt < 4; nt++) {
                    mma16816(acc[mt][nt], ah[mt][0], ah[mt][1], ah[mt][2], ah[mt][3],
                             bh[nt][0], bh[nt][1]);
                    mma16816(acc[mt][nt], ah[mt][0], ah[mt][1], ah[mt][2], ah[mt][3],
                             bl[nt][0], bl[nt][1]);
                    mma16816(acc[mt][nt], al[mt][0], al[mt][1], al[mt][2], al[mt][3],
                             bh[nt][0], bh[nt][1]);
                }
        }
    }

    int g = lane >> 2, t4 = lane & 3;
    if (SPLIT_Q && blockIdx.y < 2) {
        // q m-tiles: write split bf16 directly to g_qh / g_ql [b][m][n]
        size_t qbase = (size_t)b * CCH * NSP;
        #pragma unroll
        for (int mt = 0; mt < 4; mt++) {
            int m_g = m0 + wm + mt * 16 + g;
            #pragma unroll
            for (int nt = 0; nt < 4; nt++) {
                int n_g = n0 + wn + nt * 8 + 2 * t4;
                float4 d = acc[mt][nt];
                uint hi0, lo0, hi1, lo1;
                split2(d.x, d.y, hi0, lo0);
                split2(d.z, d.w, hi1, lo1);
                size_t o0 = qbase + (size_t)m_g * NSP + n_g;
                size_t o1 = o0 + (size_t)8 * NSP;
                *(uint*)(g_qh + o0) = hi0;
                *(uint*)(g_ql + o0) = lo0;
                *(uint*)(g_qh + o1) = hi1;
                *(uint*)(g_ql + o1) = lo1;
            }
        }
    } else {
        #pragma unroll
        for (int mt = 0; mt < 4; mt++) {
            int m_g = m0 + wm + mt * 16 + g;
            float b0v = ADD_BIAS ? bias[m_g]     : 0.f;
            float b1v = ADD_BIAS ? bias[m_g + 8] : 0.f;
            #pragma unroll
            for (int nt = 0; nt < 4; nt++) {
                int n_g = n0 + wn + nt * 8 + 2 * t4;
                float4 d = acc[mt][nt];
                float2 lo = make_float2(d.x + b0v, d.y + b0v);
                float2 hi = make_float2(d.z + b1v, d.w + b1v);
                *(float2*)(Cp + (size_t)m_g * NSP + n_g)       = lo;
                *(float2*)(Cp + (size_t)(m_g + 8) * NSP + n_g) = hi;
            }
        }
    }
}

// ---------------- 5) k-row stats ---------------------------------------------------
__global__ __launch_bounds__(256) void kstats_kernel()
{
    int row = blockIdx.x;
    int b = row >> 8, ch = row & 255;
    const float4* p4 = (const float4*)(g_qkv + (size_t)(b * M3 + CCH + ch) * NSP);

    float4 v[4];
    float mx = -3.4e38f;
    #pragma unroll
    for (int i = 0; i < 4; i++) {
        v[i] = p4[threadIdx.x + i * 256];
        mx = fmaxf(mx, fmaxf(fmaxf(v[i].x, v[i].y), fmaxf(v[i].z, v[i].w)));
    }
    __shared__ float sm[8], ssum[8];
    #pragma unroll
    for (int o = 16; o; o >>= 1) mx = fmaxf(mx, __shfl_xor_sync(0xffffffffu, mx, o));
    int w = threadIdx.x >> 5, l = threadIdx.x & 31;
    if (l == 0) sm[w] = mx;
    __syncthreads();
    mx = sm[0];
    #pragma unroll
    for (int i = 1; i < 8; i++) mx = fmaxf(mx, sm[i]);

    float s = 0.f;
    #pragma unroll
    for (int i = 0; i < 4; i++) {
        s += __expf(v[i].x - mx) + __expf(v[i].y - mx)
           + __expf(v[i].z - mx) + __expf(v[i].w - mx);
    }
    #pragma unroll
    for (int o = 16; o; o >>= 1) s += __shfl_xor_sync(0xffffffffu, s, o);
    if (l == 0) ssum[w] = s;
    __syncthreads();
    if (threadIdx.x == 0) {
        s = 0.f;
        #pragma unroll
        for (int i = 0; i < 8; i++) s += ssum[i];
        g_kmx[row] = mx;
        g_krs[row] = 1.0f / s;
    }
}

// ---------------- 6) att partials (16 chunks) ---------------------------------------
__global__ __launch_bounds__(256) void att_kernel()
{
    int bh = blockIdx.x >> 4;
    int chunk = blockIdx.x & (ACHK - 1);
    int b = bh >> 3, h = bh & 7;
    const float* kp = g_qkv + (size_t)(b * M3 + CCH     + h * HD) * NSP;
    const float* vp = g_qkv + (size_t)(b * M3 + 2 * CCH + h * HD) * NSP;

    __shared__ float ks[128][ATT_P];
    __shared__ float vs[128][ATT_P];
    __shared__ float mxs[32];

    int tid = threadIdx.x;
    if (tid < 32) mxs[tid] = g_kmx[b * CCH + h * HD + tid];
    __syncthreads();

    int sg = tid >> 6;
    int t6 = tid & 63;
    int d0 = (t6 & 7) * 4;
    int e0 = (t6 >> 3) * 4;
    int nfill = tid & 127;
    int dgb   = tid >> 7;

    float acc[4][4];
    #pragma unroll
    for (int i = 0; i < 4; i++)
        #pragma unroll
        for (int j = 0; j < 4; j++) acc[i][j] = 0.f;

    int nbeg = chunk * (NSP / ACHK);
    #pragma unroll
    for (int n0 = nbeg; n0 < nbeg + (NSP / ACHK); n0 += 128) {
        #pragma unroll
        for (int t = 0; t < 4; t++) {
            int dg = dgb + 2 * t;
            int dr = dg * 4;
            float4 kv;
            kv.x = __expf(kp[(size_t)(dr + 0) * NSP + n0 + nfill] - mxs[dr + 0]);
            kv.y = __expf(kp[(size_t)(dr + 1) * NSP + n0 + nfill] - mxs[dr + 1]);
            kv.z = __expf(kp[(size_t)(dr + 2) * NSP + n0 + nfill] - mxs[dr + 2]);
            kv.w = __expf(kp[(size_t)(dr + 3) * NSP + n0 + nfill] - mxs[dr + 3]);
            *(float4*)&ks[nfill][dr] = kv;
            float4 vv;
            vv.x = vp[(size_t)(dr + 0) * NSP + n0 + nfill];
            vv.y = vp[(size_t)(dr + 1) * NSP + n0 + nfill];
            vv.z = vp[(size_t)(dr + 2) * NSP + n0 + nfill];
            vv.w = vp[(size_t)(dr + 3) * NSP + n0 + nfill];
            *(float4*)&vs[nfill][dr] = vv;
        }
        __syncthreads();

        int nb = sg * 32;
        #pragma unroll 8
        for (int nn = 0; nn < 32; nn++) {
            float4 ka = *(const float4*)&ks[nb + nn][d0];
            float4 va = *(const float4*)&vs[nb + nn][e0];
            acc[0][0] += ka.x * va.x; acc[0][1] += ka.x * va.y;
            acc[0][2] += ka.x * va.z; acc[0][3] += ka.x * va.w;
            acc[1][0] += ka.y * va.x; acc[1][1] += ka.y * va.y;
            acc[1][2] += ka.y * va.z; acc[1][3] += ka.y * va.w;
            acc[2][0] += ka.z * va.x; acc[2][1] += ka.z * va.y;
            acc[2][2] += ka.z * va.z; acc[2][3] += ka.z * va.w;
            acc[3][0] += ka.w * va.x; acc[3][1] += ka.w * va.y;
            acc[3][2] += ka.w * va.z; acc[3][3] += ka.w * va.w;
        }
        __syncthreads();
    }

    float* ap = g_attp + ((size_t)blockIdx.x * 4 + sg) * 1024;
    #pragma unroll
    for (int i = 0; i < 4; i++) {
        float4 o = make_float4(acc[i][0], acc[i][1], acc[i][2], acc[i][3]);
        *(float4*)(ap + (d0 + i) * HD + e0) = o;
    }
}

__global__ __launch_bounds__(256) void att_reduce_kernel()
{
    int bh = blockIdx.x;
    int b = bh >> 3, h = bh & 7;
    const int NP = ACHK * 4;   // 64 partials
    #pragma unroll
    for (int t = 0; t < 4; t++) {
        int idx = threadIdx.x + t * 256;
        int d = idx >> 5;
        float s = 0.f;
        #pragma unroll
        for (int c = 0; c < NP; c++)
            s += g_attp[((size_t)bh * NP + c) * 1024 + idx];
        g_att[(size_t)bh * 1024 + idx] = s * g_krs[b * CCH + h * HD + d];
    }
}

// ---------------- 7) fold proj weights with att --------------------------------------
__global__ __launch_bounds__(256) void wf_fold_kernel(const float* __restrict__ projw)
{
    int b = blockIdx.x >> 4, ob = blockIdx.x & 15;
    __shared__ float attS[8][32][33];
    __shared__ float wS[16 * 256];
    int tid = threadIdx.x;

    #pragma unroll
    for (int t = 0; t < 8; t++) {
        int idx = tid + t * 256;
        float4 v = ((const float4*)(g_att + (size_t)b * 8192))[idx];
        int fi = idx * 4;
        int hh = fi >> 10, dd = (fi >> 5) & 31, ee = fi & 31;
        attS[hh][dd][ee + 0] = v.x;
        attS[hh][dd][ee + 1] = v.y;
        attS[hh][dd][ee + 2] = v.z;
        attS[hh][dd][ee + 3] = v.w;
    }
    #pragma unroll
    for (int t = 0; t < 4; t++) {
        int idx = tid + t * 256;
        ((float4*)wS)[idx] = ((const float4*)(projw + (size_t)ob * 16 * 256))[idx];
    }
    __syncthreads();

    int hh = tid >> 5, dd = tid & 31;
    float acc[16];
    #pragma unroll
    for (int i = 0; i < 16; i++) acc[i] = 0.f;
    for (int e = 0; e < 32; e++) {
        float a = attS[hh][dd][e];
        #pragma unroll
        for (int oi = 0; oi < 16; oi++)
            acc[oi] += a * wS[oi * 256 + hh * 32 + e];
    }
    #pragma unroll
    for (int oi = 0; oi < 16; oi++)
        g_wf[((size_t)b * CCH + ob * 16 + oi) * CCH + tid] = acc[oi];
}

// ---------------- launch ----------------------------------------------------------------
extern "C" void kernel_launch(void* const* d_in, const int* in_sizes, int n_in,
                              void* d_out, int out_size)
{
    const float* x     = (const float*)d_in[0];
    const float* gnw   = (const float*)d_in[1];
    const float* gnb   = (const float*)d_in[2];
    const float* qkvw  = (const float*)d_in[3];
    const float* projw = (const float*)d_in[4];
    const float* projb = (const float*)d_in[5];
    float* out = (float*)d_out;

    cudaFuncSetAttribute(pgemm_kernel<M3, false, 0, 0, false, true>,
                         cudaFuncAttributeMaxDynamicSharedMemorySize, GSMEM);
    cudaFuncSetAttribute(pgemm_kernel<CCH, true, 1, 1, true, false>,
                         cudaFuncAttributeMaxDynamicSharedMemorySize, GSMEM);

    gn_partial_kernel<<<BATCH * NGRP * 4, 256>>>(x);
    gn_final_kernel<<<1, BATCH * NGRP>>>();

    gnsplit_kernel<<<BATCH * CCH * NSP / 1024, 256>>>(x, gnw, gnb);
    wsplit_kernel<<<M3 * CCH / 1024, 256>>>(qkvw);

    pgemm_kernel<M3, false, 0, 0, false, true>
        <<<dim3(NSP / 128, M3 / 128, BATCH), 256, GSMEM>>>(nullptr, nullptr);

    kstats_kernel<<<BATCH * CCH, 256>>>();

    att_kernel<<<BATCH * NH * ACHK, 256>>>();
    att_reduce_kernel<<<BATCH * NH, 256>>>();

    wf_fold_kernel<<<BATCH * 16, 256>>>(projw);
    wfsplit_kernel<<<BATCH * CCH * CCH / 1024, 256>>>();

    pgemm_kernel<CCH, true, 1, 1, true, false>
        <<<dim3(NSP / 128, CCH / 128, BATCH), 256, GSMEM>>>(out, projb);
}

// round 12
// speedup vs baseline: 3.0053x; 1.2360x over previous
#include <cuda_runtime.h>
#include <cuda_fp16.h>
#include <math.h>
#include <cstdint>

#define BATCH 16
#define CCH   256
#define NSP   4096
#define M3    768
#define NGRP  4
#define CPG   64
#define NH    8
#define HD    32
#define ATT_P 36
#define ACHK  16

#define PA 40     // A smem pitch (fp16)
#define PB 136    // B smem pitch (fp16)

typedef unsigned int uint;

// smem stage layout (bytes): Ah(10240) Al(10240) Bh(8704)
#define AH_OFF 0
#define AL_OFF 10240
#define BH_OFF 20480
#define STG_B  29184
#define GSMEM  (3 * STG_B)   // 87552

// ---------------- scratch (referenced ONLY in device code) --------------------
__device__ __align__(16) float g_qkv[BATCH * M3 * NSP];
__device__ __align__(16) float g_att[BATCH * NH * HD * HD];
__device__ __align__(16) float g_attp[BATCH * NH * ACHK * 4 * HD * HD];
__device__ __align__(16) float g_wf[BATCH * CCH * CCH];
__device__ float g_mu[BATCH * NGRP];
__device__ float g_rsig[BATCH * NGRP];
__device__ float g_gnp[BATCH * NGRP * 4 * 2];
__device__ float g_kmx[BATCH * CCH];
__device__ float g_krs[BATCH * CCH];
__device__ __align__(16) __half g_x16[BATCH * CCH * NSP];    // GN(x) fp16 [b][k][n]
__device__ __align__(16) __half g_q16[BATCH * CCH * NSP];    // q fp16 [b][k][n]
__device__ __align__(16) __half g_wh[M3 * CCH];              // qkvw hi [m][k]
__device__ __align__(16) __half g_wl[M3 * CCH];              // qkvw lo
__device__ __align__(16) __half g_wfh[BATCH * CCH * CCH];    // folded w hi [b][o][k]
__device__ __align__(16) __half g_wfl[BATCH * CCH * CCH];

// ---------------- helpers ------------------------------------------------------
__device__ __forceinline__ uint pkh2(float a, float b) {
    __half2 t = __floats2half2_rn(a, b);
    return *reinterpret_cast<uint*>(&t);
}
// split a,b into fp16 hi + fp16 residual
__device__ __forceinline__ void splith2(float a, float b, uint& hi, uint& lo) {
    float ha = __half2float(__float2half_rn(a));
    float hb = __half2float(__float2half_rn(b));
    hi = pkh2(ha, hb);
    lo = pkh2(a - ha, b - hb);
}
__device__ __forceinline__ void ldsm4(uint& r0, uint& r1, uint& r2, uint& r3, uint addr) {
    asm volatile("ldmatrix.sync.aligned.m8n8.x4.shared.b16 {%0,%1,%2,%3}, [%4];"
                 : "=r"(r0), "=r"(r1), "=r"(r2), "=r"(r3) : "r"(addr));
}
__device__ __forceinline__ void ldsm2t(uint& r0, uint& r1, uint addr) {
    asm volatile("ldmatrix.sync.aligned.m8n8.x2.trans.shared.b16 {%0,%1}, [%2];"
                 : "=r"(r0), "=r"(r1) : "r"(addr));
}
__device__ __forceinline__ void mmah16816(float4& d, uint a0, uint a1, uint a2, uint a3,
                                          uint b0, uint b1) {
    asm volatile("mma.sync.aligned.m16n8k16.row.col.f32.f16.f16.f32 "
                 "{%0,%1,%2,%3}, {%4,%5,%6,%7}, {%8,%9}, {%0,%1,%2,%3};"
                 : "+f"(d.x), "+f"(d.y), "+f"(d.z), "+f"(d.w)
                 : "r"(a0), "r"(a1), "r"(a2), "r"(a3), "r"(b0), "r"(b1));
}
__device__ __forceinline__ void cpasync16(uint dst, const void* src) {
    asm volatile("cp.async.cg.shared.global [%0], [%1], 16;" :: "r"(dst), "l"(src));
}
#define CP_COMMIT() asm volatile("cp.async.commit_group;" ::: "memory")
template<int N>
__device__ __forceinline__ void cp_wait() {
    asm volatile("cp.async.wait_group %0;" :: "n"(N) : "memory");
}

// ---------------- 1) GroupNorm stats --------------------------------------------
__global__ __launch_bounds__(256) void gn_partial_kernel(const float* __restrict__ x)
{
    int bg = blockIdx.x >> 2, part = blockIdx.x & 3;
    const float4* p = (const float4*)x + (size_t)bg * 65536 + part * 16384;
    float s = 0.f, sq = 0.f;
    for (int i = threadIdx.x; i < 16384; i += 256) {
        float4 v = p[i];
        s  += v.x + v.y + v.z + v.w;
        sq += v.x * v.x + v.y * v.y + v.z * v.z + v.w * v.w;
    }
    __shared__ float ss[8], ssq[8];
    #pragma unroll
    for (int o = 16; o; o >>= 1) {
        s  += __shfl_down_sync(0xffffffffu, s, o);
        sq += __shfl_down_sync(0xffffffffu, sq, o);
    }
    int w = threadIdx.x >> 5, l = threadIdx.x & 31;
    if (l == 0) { ss[w] = s; ssq[w] = sq; }
    __syncthreads();
    if (threadIdx.x == 0) {
        s = 0.f; sq = 0.f;
        #pragma unroll
        for (int i = 0; i < 8; i++) { s += ss[i]; sq += ssq[i]; }
        g_gnp[blockIdx.x * 2]     = s;
        g_gnp[blockIdx.x * 2 + 1] = sq;
    }
}
__global__ void gn_final_kernel()
{
    int bg = threadIdx.x;
    float s = 0.f, sq = 0.f;
    #pragma unroll
    for (int i = 0; i < 4; i++) {
        s  += g_gnp[(bg * 4 + i) * 2];
        sq += g_gnp[(bg * 4 + i) * 2 + 1];
    }
    const float inv = 1.0f / (float)(CPG * NSP);
    float mu  = s * inv;
    float var = sq * inv - mu * mu;
    g_mu[bg]   = mu;
    g_rsig[bg] = rsqrtf(var + 1e-5f);
}

// ---------------- 2) GN + convert x to fp16 (no split) ---------------------------
__global__ __launch_bounds__(256) void gnconv_kernel(const float* __restrict__ x,
                                                     const float* __restrict__ gnw,
                                                     const float* __restrict__ gnb)
{
    size_t idx = (size_t)blockIdx.x * 256 + threadIdx.x;
    size_t f = idx * 4;
    int b = (int)(f >> 20);
    int c = (int)((f >> 12) & 255);
    int g = c >> 6;
    float rs = g_rsig[b * NGRP + g];
    float mu = g_mu[b * NGRP + g];
    float w  = gnw[c] * rs;
    float bb = gnb[c] - mu * w;
    float4 v = ((const float4*)x)[idx];
    uint2 o;
    o.x = pkh2(v.x * w + bb, v.y * w + bb);
    o.y = pkh2(v.z * w + bb, v.w * w + bb);
    *(uint2*)(g_x16 + f) = o;
}

// ---------------- 3) weight splits (fp16 hi/lo) ----------------------------------
__global__ __launch_bounds__(256) void wsplit_kernel(const float* __restrict__ w)
{
    int idx = blockIdx.x * 256 + threadIdx.x;
    float4 v = ((const float4*)w)[idx];
    uint2 hi, lo;
    splith2(v.x, v.y, hi.x, lo.x);
    splith2(v.z, v.w, hi.y, lo.y);
    *(uint2*)(g_wh + idx * 4) = hi;
    *(uint2*)(g_wl + idx * 4) = lo;
}
__global__ __launch_bounds__(256) void wfsplit_kernel()
{
    int idx = blockIdx.x * 256 + threadIdx.x;
    float4 v = ((const float4*)g_wf)[idx];
    uint2 hi, lo;
    splith2(v.x, v.y, hi.x, lo.x);
    splith2(v.z, v.w, hi.y, lo.y);
    *(uint2*)(g_wfh + idx * 4) = hi;
    *(uint2*)(g_wfl + idx * 4) = lo;
}

// ---------------- 4) pipelined fp16 2-term GEMM ----------------------------------
// C[b][m][n] = sum_k (Ah+Al)[m][k] * B16[b][k][n]
// SPLIT_Q: q m-tiles (blockIdx.y < 2) write fp16 to g_q16 directly.
template<int M, bool ADD_BIAS, int ASEL, int BSEL, bool C_OUT, bool SPLIT_Q>
__global__ __launch_bounds__(256, 1) void pgemm_kernel(
    float* __restrict__ Cext, const float* __restrict__ bias)
{
    extern __shared__ char smraw[];
    const int K = 256;
    int b = blockIdx.z;
    const __half* Ah = (ASEL == 0) ? g_wh : (g_wfh + (size_t)b * M * K);
    const __half* Al = (ASEL == 0) ? g_wl : (g_wfl + (size_t)b * M * K);
    const __half* Bh = ((BSEL == 0) ? g_x16 : g_q16) + (size_t)b * K * NSP;
    float* Cp = (C_OUT ? Cext : g_qkv) + (size_t)b * M * NSP;
    int m0 = blockIdx.y * 128, n0 = blockIdx.x * 128;

    int tid  = threadIdx.x;
    int wid  = tid >> 5;
    int lane = tid & 31;
    int wm = (wid >> 2) * 64;
    int wn = (wid & 3) * 32;

    uint sbase = (uint)__cvta_generic_to_shared(smraw);

    // per-thread cp.async chunk assignment (2 chunks per array)
    int c0i = tid, c1i = tid + 256;
    int a0r = c0i >> 2, a0k = (c0i & 3) * 8;
    int a1r = c1i >> 2, a1k = (c1i & 3) * 8;
    int b0k = c0i >> 4, b0n = (c0i & 15) * 8;
    int b1k = c1i >> 4, b1n = (c1i & 15) * 8;
    uint a0d = (uint)(a0r * PA + a0k) * 2;
    uint a1d = (uint)(a1r * PA + a1k) * 2;
    uint b0d = (uint)(b0k * PB + b0n) * 2;
    uint b1d = (uint)(b1k * PB + b1n) * 2;
    const __half* a0s_h = Ah + (size_t)(m0 + a0r) * K + a0k;
    const __half* a1s_h = Ah + (size_t)(m0 + a1r) * K + a1k;
    const __half* a0s_l = Al + (size_t)(m0 + a0r) * K + a0k;
    const __half* a1s_l = Al + (size_t)(m0 + a1r) * K + a1k;
    const __half* b0s   = Bh + (size_t)b0k * NSP + n0 + b0n;
    const __half* b1s   = Bh + (size_t)b1k * NSP + n0 + b1n;

    // ldmatrix lane mapping (proven)
    int a_row  = (lane & 7) + ((lane >> 3) & 1) * 8;
    int a_koff = ((lane >> 4) & 1) * 8;
    int b_row  = (lane & 7) + ((lane >> 3) & 1) * 8;

    float4 acc[4][4];
    #pragma unroll
    for (int i = 0; i < 4; i++)
        #pragma unroll
        for (int j = 0; j < 4; j++) acc[i][j] = make_float4(0.f, 0.f, 0.f, 0.f);

    const int NK = K / 32;   // 8

    #define ISSUE(kc_, stg_) do {                                           \
        int ko_ = (kc_) * 32;                                               \
        size_t bko_ = (size_t)ko_ * NSP;                                    \
        uint d_ = sbase + (uint)(stg_) * STG_B;                             \
        cpasync16(d_ + AH_OFF + a0d, a0s_h + ko_);                          \
        cpasync16(d_ + AH_OFF + a1d, a1s_h + ko_);                          \
        cpasync16(d_ + AL_OFF + a0d, a0s_l + ko_);                          \
        cpasync16(d_ + AL_OFF + a1d, a1s_l + ko_);                          \
        cpasync16(d_ + BH_OFF + b0d, b0s + bko_);                           \
        cpasync16(d_ + BH_OFF + b1d, b1s + bko_);                           \
        CP_COMMIT();                                                        \
    } while (0)

    ISSUE(0, 0);
    ISSUE(1, 1);

    for (int kc = 0; kc < NK; kc++) {
        if (kc < NK - 1) cp_wait<1>(); else cp_wait<0>();
        __syncthreads();
        if (kc + 2 < NK) {
            int stg = kc + 2;
            while (stg >= 3) stg -= 3;
            ISSUE(kc + 2, stg);
        }

        int cs = kc;
        while (cs >= 3) cs -= 3;
        uint aH = sbase + (uint)cs * STG_B + AH_OFF;
        uint aL = sbase + (uint)cs * STG_B + AL_OFF;
        uint bH = sbase + (uint)cs * STG_B + BH_OFF;

        #pragma unroll
        for (int kk = 0; kk < 32; kk += 16) {
            uint ah[4][4], al[4][4], bh[4][2];
            #pragma unroll
            for (int mt = 0; mt < 4; mt++) {
                uint off = (uint)((wm + mt * 16 + a_row) * PA + kk + a_koff) * 2;
                ldsm4(ah[mt][0], ah[mt][1], ah[mt][2], ah[mt][3], aH + off);
                ldsm4(al[mt][0], al[mt][1], al[mt][2], al[mt][3], aL + off);
            }
            #pragma unroll
            for (int nt = 0; nt < 4; nt++) {
                uint off = (uint)((kk + b_row) * PB + wn + nt * 8) * 2;
                ldsm2t(bh[nt][0], bh[nt][1], bH + off);
            }
            #pragma unroll
            for (int mt = 0; mt < 4; mt++)
                #pragma unroll
                for (int nt = 0; nt < 4; nt++) {
                    mmah16816(acc[mt][nt], ah[mt][0], ah[mt][1], ah[mt][2], ah[mt][3],
                              bh[nt][0], bh[nt][1]);
                    mmah16816(acc[mt][nt], al[mt][0], al[mt][1], al[mt][2], al[mt][3],
                              bh[nt][0], bh[nt][1]);
                }
        }
    }

    int g = lane >> 2, t4 = lane & 3;
    if (SPLIT_Q && blockIdx.y < 2) {
        size_t qbase = (size_t)b * CCH * NSP;
        #pragma unroll
        for (int mt = 0; mt < 4; mt++) {
            int m_g = m0 + wm + mt * 16 + g;
            #pragma unroll
            for (int nt = 0; nt < 4; nt++) {
                int n_g = n0 + wn + nt * 8 + 2 * t4;
                float4 d = acc[mt][nt];
                size_t o0 = qbase + (size_t)m_g * NSP + n_g;
                size_t o1 = o0 + (size_t)8 * NSP;
                *(uint*)(g_q16 + o0) = pkh2(d.x, d.y);
                *(uint*)(g_q16 + o1) = pkh2(d.z, d.w);
            }
        }
    } else {
        #pragma unroll
        for (int mt = 0; mt < 4; mt++) {
            int m_g = m0 + wm + mt * 16 + g;
            float b0v = ADD_BIAS ? bias[m_g]     : 0.f;
            float b1v = ADD_BIAS ? bias[m_g + 8] : 0.f;
            #pragma unroll
            for (int nt = 0; nt < 4; nt++) {
                int n_g = n0 + wn + nt * 8 + 2 * t4;
                float4 d = acc[mt][nt];
                float2 lo = make_float2(d.x + b0v, d.y + b0v);
                float2 hi = make_float2(d.z + b1v, d.w + b1v);
                *(float2*)(Cp + (size_t)m_g * NSP + n_g)       = lo;
                *(float2*)(Cp + (size_t)(m_g + 8) * NSP + n_g) = hi;
            }
        }
    }
}

// ---------------- 5) k-row stats ---------------------------------------------------
__global__ __launch_bounds__(256) void kstats_kernel()
{
    int row = blockIdx.x;
    int b = row >> 8, ch = row & 255;
    const float4* p4 = (const float4*)(g_qkv + (size_t)(b * M3 + CCH + ch) * NSP);

    float4 v[4];
    float mx = -3.4e38f;
    #pragma unroll
    for (int i = 0; i < 4; i++) {
        v[i] = p4[threadIdx.x + i * 256];
        mx = fmaxf(mx, fmaxf(fmaxf(v[i].x, v[i].y), fmaxf(v[i].z, v[i].w)));
    }
    __shared__ float sm[8], ssum[8];
    #pragma unroll
    for (int o = 16; o; o >>= 1) mx = fmaxf(mx, __shfl_xor_sync(0xffffffffu, mx, o));
    int w = threadIdx.x >> 5, l = threadIdx.x & 31;
    if (l == 0) sm[w] = mx;
    __syncthreads();
    mx = sm[0];
    #pragma unroll
    for (int i = 1; i < 8; i++) mx = fmaxf(mx, sm[i]);

    float s = 0.f;
    #pragma unroll
    for (int i = 0; i < 4; i++) {
        s += __expf(v[i].x - mx) + __expf(v[i].y - mx)
           + __expf(v[i].z - mx) + __expf(v[i].w - mx);
    }
    #pragma unroll
    for (int o = 16; o; o >>= 1) s += __shfl_xor_sync(0xffffffffu, s, o);
    if (l == 0) ssum[w] = s;
    __syncthreads();
    if (threadIdx.x == 0) {
        s = 0.f;
        #pragma unroll
        for (int i = 0; i < 8; i++) s += ssum[i];
        g_kmx[row] = mx;
        g_krs[row] = 1.0f / s;
    }
}

// ---------------- 6) att partials (16 chunks) ---------------------------------------
__global__ __launch_bounds__(256) void att_kernel()
{
    int bh = blockIdx.x >> 4;
    int chunk = blockIdx.x & (ACHK - 1);
    int b = bh >> 3, h = bh & 7;
    const float* kp = g_qkv + (size_t)(b * M3 + CCH     + h * HD) * NSP;
    const float* vp = g_qkv + (size_t)(b * M3 + 2 * CCH + h * HD) * NSP;

    __shared__ float ks[128][ATT_P];
    __shared__ float vs[128][ATT_P];
    __shared__ float mxs[32];

    int tid = threadIdx.x;
    if (tid < 32) mxs[tid] = g_kmx[b * CCH + h * HD + tid];
    __syncthreads();

    int sg = tid >> 6;
    int t6 = tid & 63;
    int d0 = (t6 & 7) * 4;
    int e0 = (t6 >> 3) * 4;
    int nfill = tid & 127;
    int dgb   = tid >> 7;

    float acc[4][4];
    #pragma unroll
    for (int i = 0; i < 4; i++)
        #pragma unroll
        for (int j = 0; j < 4; j++) acc[i][j] = 0.f;

    int nbeg = chunk * (NSP / ACHK);
    #pragma unroll
    for (int n0 = nbeg; n0 < nbeg + (NSP / ACHK); n0 += 128) {
        #pragma unroll
        for (int t = 0; t < 4; t++) {
            int dg = dgb + 2 * t;
            int dr = dg * 4;
            float4 kv;
            kv.x = __expf(kp[(size_t)(dr + 0) * NSP + n0 + nfill] - mxs[dr + 0]);
            kv.y = __expf(kp[(size_t)(dr + 1) * NSP + n0 + nfill] - mxs[dr + 1]);
            kv.z = __expf(kp[(size_t)(dr + 2) * NSP + n0 + nfill] - mxs[dr + 2]);
            kv.w = __expf(kp[(size_t)(dr + 3) * NSP + n0 + nfill] - mxs[dr + 3]);
            *(float4*)&ks[nfill][dr] = kv;
            float4 vv;
            vv.x = vp[(size_t)(dr + 0) * NSP + n0 + nfill];
            vv.y = vp[(size_t)(dr + 1) * NSP + n0 + nfill];
            vv.z = vp[(size_t)(dr + 2) * NSP + n0 + nfill];
            vv.w = vp[(size_t)(dr + 3) * NSP + n0 + nfill];
            *(float4*)&vs[nfill][dr] = vv;
        }
        __syncthreads();

        int nb = sg * 32;
        #pragma unroll 8
        for (int nn = 0; nn < 32; nn++) {
            float4 ka = *(const float4*)&ks[nb + nn][d0];
            float4 va = *(const float4*)&vs[nb + nn][e0];
            acc[0][0] += ka.x * va.x; acc[0][1] += ka.x * va.y;
            acc[0][2] += ka.x * va.z; acc[0][3] += ka.x * va.w;
            acc[1][0] += ka.y * va.x; acc[1][1] += ka.y * va.y;
            acc[1][2] += ka.y * va.z; acc[1][3] += ka.y * va.w;
            acc[2][0] += ka.z * va.x; acc[2][1] += ka.z * va.y;
            acc[2][2] += ka.z * va.z; acc[2][3] += ka.z * va.w;
            acc[3][0] += ka.w * va.x; acc[3][1] += ka.w * va.y;
            acc[3][2] += ka.w * va.z; acc[3][3] += ka.w * va.w;
        }
        __syncthreads();
    }

    float* ap = g_attp + ((size_t)blockIdx.x * 4 + sg) * 1024;
    #pragma unroll
    for (int i = 0; i < 4; i++) {
        float4 o = make_float4(acc[i][0], acc[i][1], acc[i][2], acc[i][3]);
        *(float4*)(ap + (d0 + i) * HD + e0) = o;
    }
}

__global__ __launch_bounds__(256) void att_reduce_kernel()
{
    int bh = blockIdx.x;
    int b = bh >> 3, h = bh & 7;
    const int NP = ACHK * 4;
    #pragma unroll
    for (int t = 0; t < 4; t++) {
        int idx = threadIdx.x + t * 256;
        int d = idx >> 5;
        float s = 0.f;
        #pragma unroll
        for (int c = 0; c < NP; c++)
            s += g_attp[((size_t)bh * NP + c) * 1024 + idx];
        g_att[(size_t)bh * 1024 + idx] = s * g_krs[b * CCH + h * HD + d];
    }
}

// ---------------- 7) fold proj weights with att --------------------------------------
__global__ __launch_bounds__(256) void wf_fold_kernel(const float* __restrict__ projw)
{
    int b = blockIdx.x >> 4, ob = blockIdx.x & 15;
    __shared__ float attS[8][32][33];
    __shared__ float wS[16 * 256];
    int tid = threadIdx.x;

    #pragma unroll
    for (int t = 0; t < 8; t++) {
        int idx = tid + t * 256;
        float4 v = ((const float4*)(g_att + (size_t)b * 8192))[idx];
        int fi = idx * 4;
        int hh = fi >> 10, dd = (fi >> 5) & 31, ee = fi & 31;
        attS[hh][dd][ee + 0] = v.x;
        attS[hh][dd][ee + 1] = v.y;
        attS[hh][dd][ee + 2] = v.z;
        attS[hh][dd][ee + 3] = v.w;
    }
    #pragma unroll
    for (int t = 0; t < 4; t++) {
        int idx = tid + t * 256;
        ((float4*)wS)[idx] = ((const float4*)(projw + (size_t)ob * 16 * 256))[idx];
    }
    __syncthreads();

    int hh = tid >> 5, dd = tid & 31;
    float acc[16];
    #pragma unroll
    for (int i = 0; i < 16; i++) acc[i] = 0.f;
    for (int e = 0; e < 32; e++) {
        float a = attS[hh][dd][e];
        #pragma unroll
        for (int oi = 0; oi < 16; oi++)
            acc[oi] += a * wS[oi * 256 + hh * 32 + e];
    }
    #pragma unroll
    for (int oi = 0; oi < 16; oi++)
        g_wf[((size_t)b * CCH + ob * 16 + oi) * CCH + tid] = acc[oi];
}

// ---------------- launch ----------------------------------------------------------------
extern "C" void kernel_launch(void* const* d_in, const int* in_sizes, int n_in,
                              void* d_out, int out_size)
{
    const float* x     = (const float*)d_in[0];
    const float* gnw   = (const float*)d_in[1];
    const float* gnb   = (const float*)d_in[2];
    const float* qkvw  = (const float*)d_in[3];
    const float* projw = (const float*)d_in[4];
    const float* projb = (const float*)d_in[5];
    float* out = (float*)d_out;

    cudaFuncSetAttribute(pgemm_kernel<M3, false, 0, 0, false, true>,
                         cudaFuncAttributeMaxDynamicSharedMemorySize, GSMEM);
    cudaFuncSetAttribute(pgemm_kernel<CCH, true, 1, 1, true, false>,
                         cudaFuncAttributeMaxDynamicSharedMemorySize, GSMEM);

    gn_partial_kernel<<<BATCH * NGRP * 4, 256>>>(x);
    gn_final_kernel<<<1, BATCH * NGRP>>>();

    gnconv_kernel<<<BATCH * CCH * NSP / 1024, 256>>>(x, gnw, gnb);
    wsplit_kernel<<<M3 * CCH / 1024, 256>>>(qkvw);

    pgemm_kernel<M3, false, 0, 0, false, true>
        <<<dim3(NSP / 128, M3 / 128, BATCH), 256, GSMEM>>>(nullptr, nullptr);

    kstats_kernel<<<BATCH * CCH, 256>>>();

    att_kernel<<<BATCH * NH * ACHK, 256>>>();
    att_reduce_kernel<<<BATCH * NH, 256>>>();

    wf_fold_kernel<<<BATCH * 16, 256>>>(projw);
    wfsplit_kernel<<<BATCH * CCH * CCH / 1024, 256>>>();

    pgemm_kernel<CCH, true, 1, 1, true, false>
        <<<dim3(NSP / 128, CCH / 128, BATCH), 256, GSMEM>>>(out, projb);
}

// round 13
// speedup vs baseline: 3.4395x; 1.1445x over previous
#include <cuda_runtime.h>
#include <cuda_fp16.h>
#include <math.h>
#include <cstdint>

#define BATCH 16
#define CCH   256
#define NSP   4096
#define M3    768
#define NGRP  4
#define CPG   64
#define NH    8
#define HD    32
#define ATT_P 36
#define ACHK  16

#define PA 40     // A smem pitch (fp16)
#define PB 136    // B smem pitch (fp16)

typedef unsigned int uint;

// smem stage layout (bytes): Ah(10240) Al(10240) B(8704)
#define AH_OFF 0
#define AL_OFF 10240
#define BH_OFF 20480
#define STG_B  29184
#define GSMEM  (3 * STG_B)   // 87552

// ---------------- scratch (referenced ONLY in device code) --------------------
__device__ __align__(16) float g_qkv[BATCH * M3 * NSP];
__device__ __align__(16) float g_att[BATCH * NH * HD * HD];
__device__ __align__(16) float g_attp[BATCH * NH * ACHK * 4 * HD * HD];
__device__ float g_mu[BATCH * NGRP];
__device__ float g_rsig[BATCH * NGRP];
__device__ float g_gnp[BATCH * NGRP * 4 * 2];
__device__ float g_krs[BATCH * CCH];
__device__ __align__(16) __half g_x16[BATCH * CCH * NSP];    // GN(x) fp16 [b][k][n]
__device__ __align__(16) __half g_q16[BATCH * CCH * NSP];    // q fp16 [b][k][n]
__device__ __align__(16) __half g_wh[M3 * CCH];              // qkvw hi [m][k]
__device__ __align__(16) __half g_wl[M3 * CCH];              // qkvw lo
__device__ __align__(16) __half g_wfh[BATCH * CCH * CCH];    // folded w hi [b][o][k]
__device__ __align__(16) __half g_wfl[BATCH * CCH * CCH];

// ---------------- helpers ------------------------------------------------------
__device__ __forceinline__ uint pkh2(float a, float b) {
    __half2 t = __floats2half2_rn(a, b);
    return *reinterpret_cast<uint*>(&t);
}
__device__ __forceinline__ void splith2(float a, float b, uint& hi, uint& lo) {
    float ha = __half2float(__float2half_rn(a));
    float hb = __half2float(__float2half_rn(b));
    hi = pkh2(ha, hb);
    lo = pkh2(a - ha, b - hb);
}
__device__ __forceinline__ void ldsm4(uint& r0, uint& r1, uint& r2, uint& r3, uint addr) {
    asm volatile("ldmatrix.sync.aligned.m8n8.x4.shared.b16 {%0,%1,%2,%3}, [%4];"
                 : "=r"(r0), "=r"(r1), "=r"(r2), "=r"(r3) : "r"(addr));
}
__device__ __forceinline__ void ldsm2t(uint& r0, uint& r1, uint addr) {
    asm volatile("ldmatrix.sync.aligned.m8n8.x2.trans.shared.b16 {%0,%1}, [%2];"
                 : "=r"(r0), "=r"(r1) : "r"(addr));
}
__device__ __forceinline__ void mmah16816(float4& d, uint a0, uint a1, uint a2, uint a3,
                                          uint b0, uint b1) {
    asm volatile("mma.sync.aligned.m16n8k16.row.col.f32.f16.f16.f32 "
                 "{%0,%1,%2,%3}, {%4,%5,%6,%7}, {%8,%9}, {%0,%1,%2,%3};"
                 : "+f"(d.x), "+f"(d.y), "+f"(d.z), "+f"(d.w)
                 : "r"(a0), "r"(a1), "r"(a2), "r"(a3), "r"(b0), "r"(b1));
}
__device__ __forceinline__ void cpasync16(uint dst, const void* src) {
    asm volatile("cp.async.cg.shared.global [%0], [%1], 16;" :: "r"(dst), "l"(src));
}
#define CP_COMMIT() asm volatile("cp.async.commit_group;" ::: "memory")
template<int N>
__device__ __forceinline__ void cp_wait() {
    asm volatile("cp.async.wait_group %0;" :: "n"(N) : "memory");
}

// ---------------- 1) GroupNorm stats --------------------------------------------
__global__ __launch_bounds__(256) void gn_partial_kernel(const float* __restrict__ x)
{
    int bg = blockIdx.x >> 2, part = blockIdx.x & 3;
    const float4* p = (const float4*)x + (size_t)bg * 65536 + part * 16384;
    float s = 0.f, sq = 0.f;
    for (int i = threadIdx.x; i < 16384; i += 256) {
        float4 v = p[i];
        s  += v.x + v.y + v.z + v.w;
        sq += v.x * v.x + v.y * v.y + v.z * v.z + v.w * v.w;
    }
    __shared__ float ss[8], ssq[8];
    #pragma unroll
    for (int o = 16; o; o >>= 1) {
        s  += __shfl_down_sync(0xffffffffu, s, o);
        sq += __shfl_down_sync(0xffffffffu, sq, o);
    }
    int w = threadIdx.x >> 5, l = threadIdx.x & 31;
    if (l == 0) { ss[w] = s; ssq[w] = sq; }
    __syncthreads();
    if (threadIdx.x == 0) {
        s = 0.f; sq = 0.f;
        #pragma unroll
        for (int i = 0; i < 8; i++) { s += ss[i]; sq += ssq[i]; }
        g_gnp[blockIdx.x * 2]     = s;
        g_gnp[blockIdx.x * 2 + 1] = sq;
    }
}
__global__ void gn_final_kernel()
{
    int bg = threadIdx.x;
    float s = 0.f, sq = 0.f;
    #pragma unroll
    for (int i = 0; i < 4; i++) {
        s  += g_gnp[(bg * 4 + i) * 2];
        sq += g_gnp[(bg * 4 + i) * 2 + 1];
    }
    const float inv = 1.0f / (float)(CPG * NSP);
    float mu  = s * inv;
    float var = sq * inv - mu * mu;
    g_mu[bg]   = mu;
    g_rsig[bg] = rsqrtf(var + 1e-5f);
}

// ---------------- 2) GN + convert x to fp16 --------------------------------------
__global__ __launch_bounds__(256) void gnconv_kernel(const float* __restrict__ x,
                                                     const float* __restrict__ gnw,
                                                     const float* __restrict__ gnb)
{
    size_t idx = (size_t)blockIdx.x * 256 + threadIdx.x;
    size_t f = idx * 4;
    int b = (int)(f >> 20);
    int c = (int)((f >> 12) & 255);
    int g = c >> 6;
    float rs = g_rsig[b * NGRP + g];
    float mu = g_mu[b * NGRP + g];
    float w  = gnw[c] * rs;
    float bb = gnb[c] - mu * w;
    float4 v = ((const float4*)x)[idx];
    uint2 o;
    o.x = pkh2(v.x * w + bb, v.y * w + bb);
    o.y = pkh2(v.z * w + bb, v.w * w + bb);
    *(uint2*)(g_x16 + f) = o;
}

// ---------------- 3) qkv weight split (fp16 hi/lo) --------------------------------
__global__ __launch_bounds__(256) void wsplit_kernel(const float* __restrict__ w)
{
    int idx = blockIdx.x * 256 + threadIdx.x;
    float4 v = ((const float4*)w)[idx];
    uint2 hi, lo;
    splith2(v.x, v.y, hi.x, lo.x);
    splith2(v.z, v.w, hi.y, lo.y);
    *(uint2*)(g_wh + idx * 4) = hi;
    *(uint2*)(g_wl + idx * 4) = lo;
}

// ---------------- 4) pipelined fp16 2-term GEMM (2 CTAs/SM) ----------------------
template<int M, bool ADD_BIAS, int ASEL, int BSEL, bool C_OUT, bool SPLIT_Q>
__global__ __launch_bounds__(256, 2) void pgemm_kernel(
    float* __restrict__ Cext, const float* __restrict__ bias)
{
    extern __shared__ char smraw[];
    const int K = 256;
    int b = blockIdx.z;
    const __half* Ah = (ASEL == 0) ? g_wh : (g_wfh + (size_t)b * M * K);
    const __half* Al = (ASEL == 0) ? g_wl : (g_wfl + (size_t)b * M * K);
    const __half* Bh = ((BSEL == 0) ? g_x16 : g_q16) + (size_t)b * K * NSP;
    float* Cp = (C_OUT ? Cext : g_qkv) + (size_t)b * M * NSP;
    int m0 = blockIdx.y * 128, n0 = blockIdx.x * 128;

    int tid  = threadIdx.x;
    int wid  = tid >> 5;
    int lane = tid & 31;
    int wm = (wid >> 2) * 64;
    int wn = (wid & 3) * 32;

    uint sbase = (uint)__cvta_generic_to_shared(smraw);

    int c0i = tid, c1i = tid + 256;
    int a0r = c0i >> 2, a0k = (c0i & 3) * 8;
    int a1r = c1i >> 2, a1k = (c1i & 3) * 8;
    int b0k = c0i >> 4, b0n = (c0i & 15) * 8;
    int b1k = c1i >> 4, b1n = (c1i & 15) * 8;
    uint a0d = (uint)(a0r * PA + a0k) * 2;
    uint a1d = (uint)(a1r * PA + a1k) * 2;
    uint b0d = (uint)(b0k * PB + b0n) * 2;
    uint b1d = (uint)(b1k * PB + b1n) * 2;
    const __half* a0s_h = Ah + (size_t)(m0 + a0r) * K + a0k;
    const __half* a1s_h = Ah + (size_t)(m0 + a1r) * K + a1k;
    const __half* a0s_l = Al + (size_t)(m0 + a0r) * K + a0k;
    const __half* a1s_l = Al + (size_t)(m0 + a1r) * K + a1k;
    const __half* b0s   = Bh + (size_t)b0k * NSP + n0 + b0n;
    const __half* b1s   = Bh + (size_t)b1k * NSP + n0 + b1n;

    int a_row  = (lane & 7) + ((lane >> 3) & 1) * 8;
    int a_koff = ((lane >> 4) & 1) * 8;
    int b_row  = (lane & 7) + ((lane >> 3) & 1) * 8;

    float4 acc[4][4];
    #pragma unroll
    for (int i = 0; i < 4; i++)
        #pragma unroll
        for (int j = 0; j < 4; j++) acc[i][j] = make_float4(0.f, 0.f, 0.f, 0.f);

    const int NK = K / 32;   // 8

    #define ISSUE(kc_, stg_) do {                                           \
        int ko_ = (kc_) * 32;                                               \
        size_t bko_ = (size_t)ko_ * NSP;                                    \
        uint d_ = sbase + (uint)(stg_) * STG_B;                             \
        cpasync16(d_ + AH_OFF + a0d, a0s_h + ko_);                          \
        cpasync16(d_ + AH_OFF + a1d, a1s_h + ko_);                          \
        cpasync16(d_ + AL_OFF + a0d, a0s_l + ko_);                          \
        cpasync16(d_ + AL_OFF + a1d, a1s_l + ko_);                          \
        cpasync16(d_ + BH_OFF + b0d, b0s + bko_);                           \
        cpasync16(d_ + BH_OFF + b1d, b1s + bko_);                           \
        CP_COMMIT();                                                        \
    } while (0)

    ISSUE(0, 0);
    ISSUE(1, 1);

    for (int kc = 0; kc < NK; kc++) {
        if (kc < NK - 1) cp_wait<1>(); else cp_wait<0>();
        __syncthreads();
        if (kc + 2 < NK) {
            int stg = kc + 2;
            while (stg >= 3) stg -= 3;
            ISSUE(kc + 2, stg);
        }

        int cs = kc;
        while (cs >= 3) cs -= 3;
        uint aH = sbase + (uint)cs * STG_B + AH_OFF;
        uint aL = sbase + (uint)cs * STG_B + AL_OFF;
        uint bH = sbase + (uint)cs * STG_B + BH_OFF;

        #pragma unroll
        for (int kk = 0; kk < 32; kk += 16) {
            uint ah[4][4], al[4][4], bh[4][2];
            #pragma unroll
            for (int mt = 0; mt < 4; mt++) {
                uint off = (uint)((wm + mt * 16 + a_row) * PA + kk + a_koff) * 2;
                ldsm4(ah[mt][0], ah[mt][1], ah[mt][2], ah[mt][3], aH + off);
                ldsm4(al[mt][0], al[mt][1], al[mt][2], al[mt][3], aL + off);
            }
            #pragma unroll
            for (int nt = 0; nt < 4; nt++) {
                uint off = (uint)((kk + b_row) * PB + wn + nt * 8) * 2;
                ldsm2t(bh[nt][0], bh[nt][1], bH + off);
            }
            #pragma unroll
            for (int mt = 0; mt < 4; mt++)
                #pragma unroll
                for (int nt = 0; nt < 4; nt++) {
                    mmah16816(acc[mt][nt], ah[mt][0], ah[mt][1], ah[mt][2], ah[mt][3],
                              bh[nt][0], bh[nt][1]);
                    mmah16816(acc[mt][nt], al[mt][0], al[mt][1], al[mt][2], al[mt][3],
                              bh[nt][0], bh[nt][1]);
                }
        }
    }

    int g = lane >> 2, t4 = lane & 3;
    if (SPLIT_Q && blockIdx.y < 2) {
        size_t qbase = (size_t)b * CCH * NSP;
        #pragma unroll
        for (int mt = 0; mt < 4; mt++) {
            int m_g = m0 + wm + mt * 16 + g;
            #pragma unroll
            for (int nt = 0; nt < 4; nt++) {
                int n_g = n0 + wn + nt * 8 + 2 * t4;
                float4 d = acc[mt][nt];
                size_t o0 = qbase + (size_t)m_g * NSP + n_g;
                size_t o1 = o0 + (size_t)8 * NSP;
                *(uint*)(g_q16 + o0) = pkh2(d.x, d.y);
                *(uint*)(g_q16 + o1) = pkh2(d.z, d.w);
            }
        }
    } else {
        #pragma unroll
        for (int mt = 0; mt < 4; mt++) {
            int m_g = m0 + wm + mt * 16 + g;
            float b0v = ADD_BIAS ? bias[m_g]     : 0.f;
            float b1v = ADD_BIAS ? bias[m_g + 8] : 0.f;
            #pragma unroll
            for (int nt = 0; nt < 4; nt++) {
                int n_g = n0 + wn + nt * 8 + 2 * t4;
                float4 d = acc[mt][nt];
                float2 lo = make_float2(d.x + b0v, d.y + b0v);
                float2 hi = make_float2(d.z + b1v, d.w + b1v);
                *(float2*)(Cp + (size_t)m_g * NSP + n_g)       = lo;
                *(float2*)(Cp + (size_t)(m_g + 8) * NSP + n_g) = hi;
            }
        }
    }
}

// ---------------- 5) k-row sum of exp (no max pass; k ~ N(0,1)) -------------------
__global__ __launch_bounds__(256) void ksum_kernel()
{
    int row = blockIdx.x;
    int b = row >> 8, ch = row & 255;
    const float4* p4 = (const float4*)(g_qkv + (size_t)(b * M3 + CCH + ch) * NSP);

    float s = 0.f;
    #pragma unroll
    for (int i = 0; i < 4; i++) {
        float4 v = p4[threadIdx.x + i * 256];
        s += __expf(v.x) + __expf(v.y) + __expf(v.z) + __expf(v.w);
    }
    __shared__ float ssum[8];
    #pragma unroll
    for (int o = 16; o; o >>= 1) s += __shfl_xor_sync(0xffffffffu, s, o);
    int w = threadIdx.x >> 5, l = threadIdx.x & 31;
    if (l == 0) ssum[w] = s;
    __syncthreads();
    if (threadIdx.x == 0) {
        s = 0.f;
        #pragma unroll
        for (int i = 0; i < 8; i++) s += ssum[i];
        g_krs[row] = 1.0f / s;
    }
}

// ---------------- 6) att partials (exp without shift) -----------------------------
__global__ __launch_bounds__(256) void att_kernel()
{
    int bh = blockIdx.x >> 4;
    int chunk = blockIdx.x & (ACHK - 1);
    int b = bh >> 3, h = bh & 7;
    const float* kp = g_qkv + (size_t)(b * M3 + CCH     + h * HD) * NSP;
    const float* vp = g_qkv + (size_t)(b * M3 + 2 * CCH + h * HD) * NSP;

    __shared__ float ks[128][ATT_P];
    __shared__ float vs[128][ATT_P];

    int tid = threadIdx.x;
    int sg = tid >> 6;
    int t6 = tid & 63;
    int d0 = (t6 & 7) * 4;
    int e0 = (t6 >> 3) * 4;
    int nfill = tid & 127;
    int dgb   = tid >> 7;

    float acc[4][4];
    #pragma unroll
    for (int i = 0; i < 4; i++)
        #pragma unroll
        for (int j = 0; j < 4; j++) acc[i][j] = 0.f;

    int nbeg = chunk * (NSP / ACHK);
    #pragma unroll
    for (int n0 = nbeg; n0 < nbeg + (NSP / ACHK); n0 += 128) {
        #pragma unroll
        for (int t = 0; t < 4; t++) {
            int dg = dgb + 2 * t;
            int dr = dg * 4;
            float4 kv;
            kv.x = __expf(kp[(size_t)(dr + 0) * NSP + n0 + nfill]);
            kv.y = __expf(kp[(size_t)(dr + 1) * NSP + n0 + nfill]);
            kv.z = __expf(kp[(size_t)(dr + 2) * NSP + n0 + nfill]);
            kv.w = __expf(kp[(size_t)(dr + 3) * NSP + n0 + nfill]);
            *(float4*)&ks[nfill][dr] = kv;
            float4 vv;
            vv.x = vp[(size_t)(dr + 0) * NSP + n0 + nfill];
            vv.y = vp[(size_t)(dr + 1) * NSP + n0 + nfill];
            vv.z = vp[(size_t)(dr + 2) * NSP + n0 + nfill];
            vv.w = vp[(size_t)(dr + 3) * NSP + n0 + nfill];
            *(float4*)&vs[nfill][dr] = vv;
        }
        __syncthreads();

        int nb = sg * 32;
        #pragma unroll 8
        for (int nn = 0; nn < 32; nn++) {
            float4 ka = *(const float4*)&ks[nb + nn][d0];
            float4 va = *(const float4*)&vs[nb + nn][e0];
            acc[0][0] += ka.x * va.x; acc[0][1] += ka.x * va.y;
            acc[0][2] += ka.x * va.z; acc[0][3] += ka.x * va.w;
            acc[1][0] += ka.y * va.x; acc[1][1] += ka.y * va.y;
            acc[1][2] += ka.y * va.z; acc[1][3] += ka.y * va.w;
            acc[2][0] += ka.z * va.x; acc[2][1] += ka.z * va.y;
            acc[2][2] += ka.z * va.z; acc[2][3] += ka.z * va.w;
            acc[3][0] += ka.w * va.x; acc[3][1] += ka.w * va.y;
            acc[3][2] += ka.w * va.z; acc[3][3] += ka.w * va.w;
        }
        __syncthreads();
    }

    float* ap = g_attp + ((size_t)blockIdx.x * 4 + sg) * 1024;
    #pragma unroll
    for (int i = 0; i < 4; i++) {
        float4 o = make_float4(acc[i][0], acc[i][1], acc[i][2], acc[i][3]);
        *(float4*)(ap + (d0 + i) * HD + e0) = o;
    }
}

__global__ __launch_bounds__(256) void att_reduce_kernel()
{
    int bh = blockIdx.x;
    int b = bh >> 3, h = bh & 7;
    const int NP = ACHK * 4;
    #pragma unroll
    for (int t = 0; t < 4; t++) {
        int idx = threadIdx.x + t * 256;
        int d = idx >> 5;
        float s = 0.f;
        #pragma unroll
        for (int c = 0; c < NP; c++)
            s += g_attp[((size_t)bh * NP + c) * 1024 + idx];
        g_att[(size_t)bh * 1024 + idx] = s * g_krs[b * CCH + h * HD + d];
    }
}

// ---------------- 7) fold proj weights with att, write fp16 split directly --------
__global__ __launch_bounds__(256) void wf_fold_kernel(const float* __restrict__ projw)
{
    int b = blockIdx.x >> 4, ob = blockIdx.x & 15;
    __shared__ float attS[8][32][33];
    __shared__ float wS[16 * 256];
    int tid = threadIdx.x;

    #pragma unroll
    for (int t = 0; t < 8; t++) {
        int idx = tid + t * 256;
        float4 v = ((const float4*)(g_att + (size_t)b * 8192))[idx];
        int fi = idx * 4;
        int hh = fi >> 10, dd = (fi >> 5) & 31, ee = fi & 31;
        attS[hh][dd][ee + 0] = v.x;
        attS[hh][dd][ee + 1] = v.y;
        attS[hh][dd][ee + 2] = v.z;
        attS[hh][dd][ee + 3] = v.w;
    }
    #pragma unroll
    for (int t = 0; t < 4; t++) {
        int idx = tid + t * 256;
        ((float4*)wS)[idx] = ((const float4*)(projw + (size_t)ob * 16 * 256))[idx];
    }
    __syncthreads();

    int hh = tid >> 5, dd = tid & 31;
    float acc[16];
    #pragma unroll
    for (int i = 0; i < 16; i++) acc[i] = 0.f;
    for (int e = 0; e < 32; e++) {
        float a = attS[hh][dd][e];
        #pragma unroll
        for (int oi = 0; oi < 16; oi++)
            acc[oi] += a * wS[oi * 256 + hh * 32 + e];
    }
    #pragma unroll
    for (int oi = 0; oi < 16; oi++) {
        size_t idx = ((size_t)b * CCH + ob * 16 + oi) * CCH + tid;
        float a = acc[oi];
        __half hh16 = __float2half_rn(a);
        g_wfh[idx] = hh16;
        g_wfl[idx] = __float2half_rn(a - __half2float(hh16));
    }
}

// ---------------- launch ----------------------------------------------------------------
extern "C" void kernel_launch(void* const* d_in, const int* in_sizes, int n_in,
                              void* d_out, int out_size)
{
    const float* x     = (const float*)d_in[0];
    const float* gnw   = (const float*)d_in[1];
    const float* gnb   = (const float*)d_in[2];
    const float* qkvw  = (const float*)d_in[3];
    const float* projw = (const float*)d_in[4];
    const float* projb = (const float*)d_in[5];
    float* out = (float*)d_out;

    cudaFuncSetAttribute(pgemm_kernel<M3, false, 0, 0, false, true>,
                         cudaFuncAttributeMaxDynamicSharedMemorySize, GSMEM);
    cudaFuncSetAttribute(pgemm_kernel<CCH, true, 1, 1, true, false>,
                         cudaFuncAttributeMaxDynamicSharedMemorySize, GSMEM);

    gn_partial_kernel<<<BATCH * NGRP * 4, 256>>>(x);
    gn_final_kernel<<<1, BATCH * NGRP>>>();

    gnconv_kernel<<<BATCH * CCH * NSP / 1024, 256>>>(x, gnw, gnb);
    wsplit_kernel<<<M3 * CCH / 1024, 256>>>(qkvw);

    pgemm_kernel<M3, false, 0, 0, false, true>
        <<<dim3(NSP / 128, M3 / 128, BATCH), 256, GSMEM>>>(nullptr, nullptr);

    ksum_kernel<<<BATCH * CCH, 256>>>();

    att_kernel<<<BATCH * NH * ACHK, 256>>>();
    att_reduce_kernel<<<BATCH * NH, 256>>>();

    wf_fold_kernel<<<BATCH * 16, 256>>>(projw);

    pgemm_kernel<CCH, true, 1, 1, true, false>
        <<<dim3(NSP / 128, CCH / 128, BATCH), 256, GSMEM>>>(out, projb);
}

// round 14
// speedup vs baseline: 3.6482x; 1.0607x over previous
#include <cuda_runtime.h>
#include <cuda_fp16.h>
#include <math.h>
#include <cstdint>

#define BATCH 16
#define CCH   256
#define NSP   4096
#define M3    768
#define NGRP  4
#define CPG   64
#define NH    8
#define HD    32
#define ATT_P 36
#define ACHK  16

#define PA 40     // A smem pitch (fp16)
#define PB 136    // B smem pitch (fp16)

typedef unsigned int uint;

// smem stage layout (bytes): Ah(10240) Al(10240) B(8704)
#define AH_OFF 0
#define AL_OFF 10240
#define BH_OFF 20480
#define STG_B  29184
#define GSMEM  (3 * STG_B)   // 87552

// ---------------- scratch (referenced ONLY in device code) --------------------
__device__ __align__(16) float g_att[BATCH * NH * HD * HD];
__device__ __align__(16) float g_attp[BATCH * NH * ACHK * 4 * HD * HD];
__device__ float g_mu[BATCH * NGRP];
__device__ float g_rsig[BATCH * NGRP];
__device__ float g_gnp[BATCH * NGRP * 4 * 2];
__device__ float g_krs[BATCH * CCH];
__device__ __align__(16) __half g_x16[BATCH * CCH * NSP];    // GN(x) fp16 [b][k][n]
__device__ __align__(16) __half g_q16[BATCH * CCH * NSP];    // q fp16 [b][k][n]
__device__ __align__(16) __half g_kv16[BATCH * 2 * CCH * NSP]; // k,v fp16 [b][512][n]
__device__ __align__(16) __half g_wh[M3 * CCH];              // qkvw hi [m][k]
__device__ __align__(16) __half g_wl[M3 * CCH];              // qkvw lo
__device__ __align__(16) __half g_wfh[BATCH * CCH * CCH];    // folded w hi [b][o][k]
__device__ __align__(16) __half g_wfl[BATCH * CCH * CCH];

// ---------------- helpers ------------------------------------------------------
__device__ __forceinline__ uint pkh2(float a, float b) {
    __half2 t = __floats2half2_rn(a, b);
    return *reinterpret_cast<uint*>(&t);
}
__device__ __forceinline__ void splith2(float a, float b, uint& hi, uint& lo) {
    float ha = __half2float(__float2half_rn(a));
    float hb = __half2float(__float2half_rn(b));
    hi = pkh2(ha, hb);
    lo = pkh2(a - ha, b - hb);
}
__device__ __forceinline__ void ldsm4(uint& r0, uint& r1, uint& r2, uint& r3, uint addr) {
    asm volatile("ldmatrix.sync.aligned.m8n8.x4.shared.b16 {%0,%1,%2,%3}, [%4];"
                 : "=r"(r0), "=r"(r1), "=r"(r2), "=r"(r3) : "r"(addr));
}
__device__ __forceinline__ void ldsm2t(uint& r0, uint& r1, uint addr) {
    asm volatile("ldmatrix.sync.aligned.m8n8.x2.trans.shared.b16 {%0,%1}, [%2];"
                 : "=r"(r0), "=r"(r1) : "r"(addr));
}
__device__ __forceinline__ void mmah16816(float4& d, uint a0, uint a1, uint a2, uint a3,
                                          uint b0, uint b1) {
    asm volatile("mma.sync.aligned.m16n8k16.row.col.f32.f16.f16.f32 "
                 "{%0,%1,%2,%3}, {%4,%5,%6,%7}, {%8,%9}, {%0,%1,%2,%3};"
                 : "+f"(d.x), "+f"(d.y), "+f"(d.z), "+f"(d.w)
                 : "r"(a0), "r"(a1), "r"(a2), "r"(a3), "r"(b0), "r"(b1));
}
__device__ __forceinline__ void cpasync16(uint dst, const void* src) {
    asm volatile("cp.async.cg.shared.global [%0], [%1], 16;" :: "r"(dst), "l"(src));
}
#define CP_COMMIT() asm volatile("cp.async.commit_group;" ::: "memory")
template<int N>
__device__ __forceinline__ void cp_wait() {
    asm volatile("cp.async.wait_group %0;" :: "n"(N) : "memory");
}

// ---------------- 1) GroupNorm stats --------------------------------------------
__global__ __launch_bounds__(256) void gn_partial_kernel(const float* __restrict__ x)
{
    int bg = blockIdx.x >> 2, part = blockIdx.x & 3;
    const float4* p = (const float4*)x + (size_t)bg * 65536 + part * 16384;
    float s = 0.f, sq = 0.f;
    for (int i = threadIdx.x; i < 16384; i += 256) {
        float4 v = p[i];
        s  += v.x + v.y + v.z + v.w;
        sq += v.x * v.x + v.y * v.y + v.z * v.z + v.w * v.w;
    }
    __shared__ float ss[8], ssq[8];
    #pragma unroll
    for (int o = 16; o; o >>= 1) {
        s  += __shfl_down_sync(0xffffffffu, s, o);
        sq += __shfl_down_sync(0xffffffffu, sq, o);
    }
    int w = threadIdx.x >> 5, l = threadIdx.x & 31;
    if (l == 0) { ss[w] = s; ssq[w] = sq; }
    __syncthreads();
    if (threadIdx.x == 0) {
        s = 0.f; sq = 0.f;
        #pragma unroll
        for (int i = 0; i < 8; i++) { s += ss[i]; sq += ssq[i]; }
        g_gnp[blockIdx.x * 2]     = s;
        g_gnp[blockIdx.x * 2 + 1] = sq;
    }
}
__global__ void gn_final_kernel()
{
    int bg = threadIdx.x;
    float s = 0.f, sq = 0.f;
    #pragma unroll
    for (int i = 0; i < 4; i++) {
        s  += g_gnp[(bg * 4 + i) * 2];
        sq += g_gnp[(bg * 4 + i) * 2 + 1];
    }
    const float inv = 1.0f / (float)(CPG * NSP);
    float mu  = s * inv;
    float var = sq * inv - mu * mu;
    g_mu[bg]   = mu;
    g_rsig[bg] = rsqrtf(var + 1e-5f);
}

// ---------------- 2) GN + convert x to fp16 --------------------------------------
__global__ __launch_bounds__(256) void gnconv_kernel(const float* __restrict__ x,
                                                     const float* __restrict__ gnw,
                                                     const float* __restrict__ gnb)
{
    size_t idx = (size_t)blockIdx.x * 256 + threadIdx.x;
    size_t f = idx * 4;
    int b = (int)(f >> 20);
    int c = (int)((f >> 12) & 255);
    int g = c >> 6;
    float rs = g_rsig[b * NGRP + g];
    float mu = g_mu[b * NGRP + g];
    float w  = gnw[c] * rs;
    float bb = gnb[c] - mu * w;
    float4 v = ((const float4*)x)[idx];
    uint2 o;
    o.x = pkh2(v.x * w + bb, v.y * w + bb);
    o.y = pkh2(v.z * w + bb, v.w * w + bb);
    *(uint2*)(g_x16 + f) = o;
}

// ---------------- 3) qkv weight split (fp16 hi/lo) --------------------------------
__global__ __launch_bounds__(256) void wsplit_kernel(const float* __restrict__ w)
{
    int idx = blockIdx.x * 256 + threadIdx.x;
    float4 v = ((const float4*)w)[idx];
    uint2 hi, lo;
    splith2(v.x, v.y, hi.x, lo.x);
    splith2(v.z, v.w, hi.y, lo.y);
    *(uint2*)(g_wh + idx * 4) = hi;
    *(uint2*)(g_wl + idx * 4) = lo;
}

// ---------------- 4) pipelined fp16 2-term GEMM (2 CTAs/SM) ----------------------
// KIND 0 = QKV: epilogue writes fp16 (q -> g_q16, k/v -> g_kv16), no bias.
// KIND 1 = PROJ: fp32 out + bias.
template<int M, int KIND, int ASEL, int BSEL>
__global__ __launch_bounds__(256, 2) void pgemm_kernel(
    float* __restrict__ Cext, const float* __restrict__ bias)
{
    extern __shared__ char smraw[];
    const int K = 256;
    int b = blockIdx.z;
    const __half* Ah = (ASEL == 0) ? g_wh : (g_wfh + (size_t)b * M * K);
    const __half* Al = (ASEL == 0) ? g_wl : (g_wfl + (size_t)b * M * K);
    const __half* Bh = ((BSEL == 0) ? g_x16 : g_q16) + (size_t)b * K * NSP;
    int m0 = blockIdx.y * 128, n0 = blockIdx.x * 128;

    int tid  = threadIdx.x;
    int wid  = tid >> 5;
    int lane = tid & 31;
    int wm = (wid >> 2) * 64;
    int wn = (wid & 3) * 32;

    uint sbase = (uint)__cvta_generic_to_shared(smraw);

    int c0i = tid, c1i = tid + 256;
    int a0r = c0i >> 2, a0k = (c0i & 3) * 8;
    int a1r = c1i >> 2, a1k = (c1i & 3) * 8;
    int b0k = c0i >> 4, b0n = (c0i & 15) * 8;
    int b1k = c1i >> 4, b1n = (c1i & 15) * 8;
    uint a0d = (uint)(a0r * PA + a0k) * 2;
    uint a1d = (uint)(a1r * PA + a1k) * 2;
    uint b0d = (uint)(b0k * PB + b0n) * 2;
    uint b1d = (uint)(b1k * PB + b1n) * 2;
    const __half* a0s_h = Ah + (size_t)(m0 + a0r) * K + a0k;
    const __half* a1s_h = Ah + (size_t)(m0 + a1r) * K + a1k;
    const __half* a0s_l = Al + (size_t)(m0 + a0r) * K + a0k;
    const __half* a1s_l = Al + (size_t)(m0 + a1r) * K + a1k;
    const __half* b0s   = Bh + (size_t)b0k * NSP + n0 + b0n;
    const __half* b1s   = Bh + (size_t)b1k * NSP + n0 + b1n;

    int a_row  = (lane & 7) + ((lane >> 3) & 1) * 8;
    int a_koff = ((lane >> 4) & 1) * 8;
    int b_row  = (lane & 7) + ((lane >> 3) & 1) * 8;

    float4 acc[4][4];
    #pragma unroll
    for (int i = 0; i < 4; i++)
        #pragma unroll
        for (int j = 0; j < 4; j++) acc[i][j] = make_float4(0.f, 0.f, 0.f, 0.f);

    const int NK = K / 32;   // 8

    #define ISSUE(kc_, stg_) do {                                           \
        int ko_ = (kc_) * 32;                                               \
        size_t bko_ = (size_t)ko_ * NSP;                                    \
        uint d_ = sbase + (uint)(stg_) * STG_B;                             \
        cpasync16(d_ + AH_OFF + a0d, a0s_h + ko_);                          \
        cpasync16(d_ + AH_OFF + a1d, a1s_h + ko_);                          \
        cpasync16(d_ + AL_OFF + a0d, a0s_l + ko_);                          \
        cpasync16(d_ + AL_OFF + a1d, a1s_l + ko_);                          \
        cpasync16(d_ + BH_OFF + b0d, b0s + bko_);                           \
        cpasync16(d_ + BH_OFF + b1d, b1s + bko_);                           \
        CP_COMMIT();                                                        \
    } while (0)

    ISSUE(0, 0);
    ISSUE(1, 1);

    for (int kc = 0; kc < NK; kc++) {
        if (kc < NK - 1) cp_wait<1>(); else cp_wait<0>();
        __syncthreads();
        if (kc + 2 < NK) {
            int stg = kc + 2;
            while (stg >= 3) stg -= 3;
            ISSUE(kc + 2, stg);
        }

        int cs = kc;
        while (cs >= 3) cs -= 3;
        uint aH = sbase + (uint)cs * STG_B + AH_OFF;
        uint aL = sbase + (uint)cs * STG_B + AL_OFF;
        uint bH = sbase + (uint)cs * STG_B + BH_OFF;

        #pragma unroll
        for (int kk = 0; kk < 32; kk += 16) {
            uint ah[4][4], al[4][4], bh[4][2];
            #pragma unroll
            for (int mt = 0; mt < 4; mt++) {
                uint off = (uint)((wm + mt * 16 + a_row) * PA + kk + a_koff) * 2;
                ldsm4(ah[mt][0], ah[mt][1], ah[mt][2], ah[mt][3], aH + off);
                ldsm4(al[mt][0], al[mt][1], al[mt][2], al[mt][3], aL + off);
            }
            #pragma unroll
            for (int nt = 0; nt < 4; nt++) {
                uint off = (uint)((kk + b_row) * PB + wn + nt * 8) * 2;
                ldsm2t(bh[nt][0], bh[nt][1], bH + off);
            }
            #pragma unroll
            for (int mt = 0; mt < 4; mt++)
                #pragma unroll
                for (int nt = 0; nt < 4; nt++) {
                    mmah16816(acc[mt][nt], ah[mt][0], ah[mt][1], ah[mt][2], ah[mt][3],
                              bh[nt][0], bh[nt][1]);
                    mmah16816(acc[mt][nt], al[mt][0], al[mt][1], al[mt][2], al[mt][3],
                              bh[nt][0], bh[nt][1]);
                }
        }
    }

    int g = lane >> 2, t4 = lane & 3;
    if (KIND == 0) {
        // fp16 epilogue: q (rows 0..255) -> g_q16; k,v (rows 256..767) -> g_kv16
        __half* dst;
        int rowoff;
        if (blockIdx.y < 2) {
            dst = g_q16 + (size_t)b * CCH * NSP;
            rowoff = 0;
        } else {
            dst = g_kv16 + (size_t)b * 2 * CCH * NSP;
            rowoff = 256;
        }
        #pragma unroll
        for (int mt = 0; mt < 4; mt++) {
            int m_g = m0 + wm + mt * 16 + g - rowoff;
            #pragma unroll
            for (int nt = 0; nt < 4; nt++) {
                int n_g = n0 + wn + nt * 8 + 2 * t4;
                float4 d = acc[mt][nt];
                size_t o0 = (size_t)m_g * NSP + n_g;
                size_t o1 = o0 + (size_t)8 * NSP;
                *(uint*)(dst + o0) = pkh2(d.x, d.y);
                *(uint*)(dst + o1) = pkh2(d.z, d.w);
            }
        }
    } else {
        float* Cp = Cext + (size_t)b * M * NSP;
        #pragma unroll
        for (int mt = 0; mt < 4; mt++) {
            int m_g = m0 + wm + mt * 16 + g;
            float b0v = bias[m_g];
            float b1v = bias[m_g + 8];
            #pragma unroll
            for (int nt = 0; nt < 4; nt++) {
                int n_g = n0 + wn + nt * 8 + 2 * t4;
                float4 d = acc[mt][nt];
                float2 lo = make_float2(d.x + b0v, d.y + b0v);
                float2 hi = make_float2(d.z + b1v, d.w + b1v);
                *(float2*)(Cp + (size_t)m_g * NSP + n_g)       = lo;
                *(float2*)(Cp + (size_t)(m_g + 8) * NSP + n_g) = hi;
            }
        }
    }
}

// ---------------- 5) k-row sum of exp (fp16 k; no max pass) ----------------------
__global__ __launch_bounds__(256) void ksum_kernel()
{
    int row = blockIdx.x;
    int b = row >> 8, ch = row & 255;
    const uint4* p4 = (const uint4*)(g_kv16 + (size_t)b * 2 * CCH * NSP
                                     + (size_t)ch * NSP);
    float s = 0.f;
    #pragma unroll
    for (int i = 0; i < 2; i++) {
        uint4 u = p4[threadIdx.x + i * 256];   // 8 halves
        const __half2* h = (const __half2*)&u;
        #pragma unroll
        for (int j = 0; j < 4; j++) {
            float2 f = __half22float2(h[j]);
            s += __expf(f.x) + __expf(f.y);
        }
    }
    __shared__ float ssum[8];
    #pragma unroll
    for (int o = 16; o; o >>= 1) s += __shfl_xor_sync(0xffffffffu, s, o);
    int w = threadIdx.x >> 5, l = threadIdx.x & 31;
    if (l == 0) ssum[w] = s;
    __syncthreads();
    if (threadIdx.x == 0) {
        s = 0.f;
        #pragma unroll
        for (int i = 0; i < 8; i++) s += ssum[i];
        g_krs[row] = 1.0f / s;
    }
}

// ---------------- 6) att partials (fp16 k,v) ---------------------------------------
__global__ __launch_bounds__(256) void att_kernel()
{
    int bh = blockIdx.x >> 4;
    int chunk = blockIdx.x & (ACHK - 1);
    int b = bh >> 3, h = bh & 7;
    const __half* kp = g_kv16 + (size_t)b * 2 * CCH * NSP + (size_t)(h * HD) * NSP;
    const __half* vp = kp + (size_t)CCH * NSP;

    __shared__ float ks[128][ATT_P];
    __shared__ float vs[128][ATT_P];

    int tid = threadIdx.x;
    int sg = tid >> 6;
    int t6 = tid & 63;
    int d0 = (t6 & 7) * 4;
    int e0 = (t6 >> 3) * 4;
    int nfill = tid & 127;
    int dgb   = tid >> 7;

    float acc[4][4];
    #pragma unroll
    for (int i = 0; i < 4; i++)
        #pragma unroll
        for (int j = 0; j < 4; j++) acc[i][j] = 0.f;

    int nbeg = chunk * (NSP / ACHK);
    #pragma unroll
    for (int n0 = nbeg; n0 < nbeg + (NSP / ACHK); n0 += 128) {
        #pragma unroll
        for (int t = 0; t < 4; t++) {
            int dg = dgb + 2 * t;
            int dr = dg * 4;
            float4 kv;
            kv.x = __expf(__half2float(kp[(size_t)(dr + 0) * NSP + n0 + nfill]));
            kv.y = __expf(__half2float(kp[(size_t)(dr + 1) * NSP + n0 + nfill]));
            kv.z = __expf(__half2float(kp[(size_t)(dr + 2) * NSP + n0 + nfill]));
            kv.w = __expf(__half2float(kp[(size_t)(dr + 3) * NSP + n0 + nfill]));
            *(float4*)&ks[nfill][dr] = kv;
            float4 vv;
            vv.x = __half2float(vp[(size_t)(dr + 0) * NSP + n0 + nfill]);
            vv.y = __half2float(vp[(size_t)(dr + 1) * NSP + n0 + nfill]);
            vv.z = __half2float(vp[(size_t)(dr + 2) * NSP + n0 + nfill]);
            vv.w = __half2float(vp[(size_t)(dr + 3) * NSP + n0 + nfill]);
            *(float4*)&vs[nfill][dr] = vv;
        }
        __syncthreads();

        int nb = sg * 32;
        #pragma unroll 8
        for (int nn = 0; nn < 32; nn++) {
            float4 ka = *(const float4*)&ks[nb + nn][d0];
            float4 va = *(const float4*)&vs[nb + nn][e0];
            acc[0][0] += ka.x * va.x; acc[0][1] += ka.x * va.y;
            acc[0][2] += ka.x * va.z; acc[0][3] += ka.x * va.w;
            acc[1][0] += ka.y * va.x; acc[1][1] += ka.y * va.y;
            acc[1][2] += ka.y * va.z; acc[1][3] += ka.y * va.w;
            acc[2][0] += ka.z * va.x; acc[2][1] += ka.z * va.y;
            acc[2][2] += ka.z * va.z; acc[2][3] += ka.z * va.w;
            acc[3][0] += ka.w * va.x; acc[3][1] += ka.w * va.y;
            acc[3][2] += ka.w * va.z; acc[3][3] += ka.w * va.w;
        }
        __syncthreads();
    }

    float* ap = g_attp + ((size_t)blockIdx.x * 4 + sg) * 1024;
    #pragma unroll
    for (int i = 0; i < 4; i++) {
        float4 o = make_float4(acc[i][0], acc[i][1], acc[i][2], acc[i][3]);
        *(float4*)(ap + (d0 + i) * HD + e0) = o;
    }
}

__global__ __launch_bounds__(256) void att_reduce_kernel()
{
    int bh = blockIdx.x;
    int b = bh >> 3, h = bh & 7;
    const int NP = ACHK * 4;
    #pragma unroll
    for (int t = 0; t < 4; t++) {
        int idx = threadIdx.x + t * 256;
        int d = idx >> 5;
        float s = 0.f;
        #pragma unroll
        for (int c = 0; c < NP; c++)
            s += g_attp[((size_t)bh * NP + c) * 1024 + idx];
        g_att[(size_t)bh * 1024 + idx] = s * g_krs[b * CCH + h * HD + d];
    }
}

// ---------------- 7) fold proj weights with att, write fp16 split directly --------
__global__ __launch_bounds__(256) void wf_fold_kernel(const float* __restrict__ projw)
{
    int b = blockIdx.x >> 4, ob = blockIdx.x & 15;
    __shared__ float attS[8][32][33];
    __shared__ float wS[16 * 256];
    int tid = threadIdx.x;

    #pragma unroll
    for (int t = 0; t < 8; t++) {
        int idx = tid + t * 256;
        float4 v = ((const float4*)(g_att + (size_t)b * 8192))[idx];
        int fi = idx * 4;
        int hh = fi >> 10, dd = (fi >> 5) & 31, ee = fi & 31;
        attS[hh][dd][ee + 0] = v.x;
        attS[hh][dd][ee + 1] = v.y;
        attS[hh][dd][ee + 2] = v.z;
        attS[hh][dd][ee + 3] = v.w;
    }
    #pragma unroll
    for (int t = 0; t < 4; t++) {
        int idx = tid + t * 256;
        ((float4*)wS)[idx] = ((const float4*)(projw + (size_t)ob * 16 * 256))[idx];
    }
    __syncthreads();

    int hh = tid >> 5, dd = tid & 31;
    float acc[16];
    #pragma unroll
    for (int i = 0; i < 16; i++) acc[i] = 0.f;
    for (int e = 0; e < 32; e++) {
        float a = attS[hh][dd][e];
        #pragma unroll
        for (int oi = 0; oi < 16; oi++)
            acc[oi] += a * wS[oi * 256 + hh * 32 + e];
    }
    #pragma unroll
    for (int oi = 0; oi < 16; oi++) {
        size_t idx = ((size_t)b * CCH + ob * 16 + oi) * CCH + tid;
        float a = acc[oi];
        __half hh16 = __float2half_rn(a);
        g_wfh[idx] = hh16;
        g_wfl[idx] = __float2half_rn(a - __half2float(hh16));
    }
}

// ---------------- launch ----------------------------------------------------------------
extern "C" void kernel_launch(void* const* d_in, const int* in_sizes, int n_in,
                              void* d_out, int out_size)
{
    const float* x     = (const float*)d_in[0];
    const float* gnw   = (const float*)d_in[1];
    const float* gnb   = (const float*)d_in[2];
    const float* qkvw  = (const float*)d_in[3];
    const float* projw = (const float*)d_in[4];
    const float* projb = (const float*)d_in[5];
    float* out = (float*)d_out;

    cudaFuncSetAttribute(pgemm_kernel<M3, 0, 0, 0>,
                         cudaFuncAttributeMaxDynamicSharedMemorySize, GSMEM);
    cudaFuncSetAttribute(pgemm_kernel<CCH, 1, 1, 1>,
                         cudaFuncAttributeMaxDynamicSharedMemorySize, GSMEM);

    gn_partial_kernel<<<BATCH * NGRP * 4, 256>>>(x);
    gn_final_kernel<<<1, BATCH * NGRP>>>();

    gnconv_kernel<<<BATCH * CCH * NSP / 1024, 256>>>(x, gnw, gnb);
    wsplit_kernel<<<M3 * CCH / 1024, 256>>>(qkvw);

    pgemm_kernel<M3, 0, 0, 0>
        <<<dim3(NSP / 128, M3 / 128, BATCH), 256, GSMEM>>>(nullptr, nullptr);

    ksum_kernel<<<BATCH * CCH, 256>>>();

    att_kernel<<<BATCH * NH * ACHK, 256>>>();
    att_reduce_kernel<<<BATCH * NH, 256>>>();

    wf_fold_kernel<<<BATCH * 16, 256>>>(projw);

    pgemm_kernel<CCH, 1, 1, 1>
        <<<dim3(NSP / 128, CCH / 128, BATCH), 256, GSMEM>>>(out, projb);
}

// round 15
// speedup vs baseline: 4.0782x; 1.1179x over previous
#include <cuda_runtime.h>
#include <cuda_fp16.h>
#include <math.h>
#include <cstdint>

#define BATCH 16
#define CCH   256
#define NSP   4096
#define M3    768
#define NGRP  4
#define CPG   64
#define NH    8
#define HD    32

#define PA 40     // A smem pitch (fp16)
#define PB 136    // B smem pitch (fp16)

typedef unsigned int uint;

// pgemm smem stage layout (bytes): Ah(10240) Al(10240) B(8704)
#define AH_OFF 0
#define AL_OFF 10240
#define BH_OFF 20480
#define STG_B  29184
#define GSMEM  (3 * STG_B)   // 87552

// att smem layout
#define EK_OFF 0
#define EV_OFF 33280              // 32*520*2
#define ATT_SMEM 66560            // 2*32*520*2 (attw 32KB overlaps EK region)

// ---------------- scratch (referenced ONLY in device code) --------------------
__device__ __align__(16) float g_att[BATCH * NH * HD * HD];
__device__ __align__(16) float g_attp[BATCH * NH * 8 * HD * HD];
__device__ float g_mu[BATCH * NGRP];
__device__ float g_rsig[BATCH * NGRP];
__device__ float g_gnp[BATCH * NGRP * 4 * 2];
__device__ float g_krs[BATCH * CCH];
__device__ __align__(16) __half g_x16[BATCH * CCH * NSP];      // GN(x) fp16 [b][k][n]
__device__ __align__(16) __half g_q16[BATCH * CCH * NSP];      // q fp16 [b][k][n]
__device__ __align__(16) __half g_kv16[BATCH * 2 * CCH * NSP]; // k,v fp16 [b][512][n]
__device__ __align__(16) __half g_wh[M3 * CCH];
__device__ __align__(16) __half g_wl[M3 * CCH];
__device__ __align__(16) __half g_wfh[BATCH * CCH * CCH];
__device__ __align__(16) __half g_wfl[BATCH * CCH * CCH];

// ---------------- helpers ------------------------------------------------------
__device__ __forceinline__ uint pkh2(float a, float b) {
    __half2 t = __floats2half2_rn(a, b);
    return *reinterpret_cast<uint*>(&t);
}
__device__ __forceinline__ void splith2(float a, float b, uint& hi, uint& lo) {
    float ha = __half2float(__float2half_rn(a));
    float hb = __half2float(__float2half_rn(b));
    hi = pkh2(ha, hb);
    lo = pkh2(a - ha, b - hb);
}
__device__ __forceinline__ void ldsm4(uint& r0, uint& r1, uint& r2, uint& r3, uint addr) {
    asm volatile("ldmatrix.sync.aligned.m8n8.x4.shared.b16 {%0,%1,%2,%3}, [%4];"
                 : "=r"(r0), "=r"(r1), "=r"(r2), "=r"(r3) : "r"(addr));
}
__device__ __forceinline__ void ldsm2t(uint& r0, uint& r1, uint addr) {
    asm volatile("ldmatrix.sync.aligned.m8n8.x2.trans.shared.b16 {%0,%1}, [%2];"
                 : "=r"(r0), "=r"(r1) : "r"(addr));
}
__device__ __forceinline__ void mmah16816(float4& d, uint a0, uint a1, uint a2, uint a3,
                                          uint b0, uint b1) {
    asm volatile("mma.sync.aligned.m16n8k16.row.col.f32.f16.f16.f32 "
                 "{%0,%1,%2,%3}, {%4,%5,%6,%7}, {%8,%9}, {%0,%1,%2,%3};"
                 : "+f"(d.x), "+f"(d.y), "+f"(d.z), "+f"(d.w)
                 : "r"(a0), "r"(a1), "r"(a2), "r"(a3), "r"(b0), "r"(b1));
}
__device__ __forceinline__ void cpasync16(uint dst, const void* src) {
    asm volatile("cp.async.cg.shared.global [%0], [%1], 16;" :: "r"(dst), "l"(src));
}
#define CP_COMMIT() asm volatile("cp.async.commit_group;" ::: "memory")
template<int N>
__device__ __forceinline__ void cp_wait() {
    asm volatile("cp.async.wait_group %0;" :: "n"(N) : "memory");
}

// ---------------- 1) GroupNorm stats --------------------------------------------
__global__ __launch_bounds__(256) void gn_partial_kernel(const float* __restrict__ x)
{
    int bg = blockIdx.x >> 2, part = blockIdx.x & 3;
    const float4* p = (const float4*)x + (size_t)bg * 65536 + part * 16384;
    float s = 0.f, sq = 0.f;
    for (int i = threadIdx.x; i < 16384; i += 256) {
        float4 v = p[i];
        s  += v.x + v.y + v.z + v.w;
        sq += v.x * v.x + v.y * v.y + v.z * v.z + v.w * v.w;
    }
    __shared__ float ss[8], ssq[8];
    #pragma unroll
    for (int o = 16; o; o >>= 1) {
        s  += __shfl_down_sync(0xffffffffu, s, o);
        sq += __shfl_down_sync(0xffffffffu, sq, o);
    }
    int w = threadIdx.x >> 5, l = threadIdx.x & 31;
    if (l == 0) { ss[w] = s; ssq[w] = sq; }
    __syncthreads();
    if (threadIdx.x == 0) {
        s = 0.f; sq = 0.f;
        #pragma unroll
        for (int i = 0; i < 8; i++) { s += ss[i]; sq += ssq[i]; }
        g_gnp[blockIdx.x * 2]     = s;
        g_gnp[blockIdx.x * 2 + 1] = sq;
    }
}
__global__ void gn_final_kernel()
{
    int bg = threadIdx.x;
    float s = 0.f, sq = 0.f;
    #pragma unroll
    for (int i = 0; i < 4; i++) {
        s  += g_gnp[(bg * 4 + i) * 2];
        sq += g_gnp[(bg * 4 + i) * 2 + 1];
    }
    const float inv = 1.0f / (float)(CPG * NSP);
    float mu  = s * inv;
    float var = sq * inv - mu * mu;
    g_mu[bg]   = mu;
    g_rsig[bg] = rsqrtf(var + 1e-5f);
}

// ---------------- 2) GN + convert x to fp16 --------------------------------------
__global__ __launch_bounds__(256) void gnconv_kernel(const float* __restrict__ x,
                                                     const float* __restrict__ gnw,
                                                     const float* __restrict__ gnb)
{
    size_t idx = (size_t)blockIdx.x * 256 + threadIdx.x;
    size_t f = idx * 4;
    int b = (int)(f >> 20);
    int c = (int)((f >> 12) & 255);
    int g = c >> 6;
    float rs = g_rsig[b * NGRP + g];
    float mu = g_mu[b * NGRP + g];
    float w  = gnw[c] * rs;
    float bb = gnb[c] - mu * w;
    float4 v = ((const float4*)x)[idx];
    uint2 o;
    o.x = pkh2(v.x * w + bb, v.y * w + bb);
    o.y = pkh2(v.z * w + bb, v.w * w + bb);
    *(uint2*)(g_x16 + f) = o;
}

// ---------------- 3) qkv weight split --------------------------------------------
__global__ __launch_bounds__(256) void wsplit_kernel(const float* __restrict__ w)
{
    int idx = blockIdx.x * 256 + threadIdx.x;
    float4 v = ((const float4*)w)[idx];
    uint2 hi, lo;
    splith2(v.x, v.y, hi.x, lo.x);
    splith2(v.z, v.w, hi.y, lo.y);
    *(uint2*)(g_wh + idx * 4) = hi;
    *(uint2*)(g_wl + idx * 4) = lo;
}

// ---------------- 4) pipelined fp16 2-term GEMM (2 CTAs/SM) ----------------------
template<int M, int KIND, int ASEL, int BSEL>
__global__ __launch_bounds__(256, 2) void pgemm_kernel(
    float* __restrict__ Cext, const float* __restrict__ bias)
{
    extern __shared__ char smraw[];
    const int K = 256;
    int b = blockIdx.z;
    const __half* Ah = (ASEL == 0) ? g_wh : (g_wfh + (size_t)b * M * K);
    const __half* Al = (ASEL == 0) ? g_wl : (g_wfl + (size_t)b * M * K);
    const __half* Bh = ((BSEL == 0) ? g_x16 : g_q16) + (size_t)b * K * NSP;
    int m0 = blockIdx.y * 128, n0 = blockIdx.x * 128;

    int tid  = threadIdx.x;
    int wid  = tid >> 5;
    int lane = tid & 31;
    int wm = (wid >> 2) * 64;
    int wn = (wid & 3) * 32;

    uint sbase = (uint)__cvta_generic_to_shared(smraw);

    int c0i = tid, c1i = tid + 256;
    int a0r = c0i >> 2, a0k = (c0i & 3) * 8;
    int a1r = c1i >> 2, a1k = (c1i & 3) * 8;
    int b0k = c0i >> 4, b0n = (c0i & 15) * 8;
    int b1k = c1i >> 4, b1n = (c1i & 15) * 8;
    uint a0d = (uint)(a0r * PA + a0k) * 2;
    uint a1d = (uint)(a1r * PA + a1k) * 2;
    uint b0d = (uint)(b0k * PB + b0n) * 2;
    uint b1d = (uint)(b1k * PB + b1n) * 2;
    const __half* a0s_h = Ah + (size_t)(m0 + a0r) * K + a0k;
    const __half* a1s_h = Ah + (size_t)(m0 + a1r) * K + a1k;
    const __half* a0s_l = Al + (size_t)(m0 + a0r) * K + a0k;
    const __half* a1s_l = Al + (size_t)(m0 + a1r) * K + a1k;
    const __half* b0s   = Bh + (size_t)b0k * NSP + n0 + b0n;
    const __half* b1s   = Bh + (size_t)b1k * NSP + n0 + b1n;

    int a_row  = (lane & 7) + ((lane >> 3) & 1) * 8;
    int a_koff = ((lane >> 4) & 1) * 8;
    int b_row  = (lane & 7) + ((lane >> 3) & 1) * 8;

    float4 acc[4][4];
    #pragma unroll
    for (int i = 0; i < 4; i++)
        #pragma unroll
        for (int j = 0; j < 4; j++) acc[i][j] = make_float4(0.f, 0.f, 0.f, 0.f);

    const int NK = K / 32;

    #define ISSUE(kc_, stg_) do {                                           \
        int ko_ = (kc_) * 32;                                               \
        size_t bko_ = (size_t)ko_ * NSP;                                    \
        uint d_ = sbase + (uint)(stg_) * STG_B;                             \
        cpasync16(d_ + AH_OFF + a0d, a0s_h + ko_);                          \
        cpasync16(d_ + AH_OFF + a1d, a1s_h + ko_);                          \
        cpasync16(d_ + AL_OFF + a0d, a0s_l + ko_);                          \
        cpasync16(d_ + AL_OFF + a1d, a1s_l + ko_);                          \
        cpasync16(d_ + BH_OFF + b0d, b0s + bko_);                           \
        cpasync16(d_ + BH_OFF + b1d, b1s + bko_);                           \
        CP_COMMIT();                                                        \
    } while (0)

    ISSUE(0, 0);
    ISSUE(1, 1);

    for (int kc = 0; kc < NK; kc++) {
        if (kc < NK - 1) cp_wait<1>(); else cp_wait<0>();
        __syncthreads();
        if (kc + 2 < NK) {
            int stg = kc + 2;
            while (stg >= 3) stg -= 3;
            ISSUE(kc + 2, stg);
        }

        int cs = kc;
        while (cs >= 3) cs -= 3;
        uint aH = sbase + (uint)cs * STG_B + AH_OFF;
        uint aL = sbase + (uint)cs * STG_B + AL_OFF;
        uint bH = sbase + (uint)cs * STG_B + BH_OFF;

        #pragma unroll
        for (int kk = 0; kk < 32; kk += 16) {
            uint ah[4][4], al[4][4], bh[4][2];
            #pragma unroll
            for (int mt = 0; mt < 4; mt++) {
                uint off = (uint)((wm + mt * 16 + a_row) * PA + kk + a_koff) * 2;
                ldsm4(ah[mt][0], ah[mt][1], ah[mt][2], ah[mt][3], aH + off);
                ldsm4(al[mt][0], al[mt][1], al[mt][2], al[mt][3], aL + off);
            }
            #pragma unroll
            for (int nt = 0; nt < 4; nt++) {
                uint off = (uint)((kk + b_row) * PB + wn + nt * 8) * 2;
                ldsm2t(bh[nt][0], bh[nt][1], bH + off);
            }
            #pragma unroll
            for (int mt = 0; mt < 4; mt++)
                #pragma unroll
                for (int nt = 0; nt < 4; nt++) {
                    mmah16816(acc[mt][nt], ah[mt][0], ah[mt][1], ah[mt][2], ah[mt][3],
                              bh[nt][0], bh[nt][1]);
                    mmah16816(acc[mt][nt], al[mt][0], al[mt][1], al[mt][2], al[mt][3],
                              bh[nt][0], bh[nt][1]);
                }
        }
    }

    int g = lane >> 2, t4 = lane & 3;
    if (KIND == 0) {
        __half* dst;
        int rowoff;
        if (blockIdx.y < 2) {
            dst = g_q16 + (size_t)b * CCH * NSP;
            rowoff = 0;
        } else {
            dst = g_kv16 + (size_t)b * 2 * CCH * NSP;
            rowoff = 256;
        }
        #pragma unroll
        for (int mt = 0; mt < 4; mt++) {
            int m_g = m0 + wm + mt * 16 + g - rowoff;
            #pragma unroll
            for (int nt = 0; nt < 4; nt++) {
                int n_g = n0 + wn + nt * 8 + 2 * t4;
                float4 d = acc[mt][nt];
                size_t o0 = (size_t)m_g * NSP + n_g;
                size_t o1 = o0 + (size_t)8 * NSP;
                *(uint*)(dst + o0) = pkh2(d.x, d.y);
                *(uint*)(dst + o1) = pkh2(d.z, d.w);
            }
        }
    } else {
        float* Cp = Cext + (size_t)b * M * NSP;
        #pragma unroll
        for (int mt = 0; mt < 4; mt++) {
            int m_g = m0 + wm + mt * 16 + g;
            float b0v = bias[m_g];
            float b1v = bias[m_g + 8];
            #pragma unroll
            for (int nt = 0; nt < 4; nt++) {
                int n_g = n0 + wn + nt * 8 + 2 * t4;
                float4 d = acc[mt][nt];
                float2 lo = make_float2(d.x + b0v, d.y + b0v);
                float2 hi = make_float2(d.z + b1v, d.w + b1v);
                *(float2*)(Cp + (size_t)m_g * NSP + n_g)       = lo;
                *(float2*)(Cp + (size_t)(m_g + 8) * NSP + n_g) = hi;
            }
        }
    }
}

// ---------------- 5) k-row sum of exp ---------------------------------------------
__global__ __launch_bounds__(256) void ksum_kernel()
{
    int row = blockIdx.x;
    int b = row >> 8, ch = row & 255;
    const uint4* p4 = (const uint4*)(g_kv16 + (size_t)b * 2 * CCH * NSP
                                     + (size_t)ch * NSP);
    float s = 0.f;
    #pragma unroll
    for (int i = 0; i < 2; i++) {
        uint4 u = p4[threadIdx.x + i * 256];
        const __half2* h = (const __half2*)&u;
        #pragma unroll
        for (int j = 0; j < 4; j++) {
            float2 f = __half22float2(h[j]);
            s += __expf(f.x) + __expf(f.y);
        }
    }
    __shared__ float ssum[8];
    #pragma unroll
    for (int o = 16; o; o >>= 1) s += __shfl_xor_sync(0xffffffffu, s, o);
    int w = threadIdx.x >> 5, l = threadIdx.x & 31;
    if (l == 0) ssum[w] = s;
    __syncthreads();
    if (threadIdx.x == 0) {
        s = 0.f;
        #pragma unroll
        for (int i = 0; i < 8; i++) s += ssum[i];
        g_krs[row] = 1.0f / s;
    }
}

// ---------------- 6) att via tensor cores -----------------------------------------
// att^T computed as C[e][d] = sum_n v[e][n] * exp(k[d][n]); partial per 512-n chunk.
__global__ __launch_bounds__(256) void att_kernel()
{
    extern __shared__ char smraw[];
    int bh = blockIdx.x >> 3;
    int chunk = blockIdx.x & 7;
    int b = bh >> 3, h = bh & 7;
    const __half* kp = g_kv16 + (size_t)b * 2 * CCH * NSP + (size_t)(h * HD) * NSP;
    const __half* vp = kp + (size_t)CCH * NSP;
    int n0 = chunk * 512;

    int tid  = threadIdx.x;
    int wid  = tid >> 5;
    int lane = tid & 31;
    uint sbase = (uint)__cvta_generic_to_shared(smraw);

    // fill: eK = exp(k) [32 d][520p n], eV = v [32 e][520p n]
    #pragma unroll
    for (int i = 0; i < 8; i++) {
        int c = tid + i * 256;
        int row  = c >> 6;
        int colq = c & 63;
        size_t gofs = (size_t)row * NSP + n0 + colq * 8;
        uint soff = (uint)(row * 520 + colq * 8) * 2;
        uint4 u = *(const uint4*)(kp + gofs);
        __half2* hh = (__half2*)&u;
        #pragma unroll
        for (int j = 0; j < 4; j++) {
            float2 f = __half22float2(hh[j]);
            hh[j] = __floats2half2_rn(__expf(f.x), __expf(f.y));
        }
        *(uint4*)(smraw + EK_OFF + soff) = u;
        *(uint4*)(smraw + EV_OFF + soff) = *(const uint4*)(vp + gofs);
    }
    __syncthreads();

    int a_row  = (lane & 7) + ((lane >> 3) & 1) * 8;
    int a_koff = ((lane >> 4) & 1) * 8;
    int b_drow = lane >> 2;          // d within n8 tile
    int b_noff = (lane & 3) * 2;     // k (=n) pair offset

    float4 acc[2][4];
    #pragma unroll
    for (int i = 0; i < 2; i++)
        #pragma unroll
        for (int j = 0; j < 4; j++) acc[i][j] = make_float4(0.f, 0.f, 0.f, 0.f);

    int nkb = wid * 64;
    #pragma unroll
    for (int cc = 0; cc < 4; cc++) {
        int nk = nkb + cc * 16;
        uint a[2][4];
        #pragma unroll
        for (int mt = 0; mt < 2; mt++) {
            uint off = (uint)((mt * 16 + a_row) * 520 + nk + a_koff) * 2;
            ldsm4(a[mt][0], a[mt][1], a[mt][2], a[mt][3], sbase + EV_OFF + off);
        }
        #pragma unroll
        for (int nt = 0; nt < 4; nt++) {
            uint boff = (uint)((nt * 8 + b_drow) * 520 + nk + b_noff) * 2;
            uint b0 = *(const uint*)(smraw + EK_OFF + boff);
            uint b1 = *(const uint*)(smraw + EK_OFF + boff + 16);
            #pragma unroll
            for (int mt = 0; mt < 2; mt++)
                mmah16816(acc[mt][nt], a[mt][0], a[mt][1], a[mt][2], a[mt][3], b0, b1);
        }
    }
    __syncthreads();

    // warp partials -> smem (reuse tile region), layout attw[w][d*32+e]
    float* attw = (float*)smraw;
    int g = lane >> 2, t4 = lane & 3;
    #pragma unroll
    for (int mt = 0; mt < 2; mt++) {
        int e = mt * 16 + g;
        #pragma unroll
        for (int nt = 0; nt < 4; nt++) {
            int d = nt * 8 + 2 * t4;
            float4 a = acc[mt][nt];
            float* base = attw + wid * 1024;
            base[(d    ) * 32 + e    ] = a.x;
            base[(d + 1) * 32 + e    ] = a.y;
            base[(d    ) * 32 + e + 8] = a.z;
            base[(d + 1) * 32 + e + 8] = a.w;
        }
    }
    __syncthreads();

    int ob = tid * 4;
    float4 o = make_float4(0.f, 0.f, 0.f, 0.f);
    #pragma unroll
    for (int w = 0; w < 8; w++) {
        float4 p = *(const float4*)(attw + w * 1024 + ob);
        o.x += p.x; o.y += p.y; o.z += p.z; o.w += p.w;
    }
    *(float4*)(g_attp + (size_t)blockIdx.x * 1024 + ob) = o;
}

// reduce 8 chunk-partials, apply 1/sum
__global__ __launch_bounds__(256) void att_reduce_kernel()
{
    int bh = blockIdx.x;
    int b = bh >> 3, h = bh & 7;
    #pragma unroll
    for (int t = 0; t < 4; t++) {
        int idx = threadIdx.x + t * 256;
        int d = idx >> 5;
        float s = 0.f;
        #pragma unroll
        for (int c = 0; c < 8; c++)
            s += g_attp[((size_t)bh * 8 + c) * 1024 + idx];
        g_att[(size_t)bh * 1024 + idx] = s * g_krs[b * CCH + h * HD + d];
    }
}

// ---------------- 7) fold proj weights with att, fp16 split out -------------------
__global__ __launch_bounds__(256) void wf_fold_kernel(const float* __restrict__ projw)
{
    int b = blockIdx.x >> 4, ob = blockIdx.x & 15;
    __shared__ float attS[8][32][33];
    __shared__ float wS[16 * 256];
    int tid = threadIdx.x;

    #pragma unroll
    for (int t = 0; t < 8; t++) {
        int idx = tid + t * 256;
        float4 v = ((const float4*)(g_att + (size_t)b * 8192))[idx];
        int fi = idx * 4;
        int hh = fi >> 10, dd = (fi >> 5) & 31, ee = fi & 31;
        attS[hh][dd][ee + 0] = v.x;
        attS[hh][dd][ee + 1] = v.y;
        attS[hh][dd][ee + 2] = v.z;
        attS[hh][dd][ee + 3] = v.w;
    }
    #pragma unroll
    for (int t = 0; t < 4; t++) {
        int idx = tid + t * 256;
        ((float4*)wS)[idx] = ((const float4*)(projw + (size_t)ob * 16 * 256))[idx];
    }
    __syncthreads();

    int hh = tid >> 5, dd = tid & 31;
    float acc[16];
    #pragma unroll
    for (int i = 0; i < 16; i++) acc[i] = 0.f;
    for (int e = 0; e < 32; e++) {
        float a = attS[hh][dd][e];
        #pragma unroll
        for (int oi = 0; oi < 16; oi++)
            acc[oi] += a * wS[oi * 256 + hh * 32 + e];
    }
    #pragma unroll
    for (int oi = 0; oi < 16; oi++) {
        size_t idx = ((size_t)b * CCH + ob * 16 + oi) * CCH + tid;
        float a = acc[oi];
        __half hh16 = __float2half_rn(a);
        g_wfh[idx] = hh16;
        g_wfl[idx] = __float2half_rn(a - __half2float(hh16));
    }
}

// ---------------- launch ----------------------------------------------------------------
extern "C" void kernel_launch(void* const* d_in, const int* in_sizes, int n_in,
                              void* d_out, int out_size)
{
    const float* x     = (const float*)d_in[0];
    const float* gnw   = (const float*)d_in[1];
    const float* gnb   = (const float*)d_in[2];
    const float* qkvw  = (const float*)d_in[3];
    const float* projw = (const float*)d_in[4];
    const float* projb = (const float*)d_in[5];
    float* out = (float*)d_out;

    cudaFuncSetAttribute(pgemm_kernel<M3, 0, 0, 0>,
                         cudaFuncAttributeMaxDynamicSharedMemorySize, GSMEM);
    cudaFuncSetAttribute(pgemm_kernel<CCH, 1, 1, 1>,
                         cudaFuncAttributeMaxDynamicSharedMemorySize, GSMEM);
    cudaFuncSetAttribute(att_kernel,
                         cudaFuncAttributeMaxDynamicSharedMemorySize, ATT_SMEM);

    gn_partial_kernel<<<BATCH * NGRP * 4, 256>>>(x);
    gn_final_kernel<<<1, BATCH * NGRP>>>();

    gnconv_kernel<<<BATCH * CCH * NSP / 1024, 256>>>(x, gnw, gnb);
    wsplit_kernel<<<M3 * CCH / 1024, 256>>>(qkvw);

    pgemm_kernel<M3, 0, 0, 0>
        <<<dim3(NSP / 128, M3 / 128, BATCH), 256, GSMEM>>>(nullptr, nullptr);

    ksum_kernel<<<BATCH * CCH, 256>>>();

    att_kernel<<<BATCH * NH * 8, 256, ATT_SMEM>>>();
    att_reduce_kernel<<<BATCH * NH, 256>>>();

    wf_fold_kernel<<<BATCH * 16, 256>>>(projw);

    pgemm_kernel<CCH, 1, 1, 1>
        <<<dim3(NSP / 128, CCH / 128, BATCH), 256, GSMEM>>>(out, projb);
}

// round 16
// speedup vs baseline: 5.2568x; 1.2890x over previous
#include <cuda_runtime.h>
#include <cuda_fp16.h>
#include <math.h>
#include <cstdint>

#define BATCH 16
#define CCH   256
#define NSP   4096
#define M3    768
#define NGRP  4
#define CPG   64
#define NH    8
#define HD    32

#define PA 40     // A smem pitch (fp16)
#define PB 136    // B smem pitch (fp16)

typedef unsigned int uint;

// pgemm smem stage layout (bytes): Ah(10240) Al(10240) B(8704)
#define AH_OFF 0
#define AL_OFF 10240
#define BH_OFF 20480
#define STG_B  29184
#define GSMEM  (3 * STG_B)   // 87552

// att smem layout
#define EK_OFF 0
#define EV_OFF 33280              // 32*520*2
#define ATT_SMEM 66560

// ---------------- scratch (referenced ONLY in device code) --------------------
__device__ __align__(16) float g_att[BATCH * NH * HD * HD];
__device__ __align__(16) float g_attp[BATCH * NH * 8 * HD * HD];
__device__ float g_mu[BATCH * NGRP];
__device__ float g_rsig[BATCH * NGRP];
__device__ float g_gnp[BATCH * NGRP * 4 * 2];
__device__ float g_krs[BATCH * CCH];
__device__ __align__(16) __half g_x16[BATCH * CCH * NSP];      // GN(x) fp16 [b][k][n]
__device__ __align__(16) __half g_q16[BATCH * CCH * NSP];      // q fp16 [b][k][n]
__device__ __align__(16) __half g_kv16[BATCH * 2 * CCH * NSP]; // k,v fp16 [b][512][n]
__device__ __align__(16) __half g_wh[M3 * CCH];
__device__ __align__(16) __half g_wl[M3 * CCH];
__device__ __align__(16) __half g_wfh[BATCH * CCH * CCH];
__device__ __align__(16) __half g_wfl[BATCH * CCH * CCH];

// ---------------- helpers ------------------------------------------------------
__device__ __forceinline__ uint pkh2(float a, float b) {
    __half2 t = __floats2half2_rn(a, b);
    return *reinterpret_cast<uint*>(&t);
}
__device__ __forceinline__ void splith2(float a, float b, uint& hi, uint& lo) {
    float ha = __half2float(__float2half_rn(a));
    float hb = __half2float(__float2half_rn(b));
    hi = pkh2(ha, hb);
    lo = pkh2(a - ha, b - hb);
}
__device__ __forceinline__ void ldsm4(uint& r0, uint& r1, uint& r2, uint& r3, uint addr) {
    asm volatile("ldmatrix.sync.aligned.m8n8.x4.shared.b16 {%0,%1,%2,%3}, [%4];"
                 : "=r"(r0), "=r"(r1), "=r"(r2), "=r"(r3) : "r"(addr));
}
__device__ __forceinline__ void ldsm2t(uint& r0, uint& r1, uint addr) {
    asm volatile("ldmatrix.sync.aligned.m8n8.x2.trans.shared.b16 {%0,%1}, [%2];"
                 : "=r"(r0), "=r"(r1) : "r"(addr));
}
__device__ __forceinline__ void mmah16816(float4& d, uint a0, uint a1, uint a2, uint a3,
                                          uint b0, uint b1) {
    asm volatile("mma.sync.aligned.m16n8k16.row.col.f32.f16.f16.f32 "
                 "{%0,%1,%2,%3}, {%4,%5,%6,%7}, {%8,%9}, {%0,%1,%2,%3};"
                 : "+f"(d.x), "+f"(d.y), "+f"(d.z), "+f"(d.w)
                 : "r"(a0), "r"(a1), "r"(a2), "r"(a3), "r"(b0), "r"(b1));
}
__device__ __forceinline__ void cpasync16(uint dst, const void* src) {
    asm volatile("cp.async.cg.shared.global [%0], [%1], 16;" :: "r"(dst), "l"(src));
}
#define CP_COMMIT() asm volatile("cp.async.commit_group;" ::: "memory")
template<int N>
__device__ __forceinline__ void cp_wait() {
    asm volatile("cp.async.wait_group %0;" :: "n"(N) : "memory");
}

// ---------------- 1) GroupNorm stats --------------------------------------------
__global__ __launch_bounds__(256) void gn_partial_kernel(const float* __restrict__ x)
{
    int bg = blockIdx.x >> 2, part = blockIdx.x & 3;
    const float4* p = (const float4*)x + (size_t)bg * 65536 + part * 16384;
    float s = 0.f, sq = 0.f;
    for (int i = threadIdx.x; i < 16384; i += 256) {
        float4 v = p[i];
        s  += v.x + v.y + v.z + v.w;
        sq += v.x * v.x + v.y * v.y + v.z * v.z + v.w * v.w;
    }
    __shared__ float ss[8], ssq[8];
    #pragma unroll
    for (int o = 16; o; o >>= 1) {
        s  += __shfl_down_sync(0xffffffffu, s, o);
        sq += __shfl_down_sync(0xffffffffu, sq, o);
    }
    int w = threadIdx.x >> 5, l = threadIdx.x & 31;
    if (l == 0) { ss[w] = s; ssq[w] = sq; }
    __syncthreads();
    if (threadIdx.x == 0) {
        s = 0.f; sq = 0.f;
        #pragma unroll
        for (int i = 0; i < 8; i++) { s += ss[i]; sq += ssq[i]; }
        g_gnp[blockIdx.x * 2]     = s;
        g_gnp[blockIdx.x * 2 + 1] = sq;
    }
}
__global__ void gn_final_kernel()
{
    int bg = threadIdx.x;
    float s = 0.f, sq = 0.f;
    #pragma unroll
    for (int i = 0; i < 4; i++) {
        s  += g_gnp[(bg * 4 + i) * 2];
        sq += g_gnp[(bg * 4 + i) * 2 + 1];
    }
    const float inv = 1.0f / (float)(CPG * NSP);
    float mu  = s * inv;
    float var = sq * inv - mu * mu;
    g_mu[bg]   = mu;
    g_rsig[bg] = rsqrtf(var + 1e-5f);
}

// ---------------- 2) GN + convert x to fp16 --------------------------------------
__global__ __launch_bounds__(256) void gnconv_kernel(const float* __restrict__ x,
                                                     const float* __restrict__ gnw,
                                                     const float* __restrict__ gnb)
{
    size_t idx = (size_t)blockIdx.x * 256 + threadIdx.x;
    size_t f = idx * 4;
    int b = (int)(f >> 20);
    int c = (int)((f >> 12) & 255);
    int g = c >> 6;
    float rs = g_rsig[b * NGRP + g];
    float mu = g_mu[b * NGRP + g];
    float w  = gnw[c] * rs;
    float bb = gnb[c] - mu * w;
    float4 v = ((const float4*)x)[idx];
    uint2 o;
    o.x = pkh2(v.x * w + bb, v.y * w + bb);
    o.y = pkh2(v.z * w + bb, v.w * w + bb);
    *(uint2*)(g_x16 + f) = o;
}

// ---------------- 3) qkv weight convert (hi only used by QKV gemm) ----------------
__global__ __launch_bounds__(256) void wsplit_kernel(const float* __restrict__ w)
{
    int idx = blockIdx.x * 256 + threadIdx.x;
    float4 v = ((const float4*)w)[idx];
    uint2 hi, lo;
    splith2(v.x, v.y, hi.x, lo.x);
    splith2(v.z, v.w, hi.y, lo.y);
    *(uint2*)(g_wh + idx * 4) = hi;
    *(uint2*)(g_wl + idx * 4) = lo;
}

// ---------------- 4) pipelined fp16 GEMM (AT = # A terms) ------------------------
template<int M, int KIND, int ASEL, int BSEL, int AT>
__global__ __launch_bounds__(256, 2) void pgemm_kernel(
    float* __restrict__ Cext, const float* __restrict__ bias)
{
    extern __shared__ char smraw[];
    const int K = 256;
    int b = blockIdx.z;
    const __half* Ah = (ASEL == 0) ? g_wh : (g_wfh + (size_t)b * M * K);
    const __half* Al = (ASEL == 0) ? g_wl : (g_wfl + (size_t)b * M * K);
    const __half* Bh = ((BSEL == 0) ? g_x16 : g_q16) + (size_t)b * K * NSP;
    int m0 = blockIdx.y * 128, n0 = blockIdx.x * 128;

    int tid  = threadIdx.x;
    int wid  = tid >> 5;
    int lane = tid & 31;
    int wm = (wid >> 2) * 64;
    int wn = (wid & 3) * 32;

    uint sbase = (uint)__cvta_generic_to_shared(smraw);

    int c0i = tid, c1i = tid + 256;
    int a0r = c0i >> 2, a0k = (c0i & 3) * 8;
    int a1r = c1i >> 2, a1k = (c1i & 3) * 8;
    int b0k = c0i >> 4, b0n = (c0i & 15) * 8;
    int b1k = c1i >> 4, b1n = (c1i & 15) * 8;
    uint a0d = (uint)(a0r * PA + a0k) * 2;
    uint a1d = (uint)(a1r * PA + a1k) * 2;
    uint b0d = (uint)(b0k * PB + b0n) * 2;
    uint b1d = (uint)(b1k * PB + b1n) * 2;
    const __half* a0s_h = Ah + (size_t)(m0 + a0r) * K + a0k;
    const __half* a1s_h = Ah + (size_t)(m0 + a1r) * K + a1k;
    const __half* a0s_l = Al + (size_t)(m0 + a0r) * K + a0k;
    const __half* a1s_l = Al + (size_t)(m0 + a1r) * K + a1k;
    const __half* b0s   = Bh + (size_t)b0k * NSP + n0 + b0n;
    const __half* b1s   = Bh + (size_t)b1k * NSP + n0 + b1n;

    int a_row  = (lane & 7) + ((lane >> 3) & 1) * 8;
    int a_koff = ((lane >> 4) & 1) * 8;
    int b_row  = (lane & 7) + ((lane >> 3) & 1) * 8;

    float4 acc[4][4];
    #pragma unroll
    for (int i = 0; i < 4; i++)
        #pragma unroll
        for (int j = 0; j < 4; j++) acc[i][j] = make_float4(0.f, 0.f, 0.f, 0.f);

    const int NK = K / 32;

    #define ISSUE(kc_, stg_) do {                                           \
        int ko_ = (kc_) * 32;                                               \
        size_t bko_ = (size_t)ko_ * NSP;                                    \
        uint d_ = sbase + (uint)(stg_) * STG_B;                             \
        cpasync16(d_ + AH_OFF + a0d, a0s_h + ko_);                          \
        cpasync16(d_ + AH_OFF + a1d, a1s_h + ko_);                          \
        if (AT == 2) {                                                      \
            cpasync16(d_ + AL_OFF + a0d, a0s_l + ko_);                      \
            cpasync16(d_ + AL_OFF + a1d, a1s_l + ko_);                      \
        }                                                                   \
        cpasync16(d_ + BH_OFF + b0d, b0s + bko_);                           \
        cpasync16(d_ + BH_OFF + b1d, b1s + bko_);                           \
        CP_COMMIT();                                                        \
    } while (0)

    ISSUE(0, 0);
    ISSUE(1, 1);

    for (int kc = 0; kc < NK; kc++) {
        if (kc < NK - 1) cp_wait<1>(); else cp_wait<0>();
        __syncthreads();
        if (kc + 2 < NK) {
            int stg = kc + 2;
            while (stg >= 3) stg -= 3;
            ISSUE(kc + 2, stg);
        }

        int cs = kc;
        while (cs >= 3) cs -= 3;
        uint aH = sbase + (uint)cs * STG_B + AH_OFF;
        uint aL = sbase + (uint)cs * STG_B + AL_OFF;
        uint bH = sbase + (uint)cs * STG_B + BH_OFF;

        #pragma unroll
        for (int kk = 0; kk < 32; kk += 16) {
            uint ah[4][4], al[4][4], bh[4][2];
            #pragma unroll
            for (int mt = 0; mt < 4; mt++) {
                uint off = (uint)((wm + mt * 16 + a_row) * PA + kk + a_koff) * 2;
                ldsm4(ah[mt][0], ah[mt][1], ah[mt][2], ah[mt][3], aH + off);
                if (AT == 2)
                    ldsm4(al[mt][0], al[mt][1], al[mt][2], al[mt][3], aL + off);
            }
            #pragma unroll
            for (int nt = 0; nt < 4; nt++) {
                uint off = (uint)((kk + b_row) * PB + wn + nt * 8) * 2;
                ldsm2t(bh[nt][0], bh[nt][1], bH + off);
            }
            #pragma unroll
            for (int mt = 0; mt < 4; mt++)
                #pragma unroll
                for (int nt = 0; nt < 4; nt++) {
                    mmah16816(acc[mt][nt], ah[mt][0], ah[mt][1], ah[mt][2], ah[mt][3],
                              bh[nt][0], bh[nt][1]);
                    if (AT == 2)
                        mmah16816(acc[mt][nt], al[mt][0], al[mt][1], al[mt][2], al[mt][3],
                                  bh[nt][0], bh[nt][1]);
                }
        }
    }

    int g = lane >> 2, t4 = lane & 3;
    if (KIND == 0) {
        __half* dst;
        int rowoff;
        if (blockIdx.y < 2) {
            dst = g_q16 + (size_t)b * CCH * NSP;
            rowoff = 0;
        } else {
            dst = g_kv16 + (size_t)b * 2 * CCH * NSP;
            rowoff = 256;
        }
        #pragma unroll
        for (int mt = 0; mt < 4; mt++) {
            int m_g = m0 + wm + mt * 16 + g - rowoff;
            #pragma unroll
            for (int nt = 0; nt < 4; nt++) {
                int n_g = n0 + wn + nt * 8 + 2 * t4;
                float4 d = acc[mt][nt];
                size_t o0 = (size_t)m_g * NSP + n_g;
                size_t o1 = o0 + (size_t)8 * NSP;
                *(uint*)(dst + o0) = pkh2(d.x, d.y);
                *(uint*)(dst + o1) = pkh2(d.z, d.w);
            }
        }
    } else {
        float* Cp = Cext + (size_t)b * M * NSP;
        #pragma unroll
        for (int mt = 0; mt < 4; mt++) {
            int m_g = m0 + wm + mt * 16 + g;
            float b0v = bias[m_g];
            float b1v = bias[m_g + 8];
            #pragma unroll
            for (int nt = 0; nt < 4; nt++) {
                int n_g = n0 + wn + nt * 8 + 2 * t4;
                float4 d = acc[mt][nt];
                float2 lo = make_float2(d.x + b0v, d.y + b0v);
                float2 hi = make_float2(d.z + b1v, d.w + b1v);
                *(float2*)(Cp + (size_t)m_g * NSP + n_g)       = lo;
                *(float2*)(Cp + (size_t)(m_g + 8) * NSP + n_g) = hi;
            }
        }
    }
}

// ---------------- 5) k-row sum of exp ---------------------------------------------
__global__ __launch_bounds__(256) void ksum_kernel()
{
    int row = blockIdx.x;
    int b = row >> 8, ch = row & 255;
    const uint4* p4 = (const uint4*)(g_kv16 + (size_t)b * 2 * CCH * NSP
                                     + (size_t)ch * NSP);
    float s = 0.f;
    #pragma unroll
    for (int i = 0; i < 2; i++) {
        uint4 u = p4[threadIdx.x + i * 256];
        const __half2* h = (const __half2*)&u;
        #pragma unroll
        for (int j = 0; j < 4; j++) {
            float2 f = __half22float2(h[j]);
            s += __expf(f.x) + __expf(f.y);
        }
    }
    __shared__ float ssum[8];
    #pragma unroll
    for (int o = 16; o; o >>= 1) s += __shfl_xor_sync(0xffffffffu, s, o);
    int w = threadIdx.x >> 5, l = threadIdx.x & 31;
    if (l == 0) ssum[w] = s;
    __syncthreads();
    if (threadIdx.x == 0) {
        s = 0.f;
        #pragma unroll
        for (int i = 0; i < 8; i++) s += ssum[i];
        g_krs[row] = 1.0f / s;
    }
}

// ---------------- 6) att via tensor cores -----------------------------------------
__global__ __launch_bounds__(256) void att_kernel()
{
    extern __shared__ char smraw[];
    int bh = blockIdx.x >> 3;
    int chunk = blockIdx.x & 7;
    int b = bh >> 3, h = bh & 7;
    const __half* kp = g_kv16 + (size_t)b * 2 * CCH * NSP + (size_t)(h * HD) * NSP;
    const __half* vp = kp + (size_t)CCH * NSP;
    int n0 = chunk * 512;

    int tid  = threadIdx.x;
    int wid  = tid >> 5;
    int lane = tid & 31;
    uint sbase = (uint)__cvta_generic_to_shared(smraw);

    #pragma unroll
    for (int i = 0; i < 8; i++) {
        int c = tid + i * 256;
        int row  = c >> 6;
        int colq = c & 63;
        size_t gofs = (size_t)row * NSP + n0 + colq * 8;
        uint soff = (uint)(row * 520 + colq * 8) * 2;
        uint4 u = *(const uint4*)(kp + gofs);
        __half2* hh = (__half2*)&u;
        #pragma unroll
        for (int j = 0; j < 4; j++) {
            float2 f = __half22float2(hh[j]);
            hh[j] = __floats2half2_rn(__expf(f.x), __expf(f.y));
        }
        *(uint4*)(smraw + EK_OFF + soff) = u;
        *(uint4*)(smraw + EV_OFF + soff) = *(const uint4*)(vp + gofs);
    }
    __syncthreads();

    int a_row  = (lane & 7) + ((lane >> 3) & 1) * 8;
    int a_koff = ((lane >> 4) & 1) * 8;
    int b_drow = lane >> 2;
    int b_noff = (lane & 3) * 2;

    float4 acc[2][4];
    #pragma unroll
    for (int i = 0; i < 2; i++)
        #pragma unroll
        for (int j = 0; j < 4; j++) acc[i][j] = make_float4(0.f, 0.f, 0.f, 0.f);

    int nkb = wid * 64;
    #pragma unroll
    for (int cc = 0; cc < 4; cc++) {
        int nk = nkb + cc * 16;
        uint a[2][4];
        #pragma unroll
        for (int mt = 0; mt < 2; mt++) {
            uint off = (uint)((mt * 16 + a_row) * 520 + nk + a_koff) * 2;
            ldsm4(a[mt][0], a[mt][1], a[mt][2], a[mt][3], sbase + EV_OFF + off);
        }
        #pragma unroll
        for (int nt = 0; nt < 4; nt++) {
            uint boff = (uint)((nt * 8 + b_drow) * 520 + nk + b_noff) * 2;
            uint b0 = *(const uint*)(smraw + EK_OFF + boff);
            uint b1 = *(const uint*)(smraw + EK_OFF + boff + 16);
            #pragma unroll
            for (int mt = 0; mt < 2; mt++)
                mmah16816(acc[mt][nt], a[mt][0], a[mt][1], a[mt][2], a[mt][3], b0, b1);
        }
    }
    __syncthreads();

    float* attw = (float*)smraw;
    int g = lane >> 2, t4 = lane & 3;
    #pragma unroll
    for (int mt = 0; mt < 2; mt++) {
        int e = mt * 16 + g;
        #pragma unroll
        for (int nt = 0; nt < 4; nt++) {
            int d = nt * 8 + 2 * t4;
            float4 a = acc[mt][nt];
            float* base = attw + wid * 1024;
            base[(d    ) * 32 + e    ] = a.x;
            base[(d + 1) * 32 + e    ] = a.y;
            base[(d    ) * 32 + e + 8] = a.z;
            base[(d + 1) * 32 + e + 8] = a.w;
        }
    }
    __syncthreads();

    int ob = tid * 4;
    float4 o = make_float4(0.f, 0.f, 0.f, 0.f);
    #pragma unroll
    for (int w = 0; w < 8; w++) {
        float4 p = *(const float4*)(attw + w * 1024 + ob);
        o.x += p.x; o.y += p.y; o.z += p.z; o.w += p.w;
    }
    *(float4*)(g_attp + (size_t)blockIdx.x * 1024 + ob) = o;
}

__global__ __launch_bounds__(256) void att_reduce_kernel()
{
    int bh = blockIdx.x;
    int b = bh >> 3, h = bh & 7;
    #pragma unroll
    for (int t = 0; t < 4; t++) {
        int idx = threadIdx.x + t * 256;
        int d = idx >> 5;
        float s = 0.f;
        #pragma unroll
        for (int c = 0; c < 8; c++)
            s += g_attp[((size_t)bh * 8 + c) * 1024 + idx];
        g_att[(size_t)bh * 1024 + idx] = s * g_krs[b * CCH + h * HD + d];
    }
}

// ---------------- 7) fold proj weights with att, fp16 split out -------------------
__global__ __launch_bounds__(256) void wf_fold_kernel(const float* __restrict__ projw)
{
    int b = blockIdx.x >> 4, ob = blockIdx.x & 15;
    __shared__ float attS[8][32][33];
    __shared__ float wS[16 * 256];
    int tid = threadIdx.x;

    #pragma unroll
    for (int t = 0; t < 8; t++) {
        int idx = tid + t * 256;
        float4 v = ((const float4*)(g_att + (size_t)b * 8192))[idx];
        int fi = idx * 4;
        int hh = fi >> 10, dd = (fi >> 5) & 31, ee = fi & 31;
        attS[hh][dd][ee + 0] = v.x;
        attS[hh][dd][ee + 1] = v.y;
        attS[hh][dd][ee + 2] = v.z;
        attS[hh][dd][ee + 3] = v.w;
    }
    #pragma unroll
    for (int t = 0; t < 4; t++) {
        int idx = tid + t * 256;
        ((float4*)wS)[idx] = ((const float4*)(projw + (size_t)ob * 16 * 256))[idx];
    }
    __syncthreads();

    int hh = tid >> 5, dd = tid & 31;
    float acc[16];
    #pragma unroll
    for (int i = 0; i < 16; i++) acc[i] = 0.f;
    for (int e = 0; e < 32; e++) {
        float a = attS[hh][dd][e];
        #pragma unroll
        for (int oi = 0; oi < 16; oi++)
            acc[oi] += a * wS[oi * 256 + hh * 32 + e];
    }
    #pragma unroll
    for (int oi = 0; oi < 16; oi++) {
        size_t idx = ((size_t)b * CCH + ob * 16 + oi) * CCH + tid;
        float a = acc[oi];
        __half hh16 = __float2half_rn(a);
        g_wfh[idx] = hh16;
        g_wfl[idx] = __float2half_rn(a - __half2float(hh16));
    }
}

// ---------------- launch ----------------------------------------------------------------
extern "C" void kernel_launch(void* const* d_in, const int* in_sizes, int n_in,
                              void* d_out, int out_size)
{
    const float* x     = (const float*)d_in[0];
    const float* gnw   = (const float*)d_in[1];
    const float* gnb   = (const float*)d_in[2];
    const float* qkvw  = (const float*)d_in[3];
    const float* projw = (const float*)d_in[4];
    const float* projb = (const float*)d_in[5];
    float* out = (float*)d_out;

    cudaFuncSetAttribute(pgemm_kernel<M3, 0, 0, 0, 1>,
                         cudaFuncAttributeMaxDynamicSharedMemorySize, GSMEM);
    cudaFuncSetAttribute(pgemm_kernel<CCH, 1, 1, 1, 2>,
                         cudaFuncAttributeMaxDynamicSharedMemorySize, GSMEM);
    cudaFuncSetAttribute(att_kernel,
                         cudaFuncAttributeMaxDynamicSharedMemorySize, ATT_SMEM);

    gn_partial_kernel<<<BATCH * NGRP * 4, 256>>>(x);
    gn_final_kernel<<<1, BATCH * NGRP>>>();

    gnconv_kernel<<<BATCH * CCH * NSP / 1024, 256>>>(x, gnw, gnb);
    wsplit_kernel<<<M3 * CCH / 1024, 256>>>(qkvw);

    pgemm_kernel<M3, 0, 0, 0, 1>
        <<<dim3(NSP / 128, M3 / 128, BATCH), 256, GSMEM>>>(nullptr, nullptr);

    ksum_kernel<<<BATCH * CCH, 256>>>();

    att_kernel<<<BATCH * NH * 8, 256, ATT_SMEM>>>();
    att_reduce_kernel<<<BATCH * NH, 256>>>();

    wf_fold_kernel<<<BATCH * 16, 256>>>(projw);

    pgemm_kernel<CCH, 1, 1, 1, 2>
        <<<dim3(NSP / 128, CCH / 128, BATCH), 256, GSMEM>>>(out, projb);
}

// round 17
// speedup vs baseline: 5.8223x; 1.1076x over previous
#include <cuda_runtime.h>
#include <cuda_fp16.h>
#include <math.h>
#include <cstdint>

#define BATCH 16
#define CCH   256
#define NSP   4096
#define M3    768
#define NGRP  4
#define CPG   64
#define NH    8
#define HD    32

#define PA 40     // A smem pitch (fp16)
#define PB 136    // B smem pitch (fp16)

typedef unsigned int uint;

// pgemm smem stage layout (bytes): Ah(10240) [Al unused at AT=1] B(8704)
#define AH_OFF 0
#define AL_OFF 10240
#define BH_OFF 20480
#define STG_B  29184
#define GSMEM  (3 * STG_B)   // 87552

// att smem layout
#define EK_OFF 0
#define EV_OFF 33280              // 32*520*2
#define ATT_SMEM 66560

// ---------------- scratch (referenced ONLY in device code) --------------------
__device__ __align__(16) float g_att[BATCH * NH * HD * HD];
__device__ __align__(16) float g_attp[BATCH * NH * 8 * HD * HD];
__device__ __align__(16) float g_ksump[BATCH * NH * 8 * HD];   // per-chunk exp sums
__device__ float g_mu[BATCH * NGRP];
__device__ float g_rsig[BATCH * NGRP];
__device__ float g_gnp[BATCH * NGRP * 4 * 2];
__device__ __align__(16) __half g_x16[BATCH * CCH * NSP];      // GN(x) fp16 [b][k][n]
__device__ __align__(16) __half g_q16[BATCH * CCH * NSP];      // q fp16 [b][k][n]
__device__ __align__(16) __half g_kv16[BATCH * 2 * CCH * NSP]; // k,v fp16 [b][512][n]
__device__ __align__(16) __half g_wh[M3 * CCH];
__device__ __align__(16) __half g_wfh[BATCH * CCH * CCH];

// ---------------- helpers ------------------------------------------------------
__device__ __forceinline__ uint pkh2(float a, float b) {
    __half2 t = __floats2half2_rn(a, b);
    return *reinterpret_cast<uint*>(&t);
}
__device__ __forceinline__ void ldsm4(uint& r0, uint& r1, uint& r2, uint& r3, uint addr) {
    asm volatile("ldmatrix.sync.aligned.m8n8.x4.shared.b16 {%0,%1,%2,%3}, [%4];"
                 : "=r"(r0), "=r"(r1), "=r"(r2), "=r"(r3) : "r"(addr));
}
__device__ __forceinline__ void ldsm2t(uint& r0, uint& r1, uint addr) {
    asm volatile("ldmatrix.sync.aligned.m8n8.x2.trans.shared.b16 {%0,%1}, [%2];"
                 : "=r"(r0), "=r"(r1) : "r"(addr));
}
__device__ __forceinline__ void mmah16816(float4& d, uint a0, uint a1, uint a2, uint a3,
                                          uint b0, uint b1) {
    asm volatile("mma.sync.aligned.m16n8k16.row.col.f32.f16.f16.f32 "
                 "{%0,%1,%2,%3}, {%4,%5,%6,%7}, {%8,%9}, {%0,%1,%2,%3};"
                 : "+f"(d.x), "+f"(d.y), "+f"(d.z), "+f"(d.w)
                 : "r"(a0), "r"(a1), "r"(a2), "r"(a3), "r"(b0), "r"(b1));
}
__device__ __forceinline__ void cpasync16(uint dst, const void* src) {
    asm volatile("cp.async.cg.shared.global [%0], [%1], 16;" :: "r"(dst), "l"(src));
}
#define CP_COMMIT() asm volatile("cp.async.commit_group;" ::: "memory")
template<int N>
__device__ __forceinline__ void cp_wait() {
    asm volatile("cp.async.wait_group %0;" :: "n"(N) : "memory");
}

// ---------------- 1) GroupNorm stats --------------------------------------------
__global__ __launch_bounds__(256) void gn_partial_kernel(const float* __restrict__ x)
{
    int bg = blockIdx.x >> 2, part = blockIdx.x & 3;
    const float4* p = (const float4*)x + (size_t)bg * 65536 + part * 16384;
    float s = 0.f, sq = 0.f;
    for (int i = threadIdx.x; i < 16384; i += 256) {
        float4 v = p[i];
        s  += v.x + v.y + v.z + v.w;
        sq += v.x * v.x + v.y * v.y + v.z * v.z + v.w * v.w;
    }
    __shared__ float ss[8], ssq[8];
    #pragma unroll
    for (int o = 16; o; o >>= 1) {
        s  += __shfl_down_sync(0xffffffffu, s, o);
        sq += __shfl_down_sync(0xffffffffu, sq, o);
    }
    int w = threadIdx.x >> 5, l = threadIdx.x & 31;
    if (l == 0) { ss[w] = s; ssq[w] = sq; }
    __syncthreads();
    if (threadIdx.x == 0) {
        s = 0.f; sq = 0.f;
        #pragma unroll
        for (int i = 0; i < 8; i++) { s += ss[i]; sq += ssq[i]; }
        g_gnp[blockIdx.x * 2]     = s;
        g_gnp[blockIdx.x * 2 + 1] = sq;
    }
}
__global__ void gn_final_kernel()
{
    int bg = threadIdx.x;
    float s = 0.f, sq = 0.f;
    #pragma unroll
    for (int i = 0; i < 4; i++) {
        s  += g_gnp[(bg * 4 + i) * 2];
        sq += g_gnp[(bg * 4 + i) * 2 + 1];
    }
    const float inv = 1.0f / (float)(CPG * NSP);
    float mu  = s * inv;
    float var = sq * inv - mu * mu;
    g_mu[bg]   = mu;
    g_rsig[bg] = rsqrtf(var + 1e-5f);
}

// ---------------- 2) GN + convert x to fp16 --------------------------------------
__global__ __launch_bounds__(256) void gnconv_kernel(const float* __restrict__ x,
                                                     const float* __restrict__ gnw,
                                                     const float* __restrict__ gnb)
{
    size_t idx = (size_t)blockIdx.x * 256 + threadIdx.x;
    size_t f = idx * 4;
    int b = (int)(f >> 20);
    int c = (int)((f >> 12) & 255);
    int g = c >> 6;
    float rs = g_rsig[b * NGRP + g];
    float mu = g_mu[b * NGRP + g];
    float w  = gnw[c] * rs;
    float bb = gnb[c] - mu * w;
    float4 v = ((const float4*)x)[idx];
    uint2 o;
    o.x = pkh2(v.x * w + bb, v.y * w + bb);
    o.y = pkh2(v.z * w + bb, v.w * w + bb);
    *(uint2*)(g_x16 + f) = o;
}

// ---------------- 3) qkv weight convert to fp16 ------------------------------------
__global__ __launch_bounds__(256) void wconv_kernel(const float* __restrict__ w)
{
    int idx = blockIdx.x * 256 + threadIdx.x;
    float4 v = ((const float4*)w)[idx];
    uint2 hi;
    hi.x = pkh2(v.x, v.y);
    hi.y = pkh2(v.z, v.w);
    *(uint2*)(g_wh + idx * 4) = hi;
}

// ---------------- 4) pipelined fp16 GEMM (single A term) ---------------------------
template<int M, int KIND, int ASEL, int BSEL>
__global__ __launch_bounds__(256, 2) void pgemm_kernel(
    float* __restrict__ Cext, const float* __restrict__ bias)
{
    extern __shared__ char smraw[];
    const int K = 256;
    int b = blockIdx.z;
    const __half* Ah = (ASEL == 0) ? g_wh : (g_wfh + (size_t)b * M * K);
    const __half* Bh = ((BSEL == 0) ? g_x16 : g_q16) + (size_t)b * K * NSP;
    int m0 = blockIdx.y * 128, n0 = blockIdx.x * 128;

    int tid  = threadIdx.x;
    int wid  = tid >> 5;
    int lane = tid & 31;
    int wm = (wid >> 2) * 64;
    int wn = (wid & 3) * 32;

    uint sbase = (uint)__cvta_generic_to_shared(smraw);

    int c0i = tid, c1i = tid + 256;
    int a0r = c0i >> 2, a0k = (c0i & 3) * 8;
    int a1r = c1i >> 2, a1k = (c1i & 3) * 8;
    int b0k = c0i >> 4, b0n = (c0i & 15) * 8;
    int b1k = c1i >> 4, b1n = (c1i & 15) * 8;
    uint a0d = (uint)(a0r * PA + a0k) * 2;
    uint a1d = (uint)(a1r * PA + a1k) * 2;
    uint b0d = (uint)(b0k * PB + b0n) * 2;
    uint b1d = (uint)(b1k * PB + b1n) * 2;
    const __half* a0s_h = Ah + (size_t)(m0 + a0r) * K + a0k;
    const __half* a1s_h = Ah + (size_t)(m0 + a1r) * K + a1k;
    const __half* b0s   = Bh + (size_t)b0k * NSP + n0 + b0n;
    const __half* b1s   = Bh + (size_t)b1k * NSP + n0 + b1n;

    int a_row  = (lane & 7) + ((lane >> 3) & 1) * 8;
    int a_koff = ((lane >> 4) & 1) * 8;
    int b_row  = (lane & 7) + ((lane >> 3) & 1) * 8;

    float4 acc[4][4];
    #pragma unroll
    for (int i = 0; i < 4; i++)
        #pragma unroll
        for (int j = 0; j < 4; j++) acc[i][j] = make_float4(0.f, 0.f, 0.f, 0.f);

    const int NK = K / 32;

    #define ISSUE(kc_, stg_) do {                                           \
        int ko_ = (kc_) * 32;                                               \
        size_t bko_ = (size_t)ko_ * NSP;                                    \
        uint d_ = sbase + (uint)(stg_) * STG_B;                             \
        cpasync16(d_ + AH_OFF + a0d, a0s_h + ko_);                          \
        cpasync16(d_ + AH_OFF + a1d, a1s_h + ko_);                          \
        cpasync16(d_ + BH_OFF + b0d, b0s + bko_);                           \
        cpasync16(d_ + BH_OFF + b1d, b1s + bko_);                           \
        CP_COMMIT();                                                        \
    } while (0)

    ISSUE(0, 0);
    ISSUE(1, 1);

    for (int kc = 0; kc < NK; kc++) {
        if (kc < NK - 1) cp_wait<1>(); else cp_wait<0>();
        __syncthreads();
        if (kc + 2 < NK) {
            int stg = kc + 2;
            while (stg >= 3) stg -= 3;
            ISSUE(kc + 2, stg);
        }

        int cs = kc;
        while (cs >= 3) cs -= 3;
        uint aH = sbase + (uint)cs * STG_B + AH_OFF;
        uint bH = sbase + (uint)cs * STG_B + BH_OFF;

        #pragma unroll
        for (int kk = 0; kk < 32; kk += 16) {
            uint ah[4][4], bh[4][2];
            #pragma unroll
            for (int mt = 0; mt < 4; mt++) {
                uint off = (uint)((wm + mt * 16 + a_row) * PA + kk + a_koff) * 2;
                ldsm4(ah[mt][0], ah[mt][1], ah[mt][2], ah[mt][3], aH + off);
            }
            #pragma unroll
            for (int nt = 0; nt < 4; nt++) {
                uint off = (uint)((kk + b_row) * PB + wn + nt * 8) * 2;
                ldsm2t(bh[nt][0], bh[nt][1], bH + off);
            }
            #pragma unroll
            for (int mt = 0; mt < 4; mt++)
                #pragma unroll
                for (int nt = 0; nt < 4; nt++)
                    mmah16816(acc[mt][nt], ah[mt][0], ah[mt][1], ah[mt][2], ah[mt][3],
                              bh[nt][0], bh[nt][1]);
        }
    }

    int g = lane >> 2, t4 = lane & 3;
    if (KIND == 0) {
        __half* dst;
        int rowoff;
        if (blockIdx.y < 2) {
            dst = g_q16 + (size_t)b * CCH * NSP;
            rowoff = 0;
        } else {
            dst = g_kv16 + (size_t)b * 2 * CCH * NSP;
            rowoff = 256;
        }
        #pragma unroll
        for (int mt = 0; mt < 4; mt++) {
            int m_g = m0 + wm + mt * 16 + g - rowoff;
            #pragma unroll
            for (int nt = 0; nt < 4; nt++) {
                int n_g = n0 + wn + nt * 8 + 2 * t4;
                float4 d = acc[mt][nt];
                size_t o0 = (size_t)m_g * NSP + n_g;
                size_t o1 = o0 + (size_t)8 * NSP;
                *(uint*)(dst + o0) = pkh2(d.x, d.y);
                *(uint*)(dst + o1) = pkh2(d.z, d.w);
            }
        }
    } else {
        float* Cp = Cext + (size_t)b * M * NSP;
        #pragma unroll
        for (int mt = 0; mt < 4; mt++) {
            int m_g = m0 + wm + mt * 16 + g;
            float b0v = bias[m_g];
            float b1v = bias[m_g + 8];
            #pragma unroll
            for (int nt = 0; nt < 4; nt++) {
                int n_g = n0 + wn + nt * 8 + 2 * t4;
                float4 d = acc[mt][nt];
                float2 lo = make_float2(d.x + b0v, d.y + b0v);
                float2 hi = make_float2(d.z + b1v, d.w + b1v);
                *(float2*)(Cp + (size_t)m_g * NSP + n_g)       = lo;
                *(float2*)(Cp + (size_t)(m_g + 8) * NSP + n_g) = hi;
            }
        }
    }
}

// ---------------- 5) att via tensor cores + fused exp-sum --------------------------
__global__ __launch_bounds__(256) void att_kernel()
{
    extern __shared__ char smraw[];
    int bh = blockIdx.x >> 3;
    int chunk = blockIdx.x & 7;
    int b = bh >> 3, h = bh & 7;
    const __half* kp = g_kv16 + (size_t)b * 2 * CCH * NSP + (size_t)(h * HD) * NSP;
    const __half* vp = kp + (size_t)CCH * NSP;
    int n0 = chunk * 512;

    int tid  = threadIdx.x;
    int wid  = tid >> 5;
    int lane = tid & 31;
    uint sbase = (uint)__cvta_generic_to_shared(smraw);

    #pragma unroll
    for (int i = 0; i < 8; i++) {
        int c = tid + i * 256;
        int row  = c >> 6;
        int colq = c & 63;
        size_t gofs = (size_t)row * NSP + n0 + colq * 8;
        uint soff = (uint)(row * 520 + colq * 8) * 2;
        uint4 u = *(const uint4*)(kp + gofs);
        __half2* hh = (__half2*)&u;
        #pragma unroll
        for (int j = 0; j < 4; j++) {
            float2 f = __half22float2(hh[j]);
            hh[j] = __floats2half2_rn(__expf(f.x), __expf(f.y));
        }
        *(uint4*)(smraw + EK_OFF + soff) = u;
        *(uint4*)(smraw + EV_OFF + soff) = *(const uint4*)(vp + gofs);
    }
    __syncthreads();

    // fused per-chunk exp-sum: 8 threads per d row sum 64 elems each
    {
        int d = tid >> 3, part = tid & 7;
        const __half2* row = (const __half2*)(smraw + EK_OFF + (uint)d * 520 * 2)
                             + part * 32;
        float s = 0.f;
        #pragma unroll
        for (int i = 0; i < 32; i++) {
            float2 f = __half22float2(row[i]);
            s += f.x + f.y;
        }
        #pragma unroll
        for (int o = 4; o; o >>= 1) s += __shfl_xor_sync(0xffffffffu, s, o);
        if (part == 0) g_ksump[(size_t)blockIdx.x * HD + d] = s;
    }

    int a_row  = (lane & 7) + ((lane >> 3) & 1) * 8;
    int a_koff = ((lane >> 4) & 1) * 8;
    int b_drow = lane >> 2;
    int b_noff = (lane & 3) * 2;

    float4 acc[2][4];
    #pragma unroll
    for (int i = 0; i < 2; i++)
        #pragma unroll
        for (int j = 0; j < 4; j++) acc[i][j] = make_float4(0.f, 0.f, 0.f, 0.f);

    int nkb = wid * 64;
    #pragma unroll
    for (int cc = 0; cc < 4; cc++) {
        int nk = nkb + cc * 16;
        uint a[2][4];
        #pragma unroll
        for (int mt = 0; mt < 2; mt++) {
            uint off = (uint)((mt * 16 + a_row) * 520 + nk + a_koff) * 2;
            ldsm4(a[mt][0], a[mt][1], a[mt][2], a[mt][3], sbase + EV_OFF + off);
        }
        #pragma unroll
        for (int nt = 0; nt < 4; nt++) {
            uint boff = (uint)((nt * 8 + b_drow) * 520 + nk + b_noff) * 2;
            uint b0 = *(const uint*)(smraw + EK_OFF + boff);
            uint b1 = *(const uint*)(smraw + EK_OFF + boff + 16);
            #pragma unroll
            for (int mt = 0; mt < 2; mt++)
                mmah16816(acc[mt][nt], a[mt][0], a[mt][1], a[mt][2], a[mt][3], b0, b1);
        }
    }
    __syncthreads();

    float* attw = (float*)smraw;
    int g = lane >> 2, t4 = lane & 3;
    #pragma unroll
    for (int mt = 0; mt < 2; mt++) {
        int e = mt * 16 + g;
        #pragma unroll
        for (int nt = 0; nt < 4; nt++) {
            int d = nt * 8 + 2 * t4;
            float4 a = acc[mt][nt];
            float* base = attw + wid * 1024;
            base[(d    ) * 32 + e    ] = a.x;
            base[(d + 1) * 32 + e    ] = a.y;
            base[(d    ) * 32 + e + 8] = a.z;
            base[(d + 1) * 32 + e + 8] = a.w;
        }
    }
    __syncthreads();

    int ob = tid * 4;
    float4 o = make_float4(0.f, 0.f, 0.f, 0.f);
    #pragma unroll
    for (int w = 0; w < 8; w++) {
        float4 p = *(const float4*)(attw + w * 1024 + ob);
        o.x += p.x; o.y += p.y; o.z += p.z; o.w += p.w;
    }
    *(float4*)(g_attp + (size_t)blockIdx.x * 1024 + ob) = o;
}

// reduce 8 chunk-partials + chunk exp-sums, apply 1/sum
__global__ __launch_bounds__(256) void att_reduce_kernel()
{
    int bh = blockIdx.x;
    #pragma unroll
    for (int t = 0; t < 4; t++) {
        int idx = threadIdx.x + t * 256;
        int d = idx >> 5;
        float s = 0.f, ks = 0.f;
        #pragma unroll
        for (int c = 0; c < 8; c++) {
            s  += g_attp[((size_t)bh * 8 + c) * 1024 + idx];
            ks += g_ksump[((size_t)bh * 8 + c) * HD + d];
        }
        g_att[(size_t)bh * 1024 + idx] = s / ks;
    }
}

// ---------------- 6) fold proj weights with att, fp16 out --------------------------
__global__ __launch_bounds__(256) void wf_fold_kernel(const float* __restrict__ projw)
{
    int b = blockIdx.x >> 4, ob = blockIdx.x & 15;
    __shared__ float attS[8][32][33];
    __shared__ float wS[16 * 256];
    int tid = threadIdx.x;

    #pragma unroll
    for (int t = 0; t < 8; t++) {
        int idx = tid + t * 256;
        float4 v = ((const float4*)(g_att + (size_t)b * 8192))[idx];
        int fi = idx * 4;
        int hh = fi >> 10, dd = (fi >> 5) & 31, ee = fi & 31;
        attS[hh][dd][ee + 0] = v.x;
        attS[hh][dd][ee + 1] = v.y;
        attS[hh][dd][ee + 2] = v.z;
        attS[hh][dd][ee + 3] = v.w;
    }
    #pragma unroll
    for (int t = 0; t < 4; t++) {
        int idx = tid + t * 256;
        ((float4*)wS)[idx] = ((const float4*)(projw + (size_t)ob * 16 * 256))[idx];
    }
    __syncthreads();

    int hh = tid >> 5, dd = tid & 31;
    float acc[16];
    #pragma unroll
    for (int i = 0; i < 16; i++) acc[i] = 0.f;
    for (int e = 0; e < 32; e++) {
        float a = attS[hh][dd][e];
        #pragma unroll
        for (int oi = 0; oi < 16; oi++)
            acc[oi] += a * wS[oi * 256 + hh * 32 + e];
    }
    #pragma unroll
    for (int oi = 0; oi < 16; oi++) {
        size_t idx = ((size_t)b * CCH + ob * 16 + oi) * CCH + tid;
        g_wfh[idx] = __float2half_rn(acc[oi]);
    }
}

// ---------------- launch ----------------------------------------------------------------
extern "C" void kernel_launch(void* const* d_in, const int* in_sizes, int n_in,
                              void* d_out, int out_size)
{
    const float* x     = (const float*)d_in[0];
    const float* gnw   = (const float*)d_in[1];
    const float* gnb   = (const float*)d_in[2];
    const float* qkvw  = (const float*)d_in[3];
    const float* projw = (const float*)d_in[4];
    const float* projb = (const float*)d_in[5];
    float* out = (float*)d_out;

    cudaFuncSetAttribute(pgemm_kernel<M3, 0, 0, 0>,
                         cudaFuncAttributeMaxDynamicSharedMemorySize, GSMEM);
    cudaFuncSetAttribute(pgemm_kernel<CCH, 1, 1, 1>,
                         cudaFuncAttributeMaxDynamicSharedMemorySize, GSMEM);
    cudaFuncSetAttribute(att_kernel,
                         cudaFuncAttributeMaxDynamicSharedMemorySize, ATT_SMEM);

    gn_partial_kernel<<<BATCH * NGRP * 4, 256>>>(x);
    gn_final_kernel<<<1, BATCH * NGRP>>>();

    gnconv_kernel<<<BATCH * CCH * NSP / 1024, 256>>>(x, gnw, gnb);
    wconv_kernel<<<M3 * CCH / 1024, 256>>>(qkvw);

    pgemm_kernel<M3, 0, 0, 0>
        <<<dim3(NSP / 128, M3 / 128, BATCH), 256, GSMEM>>>(nullptr, nullptr);

    att_kernel<<<BATCH * NH * 8, 256, ATT_SMEM>>>();
    att_reduce_kernel<<<BATCH * NH, 256>>>();

    wf_fold_kernel<<<BATCH * 16, 256>>>(projw);

    pgemm_kernel<CCH, 1, 1, 1>
        <<<dim3(NSP / 128, CCH / 128, BATCH), 256, GSMEM>>>(out, projb);
}